// round 1
// baseline (speedup 1.0000x reference)
#include <cuda_runtime.h>
#include <math.h>

// Problem constants
constexpr int Bc   = 16;
constexpr int Nn   = 20000;
constexpr int Cc   = 64;
constexpr int DIMc = 128;
constexpr int Ee   = 640000;
constexpr int NBlk = 3;
constexpr int ROWS = Nn * Bc;          // 320000
constexpr int RowF = Bc * Cc;          // 1024 floats per node row (h/t layout [N][B][C])
constexpr int RowF4 = RowF / 4;        // 256 float4

// -------- device scratch (static: allocation is forbidden) --------
__device__ float g_h [ROWS * Cc];      // [N][B][64]   81.9 MB
__device__ float g_t1[ROWS * Cc];
__device__ float g_t2[ROWS * Cc];
__device__ float g_a1[ROWS * DIMc];    // [N*B][128]  163.8 MB
__device__ float g_a2[ROWS * DIMc];
__device__ float g_deg [Nn];
__device__ float g_dinv[Nn];
__device__ float g_w   [Ee];
__device__ int   g_off [Nn + 1];
__device__ int   g_cnt [Nn];
__device__ int   g_csrc[Ee];
__device__ float g_csw [Ee];
__device__ float g_wc  [192 * 128];    // prepacked cheb weights [W0-W2 | W1 | 2W2]

// -------- small setup kernels --------
__global__ void zero_deg_cnt() {
    int i = blockIdx.x * blockDim.x + threadIdx.x;
    if (i < Nn) { g_deg[i] = 0.f; g_cnt[i] = 0; }
}
__global__ void zero_cnt() {
    int i = blockIdx.x * blockDim.x + threadIdx.x;
    if (i < Nn) g_cnt[i] = 0;
}
__global__ void deg_kernel(const int* __restrict__ src, const float* __restrict__ ew) {
    int e = blockIdx.x * blockDim.x + threadIdx.x;
    if (e < Ee) atomicAdd(&g_deg[src[e]], ew[e]);
}
__global__ void dinv_kernel() {
    int i = blockIdx.x * blockDim.x + threadIdx.x;
    if (i < Nn) {
        float d = g_deg[i];
        g_dinv[i] = (d > 0.f) ? rsqrtf(fmaxf(d, 1e-12f)) : 0.f;
    }
}
__global__ void w_count_kernel(const int* __restrict__ src, const int* __restrict__ dst,
                               const float* __restrict__ ew) {
    int e = blockIdx.x * blockDim.x + threadIdx.x;
    if (e < Ee) {
        int s = src[e], d = dst[e];
        g_w[e] = -g_dinv[s] * ew[e] * g_dinv[d];
        atomicAdd(&g_cnt[d], 1);
    }
}
// single-block exclusive scan over g_cnt[0..Nn) -> g_off, g_off[Nn] = total
__global__ void scan_kernel() {
    __shared__ int warp_sums[32];
    __shared__ int s_carry;
    int t = threadIdx.x;                 // 1024 threads
    if (t == 0) s_carry = 0;
    __syncthreads();
    for (int base = 0; base < Nn; base += 1024) {
        int v = (base + t < Nn) ? g_cnt[base + t] : 0;
        int x = v;
        #pragma unroll
        for (int d = 1; d < 32; d <<= 1) {
            int y = __shfl_up_sync(0xFFFFFFFFu, x, d);
            if ((t & 31) >= d) x += y;
        }
        if ((t & 31) == 31) warp_sums[t >> 5] = x;
        __syncthreads();
        if (t < 32) {
            int y = warp_sums[t];
            #pragma unroll
            for (int d = 1; d < 32; d <<= 1) {
                int z = __shfl_up_sync(0xFFFFFFFFu, y, d);
                if (t >= d) y += z;
            }
            warp_sums[t] = y;
        }
        __syncthreads();
        int excl = s_carry + (x - v) + ((t >= 32) ? warp_sums[(t >> 5) - 1] : 0);
        if (base + t < Nn) g_off[base + t] = excl;
        __syncthreads();
        if (t == 0) s_carry += warp_sums[31];
        __syncthreads();
    }
    if (t == 0) g_off[Nn] = s_carry;
}
__global__ void fill_kernel(const int* __restrict__ src, const int* __restrict__ dst) {
    int e = blockIdx.x * blockDim.x + threadIdx.x;
    if (e < Ee) {
        int d = dst[e];
        int pos = g_off[d] + atomicAdd(&g_cnt[d], 1);
        g_csrc[pos] = src[e];
        g_csw[pos]  = g_w[e];
    }
}

// -------- layout transforms: x [B][N][C] <-> h [N][B][C] (as float4) --------
__global__ void t_in_kernel(const float4* __restrict__ x4) {
    int idx = blockIdx.x * 256 + threadIdx.x;        // 5,120,000 total
    int b = idx / (Nn * 16);
    int r = idx % (Nn * 16);
    int n = r >> 4, c4 = r & 15;
    ((float4*)g_h)[n * RowF4 + b * 16 + c4] = x4[idx];
}
__global__ void t_out_kernel(float4* __restrict__ o4) {
    int idx = blockIdx.x * 256 + threadIdx.x;
    int b = idx / (Nn * 16);
    int r = idx % (Nn * 16);
    int n = r >> 4, c4 = r & 15;
    o4[idx] = ((const float4*)g_h)[n * RowF4 + b * 16 + c4];
}

// -------- SpMM: out[n] = sum_{e in CSR(n)} w_e * in[src_e], row = 1024 floats --------
template <int PHASE>
__global__ void spmm_kernel() {
    const float4* __restrict__ in = (PHASE == 0) ? (const float4*)g_h : (const float4*)g_t1;
    float4* __restrict__ out      = (PHASE == 0) ? (float4*)g_t1      : (float4*)g_t2;
    int n = blockIdx.x;
    int t = threadIdx.x;                 // 256 threads == RowF4
    int e0 = g_off[n], e1 = g_off[n + 1];
    float4 acc = make_float4(0.f, 0.f, 0.f, 0.f);
    #pragma unroll 4
    for (int e = e0; e < e1; ++e) {
        int   s  = __ldg(&g_csrc[e]);
        float wv = __ldg(&g_csw[e]);
        float4 v = __ldg(&in[(size_t)s * RowF4 + t]);
        acc.x = fmaf(wv, v.x, acc.x);
        acc.y = fmaf(wv, v.y, acc.y);
        acc.z = fmaf(wv, v.z, acc.z);
        acc.w = fmaf(wv, v.w, acc.w);
    }
    out[(size_t)n * RowF4 + t] = acc;
}

// -------- prepack cheb weights for block b: [W0-W2 | W1 | 2*W2] (192x128) --------
__global__ void prep_wc(const float* __restrict__ cw, int b) {
    int idx = blockIdx.x * 256 + threadIdx.x;        // 8192 total
    if (idx < 64 * 128) {
        const float* base = cw + (size_t)b * 3 * 64 * 128;
        float w0 = base[idx];
        float w1v = base[8192 + idx];
        float w2v = base[16384 + idx];
        g_wc[idx]          = w0 - w2v;
        g_wc[8192 + idx]   = w1v;
        g_wc[16384 + idx]  = 2.f * w2v;
    }
}

// -------- GEMM: [320000 x KTOT] @ [KTOT x BN] + bias, optional swish / residual --------
// MODE 0: out = swish(A@W + bias)         (cheb -> g_a1, mlp1 -> g_a2)
// MODE 1: out += A@W + bias               (mlp2: h += Fx)
template <int KTOT, int BN, int MODE>
__global__ void __launch_bounds__(256)
gemm_kernel(const float* __restrict__ Wext, const float* __restrict__ bias,
            const float* __restrict__ betaPtr) {
    constexpr int BM = 128;
    constexpr int TN = BN / 16;
    constexpr int PITCH = KTOT + 4;      // floats; 196 / 132 both 16B-aligned strides

    const float* A0; const float* A1; const float* A2; float* OUT;
    if constexpr (KTOT == 192)      { A0 = g_h;  A1 = g_t1; A2 = g_t2; OUT = g_a1; }
    else if constexpr (BN == 128)   { A0 = g_a1; A1 = nullptr; A2 = nullptr; OUT = g_a2; }
    else                            { A0 = g_a2; A1 = nullptr; A2 = nullptr; OUT = g_h; }
    const float* Wsrc = (KTOT == 192) ? g_wc : Wext;

    extern __shared__ float sm[];
    float* As = sm;                      // [BM][PITCH]
    float* Ws = sm + BM * PITCH;         // [KTOT][BN]

    const int tid = threadIdx.x;
    const int m0  = blockIdx.x * BM;

    for (int i = tid; i < KTOT * BN / 4; i += 256)
        ((float4*)Ws)[i] = ((const float4*)Wsrc)[i];

    if constexpr (KTOT == 192) {
        for (int i = tid; i < BM * 48; i += 256) {
            int m = i / 48, q = i % 48;
            const float4* src = (q < 16) ? (const float4*)A0
                              : (q < 32) ? (const float4*)A1
                                         : (const float4*)A2;
            float4 v = src[(size_t)(m0 + m) * 16 + (q & 15)];
            *(float4*)(As + m * PITCH + q * 4) = v;
        }
    } else {
        constexpr int QW = KTOT / 4;
        for (int i = tid; i < BM * QW; i += 256) {
            int m = i / QW, q = i % QW;
            float4 v = ((const float4*)A0)[(size_t)(m0 + m) * QW + q];
            *(float4*)(As + m * PITCH + q * 4) = v;
        }
    }
    __syncthreads();

    const int tx = tid & 15, ty = tid >> 4;
    const int r0 = ty * 8, c0 = tx * TN;

    float acc[8][TN];
    #pragma unroll
    for (int i = 0; i < 8; ++i)
        #pragma unroll
        for (int j = 0; j < TN; ++j) acc[i][j] = 0.f;

    #pragma unroll 4
    for (int k = 0; k < KTOT; ++k) {
        float bfr[TN];
        #pragma unroll
        for (int j = 0; j < TN; j += 4)
            *(float4*)(bfr + j) = *(const float4*)(Ws + k * BN + c0 + j);
        float afr[8];
        #pragma unroll
        for (int i = 0; i < 8; ++i) afr[i] = As[(r0 + i) * PITCH + k];
        #pragma unroll
        for (int i = 0; i < 8; ++i)
            #pragma unroll
            for (int j = 0; j < TN; ++j)
                acc[i][j] = fmaf(afr[i], bfr[j], acc[i][j]);
    }

    float bv[TN];
    #pragma unroll
    for (int j = 0; j < TN; ++j) bv[j] = bias[c0 + j];

    if constexpr (MODE == 0) {
        float spv = log1pf(__expf(*betaPtr));   // softplus(beta)
        #pragma unroll
        for (int i = 0; i < 8; ++i) {
            float o[TN];
            #pragma unroll
            for (int j = 0; j < TN; ++j) {
                float v = acc[i][j] + bv[j];
                o[j] = v / (1.1f * (1.f + __expf(-v * spv)));
            }
            size_t base = (size_t)(m0 + r0 + i) * BN + c0;
            #pragma unroll
            for (int j4 = 0; j4 < TN / 4; ++j4)
                *(float4*)(OUT + base + j4 * 4) = *(float4*)(o + j4 * 4);
        }
    } else {
        #pragma unroll
        for (int i = 0; i < 8; ++i) {
            size_t base = (size_t)(m0 + r0 + i) * BN + c0;
            #pragma unroll
            for (int j4 = 0; j4 < TN / 4; ++j4) {
                float4 cur = *(float4*)(OUT + base + j4 * 4);
                cur.x += acc[i][j4 * 4 + 0] + bv[j4 * 4 + 0];
                cur.y += acc[i][j4 * 4 + 1] + bv[j4 * 4 + 1];
                cur.z += acc[i][j4 * 4 + 2] + bv[j4 * 4 + 2];
                cur.w += acc[i][j4 * 4 + 3] + bv[j4 * 4 + 3];
                *(float4*)(OUT + base + j4 * 4) = cur;
            }
        }
    }
}

// -------- host launcher --------
extern "C" void kernel_launch(void* const* d_in, const int* in_sizes, int n_in,
                              void* d_out, int out_size) {
    const float* x      = (const float*)d_in[0];
    const int*   ei     = (const int*)  d_in[1];
    const float* ew     = (const float*)d_in[2];
    const float* cheb_w = (const float*)d_in[3];
    const float* cheb_b = (const float*)d_in[4];
    const float* beta   = (const float*)d_in[5];
    const float* w1     = (const float*)d_in[6];
    const float* b1     = (const float*)d_in[7];
    const float* w2     = (const float*)d_in[8];
    const float* b2     = (const float*)d_in[9];
    float* out = (float*)d_out;
    const int* src = ei;
    const int* dst = ei + Ee;

    constexpr int SMEM_CHEB = (128 * 196 + 192 * 128) * 4;  // 198656 B
    constexpr int SMEM_M1   = (128 * 132 + 128 * 128) * 4;  // 133120 B
    constexpr int SMEM_M2   = (128 * 132 + 128 * 64)  * 4;  // 100352 B
    cudaFuncSetAttribute((const void*)gemm_kernel<192,128,0>,
                         cudaFuncAttributeMaxDynamicSharedMemorySize, SMEM_CHEB);
    cudaFuncSetAttribute((const void*)gemm_kernel<128,128,0>,
                         cudaFuncAttributeMaxDynamicSharedMemorySize, SMEM_M1);
    cudaFuncSetAttribute((const void*)gemm_kernel<128,64,1>,
                         cudaFuncAttributeMaxDynamicSharedMemorySize, SMEM_M2);

    const int EB = (Ee + 255) / 256;     // 2500
    const int NBk = (Nn + 255) / 256;    // 79

    zero_deg_cnt<<<NBk, 256>>>();
    deg_kernel<<<EB, 256>>>(src, ew);
    dinv_kernel<<<NBk, 256>>>();
    w_count_kernel<<<EB, 256>>>(src, dst, ew);
    scan_kernel<<<1, 1024>>>();
    zero_cnt<<<NBk, 256>>>();
    fill_kernel<<<EB, 256>>>(src, dst);

    t_in_kernel<<<Nn, 256>>>((const float4*)x);   // 20000 blocks: 5.12M float4

    for (int b = 0; b < NBlk; ++b) {
        spmm_kernel<0><<<Nn, 256>>>();                       // t1 = Lhat h
        spmm_kernel<1><<<Nn, 256>>>();                       // t2raw = Lhat t1
        prep_wc<<<32, 256>>>(cheb_w, b);
        gemm_kernel<192,128,0><<<2500, 256, SMEM_CHEB>>>(nullptr, cheb_b + b * 128, beta + b);
        gemm_kernel<128,128,0><<<2500, 256, SMEM_M1>>>(w1 + (size_t)b * 128 * 128, b1 + b * 128, beta + b);
        gemm_kernel<128,64,1> <<<2500, 256, SMEM_M2>>>(w2 + (size_t)b * 128 * 64,  b2 + b * 64,  beta + b);
    }

    t_out_kernel<<<Nn, 256>>>((float4*)out);
}

// round 2
// speedup vs baseline: 1.3033x; 1.3033x over previous
#include <cuda_runtime.h>
#include <stdint.h>
#include <math.h>

// Problem constants
constexpr int Bc   = 16;
constexpr int Nn   = 20000;
constexpr int Cc   = 64;
constexpr int DIMc = 128;
constexpr int Ee   = 640000;
constexpr int NBlk = 3;
constexpr int ROWS = Nn * Bc;          // 320000
constexpr int RowF = Bc * Cc;          // 1024 floats per node row (h/t layout [N][B][C])
constexpr int RowF4 = RowF / 4;        // 256 float4

// -------- device scratch (static: allocation is forbidden) --------
__device__ float g_h [ROWS * Cc];      // [N][B][64]   81.9 MB
__device__ float g_t1[ROWS * Cc];
__device__ float g_t2[ROWS * Cc];
__device__ float g_a1[ROWS * DIMc];    // [N*B][128]  163.8 MB
__device__ float g_a2[ROWS * DIMc];
__device__ float g_deg [Nn];
__device__ float g_dinv[Nn];
__device__ float g_w   [Ee];
__device__ int   g_off [Nn + 1];
__device__ int   g_cnt [Nn];
__device__ int   g_csrc[Ee];
__device__ float g_csw [Ee];
__device__ float g_wc  [192 * 128];    // prepacked cheb weights [W0-W2 | W1 | 2W2]

// -------- small setup kernels --------
__global__ void zero_deg_cnt() {
    int i = blockIdx.x * blockDim.x + threadIdx.x;
    if (i < Nn) { g_deg[i] = 0.f; g_cnt[i] = 0; }
}
__global__ void zero_cnt() {
    int i = blockIdx.x * blockDim.x + threadIdx.x;
    if (i < Nn) g_cnt[i] = 0;
}
__global__ void deg_kernel(const int* __restrict__ src, const float* __restrict__ ew) {
    int e = blockIdx.x * blockDim.x + threadIdx.x;
    if (e < Ee) atomicAdd(&g_deg[src[e]], ew[e]);
}
__global__ void dinv_kernel() {
    int i = blockIdx.x * blockDim.x + threadIdx.x;
    if (i < Nn) {
        float d = g_deg[i];
        g_dinv[i] = (d > 0.f) ? rsqrtf(fmaxf(d, 1e-12f)) : 0.f;
    }
}
__global__ void w_count_kernel(const int* __restrict__ src, const int* __restrict__ dst,
                               const float* __restrict__ ew) {
    int e = blockIdx.x * blockDim.x + threadIdx.x;
    if (e < Ee) {
        int s = src[e], d = dst[e];
        g_w[e] = -g_dinv[s] * ew[e] * g_dinv[d];
        atomicAdd(&g_cnt[d], 1);
    }
}
// single-block exclusive scan over g_cnt[0..Nn) -> g_off, g_off[Nn] = total
__global__ void scan_kernel() {
    __shared__ int warp_sums[32];
    __shared__ int s_carry;
    int t = threadIdx.x;                 // 1024 threads
    if (t == 0) s_carry = 0;
    __syncthreads();
    for (int base = 0; base < Nn; base += 1024) {
        int v = (base + t < Nn) ? g_cnt[base + t] : 0;
        int x = v;
        #pragma unroll
        for (int d = 1; d < 32; d <<= 1) {
            int y = __shfl_up_sync(0xFFFFFFFFu, x, d);
            if ((t & 31) >= d) x += y;
        }
        if ((t & 31) == 31) warp_sums[t >> 5] = x;
        __syncthreads();
        if (t < 32) {
            int y = warp_sums[t];
            #pragma unroll
            for (int d = 1; d < 32; d <<= 1) {
                int z = __shfl_up_sync(0xFFFFFFFFu, y, d);
                if (t >= d) y += z;
            }
            warp_sums[t] = y;
        }
        __syncthreads();
        int excl = s_carry + (x - v) + ((t >= 32) ? warp_sums[(t >> 5) - 1] : 0);
        if (base + t < Nn) g_off[base + t] = excl;
        __syncthreads();
        if (t == 0) s_carry += warp_sums[31];
        __syncthreads();
    }
    if (t == 0) g_off[Nn] = s_carry;
}
__global__ void fill_kernel(const int* __restrict__ src, const int* __restrict__ dst) {
    int e = blockIdx.x * blockDim.x + threadIdx.x;
    if (e < Ee) {
        int d = dst[e];
        int pos = g_off[d] + atomicAdd(&g_cnt[d], 1);
        g_csrc[pos] = src[e];
        g_csw[pos]  = g_w[e];
    }
}

// -------- layout transforms: x [B][N][C] <-> h [N][B][C] (as float4) --------
__global__ void t_in_kernel(const float4* __restrict__ x4) {
    int idx = blockIdx.x * 256 + threadIdx.x;        // 5,120,000 total
    int b = idx / (Nn * 16);
    int r = idx % (Nn * 16);
    int n = r >> 4, c4 = r & 15;
    ((float4*)g_h)[n * RowF4 + b * 16 + c4] = x4[idx];
}
__global__ void t_out_kernel(float4* __restrict__ o4) {
    int idx = blockIdx.x * 256 + threadIdx.x;
    int b = idx / (Nn * 16);
    int r = idx % (Nn * 16);
    int n = r >> 4, c4 = r & 15;
    o4[idx] = ((const float4*)g_h)[n * RowF4 + b * 16 + c4];
}

// -------- SpMM: out[n] = sum_{e in CSR(n)} w_e * in[src_e], row = 1024 floats --------
template <int PHASE>
__global__ void spmm_kernel() {
    const float4* __restrict__ in = (PHASE == 0) ? (const float4*)g_h : (const float4*)g_t1;
    float4* __restrict__ out      = (PHASE == 0) ? (float4*)g_t1      : (float4*)g_t2;
    int n = blockIdx.x;
    int t = threadIdx.x;                 // 256 threads == RowF4
    int e0 = g_off[n], e1 = g_off[n + 1];
    float4 acc = make_float4(0.f, 0.f, 0.f, 0.f);
    #pragma unroll 4
    for (int e = e0; e < e1; ++e) {
        int   s  = __ldg(&g_csrc[e]);
        float wv = __ldg(&g_csw[e]);
        float4 v = __ldg(&in[(size_t)s * RowF4 + t]);
        acc.x = fmaf(wv, v.x, acc.x);
        acc.y = fmaf(wv, v.y, acc.y);
        acc.z = fmaf(wv, v.z, acc.z);
        acc.w = fmaf(wv, v.w, acc.w);
    }
    out[(size_t)n * RowF4 + t] = acc;
}

// -------- prepack cheb weights for block b: [W0-W2 | W1 | 2*W2] (192x128) --------
__global__ void prep_wc(const float* __restrict__ cw, int b) {
    int idx = blockIdx.x * 256 + threadIdx.x;        // 8192 total
    if (idx < 64 * 128) {
        const float* base = cw + (size_t)b * 3 * 64 * 128;
        float w0 = base[idx];
        float w1v = base[8192 + idx];
        float w2v = base[16384 + idx];
        g_wc[idx]          = w0 - w2v;
        g_wc[8192 + idx]   = w1v;
        g_wc[16384 + idx]  = 2.f * w2v;
    }
}

// -------- 3xTF32 tensor-core GEMM --------
__device__ __forceinline__ void split_tf32(float v, uint32_t& hi, uint32_t& lo) {
    uint32_t h;
    asm("cvt.rna.tf32.f32 %0, %1;" : "=r"(h) : "f"(v));
    float r = v - __uint_as_float(h);
    uint32_t l;
    asm("cvt.rna.tf32.f32 %0, %1;" : "=r"(l) : "f"(r));
    hi = h; lo = l;
}
__device__ __forceinline__ void mma8(float* c, const uint32_t* a, const uint32_t* b) {
    asm volatile(
        "mma.sync.aligned.m16n8k8.row.col.f32.tf32.tf32.f32 "
        "{%0,%1,%2,%3}, {%4,%5,%6,%7}, {%8,%9}, {%0,%1,%2,%3};\n"
        : "+f"(c[0]), "+f"(c[1]), "+f"(c[2]), "+f"(c[3])
        : "r"(a[0]), "r"(a[1]), "r"(a[2]), "r"(a[3]), "r"(b[0]), "r"(b[1]));
}

// GEMM: [320000 x KTOT] @ [KTOT x BN] + bias, optional swish / residual
// MODE 0: out = swish(A@W + bias)         (cheb -> g_a1, mlp1 -> g_a2)
// MODE 1: out += A@W + bias               (mlp2: h += Fx)
template <int KTOT, int BN, int MODE>
__global__ void __launch_bounds__(256)
gemm_tc(const float* __restrict__ Wext, const float* __restrict__ bias,
        const float* __restrict__ betaPtr) {
    constexpr int BM = 128;
    constexpr int KC = 64;
    constexpr int NCHUNK = KTOT / KC;
    constexpr int PA = KC + 4;           // 68
    constexpr int PB = BN + 4;           // 132 or 68
    constexpr int WROWS = (BN == 128) ? 2 : 4;
    constexpr int WCOLS = 8 / WROWS;
    constexpr int MI = (BM / WROWS) / 16;    // 4 or 2
    constexpr int NI = (BN / WCOLS) / 8;     // 4

    const float* A0; float* OUT;
    if constexpr (KTOT == 192)      { A0 = nullptr; OUT = g_a1; }
    else if constexpr (BN == 128)   { A0 = g_a1;    OUT = g_a2; }
    else                            { A0 = g_a2;    OUT = g_h;  }
    const float* Wsrc = (KTOT == 192) ? g_wc : Wext;

    extern __shared__ uint32_t sm[];
    uint32_t* Ah = sm;                    // [BM][PA]
    uint32_t* Al = Ah + BM * PA;
    uint32_t* Bh = Al + BM * PA;          // [KC][PB]
    uint32_t* Bl = Bh + KC * PB;

    const int tid  = threadIdx.x;
    const int warp = tid >> 5, lane = tid & 31;
    const int gq   = lane >> 2, l4 = lane & 3;
    const int wm   = warp / WCOLS, wn = warp % WCOLS;
    const int m0w  = wm * (BM / WROWS);
    const int n0w  = wn * (BN / WCOLS);
    const int mblk = blockIdx.x * BM;

    float acc[MI][NI][4];
    #pragma unroll
    for (int mi = 0; mi < MI; ++mi)
        #pragma unroll
        for (int ni = 0; ni < NI; ++ni)
            #pragma unroll
            for (int q = 0; q < 4; ++q) acc[mi][ni][q] = 0.f;

    for (int ch = 0; ch < NCHUNK; ++ch) {
        if (ch) __syncthreads();
        // ---- fill A chunk (hi/lo split) ----
        const float* Asrc;
        int rowStride, col0;
        if constexpr (KTOT == 192) {
            Asrc = (ch == 0) ? g_h : (ch == 1) ? g_t1 : g_t2;
            rowStride = 64; col0 = 0;
        } else {
            Asrc = A0; rowStride = KTOT; col0 = ch * KC;
        }
        for (int i = tid; i < BM * (KC / 4); i += 256) {
            int m = i >> 4, q = i & 15;
            float4 v = *(const float4*)(Asrc + (size_t)(mblk + m) * rowStride + col0 + q * 4);
            uint4 h4, l4v;
            split_tf32(v.x, h4.x, l4v.x);
            split_tf32(v.y, h4.y, l4v.y);
            split_tf32(v.z, h4.z, l4v.z);
            split_tf32(v.w, h4.w, l4v.w);
            *(uint4*)(Ah + m * PA + q * 4) = h4;
            *(uint4*)(Al + m * PA + q * 4) = l4v;
        }
        // ---- fill B chunk ----
        for (int i = tid; i < KC * (BN / 4); i += 256) {
            int k = i / (BN / 4), q = i % (BN / 4);
            float4 v = *(const float4*)(Wsrc + (size_t)(ch * KC + k) * BN + q * 4);
            uint4 h4, l4v;
            split_tf32(v.x, h4.x, l4v.x);
            split_tf32(v.y, h4.y, l4v.y);
            split_tf32(v.z, h4.z, l4v.z);
            split_tf32(v.w, h4.w, l4v.w);
            *(uint4*)(Bh + k * PB + q * 4) = h4;
            *(uint4*)(Bl + k * PB + q * 4) = l4v;
        }
        __syncthreads();

        // ---- mma over the chunk ----
        #pragma unroll
        for (int ks = 0; ks < KC; ks += 8) {
            uint32_t ah[MI][4], al[MI][4];
            #pragma unroll
            for (int mi = 0; mi < MI; ++mi) {
                int r = m0w + mi * 16 + gq;
                ah[mi][0] = Ah[r * PA + ks + l4];
                ah[mi][1] = Ah[(r + 8) * PA + ks + l4];
                ah[mi][2] = Ah[r * PA + ks + 4 + l4];
                ah[mi][3] = Ah[(r + 8) * PA + ks + 4 + l4];
                al[mi][0] = Al[r * PA + ks + l4];
                al[mi][1] = Al[(r + 8) * PA + ks + l4];
                al[mi][2] = Al[r * PA + ks + 4 + l4];
                al[mi][3] = Al[(r + 8) * PA + ks + 4 + l4];
            }
            uint32_t bh[NI][2], bl[NI][2];
            #pragma unroll
            for (int ni = 0; ni < NI; ++ni) {
                int n = n0w + ni * 8 + gq;
                bh[ni][0] = Bh[(ks + l4) * PB + n];
                bh[ni][1] = Bh[(ks + 4 + l4) * PB + n];
                bl[ni][0] = Bl[(ks + l4) * PB + n];
                bl[ni][1] = Bl[(ks + 4 + l4) * PB + n];
            }
            #pragma unroll
            for (int mi = 0; mi < MI; ++mi)
                #pragma unroll
                for (int ni = 0; ni < NI; ++ni) {
                    mma8(acc[mi][ni], ah[mi], bh[ni]);
                    mma8(acc[mi][ni], al[mi], bh[ni]);
                    mma8(acc[mi][ni], ah[mi], bl[ni]);
                }
        }
    }

    // ---- epilogue ----
    float spv = 0.f;
    if constexpr (MODE == 0) spv = log1pf(__expf(*betaPtr));

    #pragma unroll
    for (int mi = 0; mi < MI; ++mi) {
        int r0 = mblk + m0w + mi * 16 + gq;
        #pragma unroll
        for (int ni = 0; ni < NI; ++ni) {
            int c = n0w + ni * 8 + 2 * l4;
            float b0 = __ldg(bias + c), b1 = __ldg(bias + c + 1);
            float v00 = acc[mi][ni][0] + b0, v01 = acc[mi][ni][1] + b1;
            float v10 = acc[mi][ni][2] + b0, v11 = acc[mi][ni][3] + b1;
            if constexpr (MODE == 0) {
                v00 = v00 / (1.1f * (1.f + __expf(-v00 * spv)));
                v01 = v01 / (1.1f * (1.f + __expf(-v01 * spv)));
                v10 = v10 / (1.1f * (1.f + __expf(-v10 * spv)));
                v11 = v11 / (1.1f * (1.f + __expf(-v11 * spv)));
                *(float2*)(OUT + (size_t)r0 * BN + c)       = make_float2(v00, v01);
                *(float2*)(OUT + (size_t)(r0 + 8) * BN + c) = make_float2(v10, v11);
            } else {
                float2 cur0 = *(float2*)(OUT + (size_t)r0 * BN + c);
                float2 cur1 = *(float2*)(OUT + (size_t)(r0 + 8) * BN + c);
                cur0.x += v00; cur0.y += v01;
                cur1.x += v10; cur1.y += v11;
                *(float2*)(OUT + (size_t)r0 * BN + c)       = cur0;
                *(float2*)(OUT + (size_t)(r0 + 8) * BN + c) = cur1;
            }
        }
    }
}

// -------- host launcher --------
extern "C" void kernel_launch(void* const* d_in, const int* in_sizes, int n_in,
                              void* d_out, int out_size) {
    const float* x      = (const float*)d_in[0];
    const int*   ei     = (const int*)  d_in[1];
    const float* ew     = (const float*)d_in[2];
    const float* cheb_w = (const float*)d_in[3];
    const float* cheb_b = (const float*)d_in[4];
    const float* beta   = (const float*)d_in[5];
    const float* w1     = (const float*)d_in[6];
    const float* b1     = (const float*)d_in[7];
    const float* w2     = (const float*)d_in[8];
    const float* b2     = (const float*)d_in[9];
    float* out = (float*)d_out;
    const int* src = ei;
    const int* dst = ei + Ee;

    // smem: A(hi+lo) = 2*128*68*4 = 69632 B ; B(hi+lo) = 2*64*(BN+4)*4
    constexpr int SMEM_128 = 69632 + 2 * 64 * 132 * 4;  // 137216
    constexpr int SMEM_64  = 69632 + 2 * 64 * 68 * 4;   // 104448
    cudaFuncSetAttribute((const void*)gemm_tc<192,128,0>,
                         cudaFuncAttributeMaxDynamicSharedMemorySize, SMEM_128);
    cudaFuncSetAttribute((const void*)gemm_tc<128,128,0>,
                         cudaFuncAttributeMaxDynamicSharedMemorySize, SMEM_128);
    cudaFuncSetAttribute((const void*)gemm_tc<128,64,1>,
                         cudaFuncAttributeMaxDynamicSharedMemorySize, SMEM_64);

    const int EB = (Ee + 255) / 256;     // 2500
    const int NBk = (Nn + 255) / 256;    // 79

    zero_deg_cnt<<<NBk, 256>>>();
    deg_kernel<<<EB, 256>>>(src, ew);
    dinv_kernel<<<NBk, 256>>>();
    w_count_kernel<<<EB, 256>>>(src, dst, ew);
    scan_kernel<<<1, 1024>>>();
    zero_cnt<<<NBk, 256>>>();
    fill_kernel<<<EB, 256>>>(src, dst);

    t_in_kernel<<<Nn, 256>>>((const float4*)x);

    for (int b = 0; b < NBlk; ++b) {
        spmm_kernel<0><<<Nn, 256>>>();                       // t1 = Lhat h
        spmm_kernel<1><<<Nn, 256>>>();                       // t2raw = Lhat t1
        prep_wc<<<32, 256>>>(cheb_w, b);
        gemm_tc<192,128,0><<<2500, 256, SMEM_128>>>(nullptr, cheb_b + b * 128, beta + b);
        gemm_tc<128,128,0><<<2500, 256, SMEM_128>>>(w1 + (size_t)b * 128 * 128, b1 + b * 128, beta + b);
        gemm_tc<128,64,1> <<<2500, 256, SMEM_64>>>(w2 + (size_t)b * 128 * 64,  b2 + b * 64,  beta + b);
    }

    t_out_kernel<<<Nn, 256>>>((float4*)out);
}

// round 3
// speedup vs baseline: 1.4666x; 1.1253x over previous
#include <cuda_runtime.h>
#include <cuda_fp16.h>
#include <stdint.h>
#include <math.h>

// Problem constants
constexpr int Bc   = 16;
constexpr int Nn   = 20000;
constexpr int Cc   = 64;
constexpr int Ee   = 640000;
constexpr int NBlk = 3;
constexpr int ROWS = Nn * Bc;          // 320000
constexpr int RowF = Bc * Cc;          // 1024 floats per node row ([N][B][C])
constexpr int RowF4 = RowF / 4;        // 256 float4

// -------- device scratch (static: allocation is forbidden) --------
__device__ float  g_h  [ROWS * Cc];    // fp32 h  [N][B][64]   81.9 MB
__device__ __half g_hh [ROWS * Cc];    // fp16 h                41.0 MB
__device__ __half g_t1h[ROWS * Cc];    // fp16 t1
__device__ __half g_t2h[ROWS * Cc];    // fp16 t2
__device__ float g_deg [Nn];
__device__ float g_dinv[Nn];
__device__ float g_w   [Ee];
__device__ int   g_off [Nn + 1];
__device__ int   g_cnt [Nn];
__device__ int   g_csrc[Ee];
__device__ float g_csw [Ee];
__device__ float g_wc  [192 * 128];    // prepacked cheb weights [W0-W2 | W1 | 2W2]

// -------- small setup kernels --------
__global__ void zero_deg_cnt() {
    int i = blockIdx.x * blockDim.x + threadIdx.x;
    if (i < Nn) { g_deg[i] = 0.f; g_cnt[i] = 0; }
}
__global__ void zero_cnt() {
    int i = blockIdx.x * blockDim.x + threadIdx.x;
    if (i < Nn) g_cnt[i] = 0;
}
__global__ void deg_kernel(const int* __restrict__ src, const float* __restrict__ ew) {
    int e = blockIdx.x * blockDim.x + threadIdx.x;
    if (e < Ee) atomicAdd(&g_deg[src[e]], ew[e]);
}
__global__ void dinv_kernel() {
    int i = blockIdx.x * blockDim.x + threadIdx.x;
    if (i < Nn) {
        float d = g_deg[i];
        g_dinv[i] = (d > 0.f) ? rsqrtf(fmaxf(d, 1e-12f)) : 0.f;
    }
}
__global__ void w_count_kernel(const int* __restrict__ src, const int* __restrict__ dst,
                               const float* __restrict__ ew) {
    int e = blockIdx.x * blockDim.x + threadIdx.x;
    if (e < Ee) {
        int s = src[e], d = dst[e];
        g_w[e] = -g_dinv[s] * ew[e] * g_dinv[d];
        atomicAdd(&g_cnt[d], 1);
    }
}
__global__ void scan_kernel() {
    __shared__ int warp_sums[32];
    __shared__ int s_carry;
    int t = threadIdx.x;                 // 1024 threads
    if (t == 0) s_carry = 0;
    __syncthreads();
    for (int base = 0; base < Nn; base += 1024) {
        int v = (base + t < Nn) ? g_cnt[base + t] : 0;
        int x = v;
        #pragma unroll
        for (int d = 1; d < 32; d <<= 1) {
            int y = __shfl_up_sync(0xFFFFFFFFu, x, d);
            if ((t & 31) >= d) x += y;
        }
        if ((t & 31) == 31) warp_sums[t >> 5] = x;
        __syncthreads();
        if (t < 32) {
            int y = warp_sums[t];
            #pragma unroll
            for (int d = 1; d < 32; d <<= 1) {
                int z = __shfl_up_sync(0xFFFFFFFFu, y, d);
                if (t >= d) y += z;
            }
            warp_sums[t] = y;
        }
        __syncthreads();
        int excl = s_carry + (x - v) + ((t >= 32) ? warp_sums[(t >> 5) - 1] : 0);
        if (base + t < Nn) g_off[base + t] = excl;
        __syncthreads();
        if (t == 0) s_carry += warp_sums[31];
        __syncthreads();
    }
    if (t == 0) g_off[Nn] = s_carry;
}
__global__ void fill_kernel(const int* __restrict__ src, const int* __restrict__ dst) {
    int e = blockIdx.x * blockDim.x + threadIdx.x;
    if (e < Ee) {
        int d = dst[e];
        int pos = g_off[d] + atomicAdd(&g_cnt[d], 1);
        g_csrc[pos] = src[e];
        g_csw[pos]  = g_w[e];
    }
}

// -------- layout transforms: x [B][N][C] -> h [N][B][C] (fp32 + fp16) --------
__global__ void t_in_kernel(const float4* __restrict__ x4) {
    int idx = blockIdx.x * 256 + threadIdx.x;        // 5,120,000 total
    int b = idx / (Nn * 16);
    int r = idx % (Nn * 16);
    int n = r >> 4, c4 = r & 15;
    float4 v = x4[idx];
    int o4 = n * RowF4 + b * 16 + c4;
    ((float4*)g_h)[o4] = v;
    __half2 h0 = __floats2half2_rn(v.x, v.y);
    __half2 h1 = __floats2half2_rn(v.z, v.w);
    ((__half2*)g_hh)[o4 * 2]     = h0;
    ((__half2*)g_hh)[o4 * 2 + 1] = h1;
}
__global__ void t_out_kernel(float4* __restrict__ o4) {
    int idx = blockIdx.x * 256 + threadIdx.x;
    int b = idx / (Nn * 16);
    int r = idx % (Nn * 16);
    int n = r >> 4, c4 = r & 15;
    o4[idx] = ((const float4*)g_h)[n * RowF4 + b * 16 + c4];
}

// -------- SpMM fp16: out[n] = sum_e w_e * in[src_e]; row = 1024 halfs = 2KB --------
// 128 threads/block, each owns 8 halfs (16B)
template <int PHASE>
__global__ void __launch_bounds__(128) spmm16_kernel() {
    const __half* __restrict__ in = (PHASE == 0) ? g_hh : g_t1h;
    __half* __restrict__ out      = (PHASE == 0) ? g_t1h : g_t2h;
    int n = blockIdx.x;
    int t = threadIdx.x;
    int e0 = g_off[n], e1 = g_off[n + 1];
    float acc[8];
    #pragma unroll
    for (int q = 0; q < 8; ++q) acc[q] = 0.f;
    #pragma unroll 4
    for (int e = e0; e < e1; ++e) {
        int   s  = __ldg(&g_csrc[e]);
        float wv = __ldg(&g_csw[e]);
        uint4 raw = __ldg((const uint4*)(in + (size_t)s * RowF) + t);
        const __half2* hp = (const __half2*)&raw;
        #pragma unroll
        for (int p = 0; p < 4; ++p) {
            float2 f = __half22float2(hp[p]);
            acc[2 * p]     = fmaf(wv, f.x, acc[2 * p]);
            acc[2 * p + 1] = fmaf(wv, f.y, acc[2 * p + 1]);
        }
    }
    uint4 res;
    __half2* rp = (__half2*)&res;
    #pragma unroll
    for (int p = 0; p < 4; ++p)
        rp[p] = __floats2half2_rn(acc[2 * p], acc[2 * p + 1]);
    ((uint4*)(out + (size_t)n * RowF))[t] = res;
}

// -------- prepack cheb weights: [W0-W2 | W1 | 2*W2] (192x128) --------
__global__ void prep_wc(const float* __restrict__ cw, int b) {
    int idx = blockIdx.x * 256 + threadIdx.x;
    if (idx < 64 * 128) {
        const float* base = cw + (size_t)b * 3 * 64 * 128;
        float w0  = base[idx];
        float w1v = base[8192 + idx];
        float w2v = base[16384 + idx];
        g_wc[idx]         = w0 - w2v;
        g_wc[8192 + idx]  = w1v;
        g_wc[16384 + idx] = 2.f * w2v;
    }
}

// -------- 3xTF32 helpers --------
__device__ __forceinline__ void split_tf32(float v, uint32_t& hi, uint32_t& lo) {
    uint32_t h;
    asm("cvt.rna.tf32.f32 %0, %1;" : "=r"(h) : "f"(v));
    float r = v - __uint_as_float(h);
    uint32_t l;
    asm("cvt.rna.tf32.f32 %0, %1;" : "=r"(l) : "f"(r));
    hi = h; lo = l;
}
__device__ __forceinline__ uint32_t to_tf32(float v) {
    uint32_t h;
    asm("cvt.rna.tf32.f32 %0, %1;" : "=r"(h) : "f"(v));
    return h;
}
__device__ __forceinline__ void mma8(float* c, const uint32_t* a, const uint32_t* b) {
    asm volatile(
        "mma.sync.aligned.m16n8k8.row.col.f32.tf32.tf32.f32 "
        "{%0,%1,%2,%3}, {%4,%5,%6,%7}, {%8,%9}, {%0,%1,%2,%3};\n"
        : "+f"(c[0]), "+f"(c[1]), "+f"(c[2]), "+f"(c[3])
        : "r"(a[0]), "r"(a[1]), "r"(a[2]), "r"(a[3]), "r"(b[0]), "r"(b[1]));
}

constexpr int PA  = 68;                // A smem pitch (u32)
constexpr int PB  = 132;               // B smem pitch (u32), BN=128
constexpr int PB3 = 68;                // B smem pitch, BN=64
constexpr int PG  = 132;               // G smem pitch (float)

// mma over one K=64 chunk; MI=4 (warp covers 64 rows), NI = BN/WCOLS/8
template <int NI, int PBx>
__device__ __forceinline__ void mma_chunk(
    const uint32_t* __restrict__ Ah, const uint32_t* __restrict__ Al,
    const uint32_t* __restrict__ Bh, const uint32_t* __restrict__ Bl,
    int m0w, int n0w, int gq, int l4, float acc[4][NI][4], bool useLo)
{
    #pragma unroll
    for (int ks = 0; ks < 64; ks += 8) {
        uint32_t ah[4][4], al[4][4];
        #pragma unroll
        for (int mi = 0; mi < 4; ++mi) {
            int r = m0w + mi * 16 + gq;
            ah[mi][0] = Ah[r * PA + ks + l4];
            ah[mi][1] = Ah[(r + 8) * PA + ks + l4];
            ah[mi][2] = Ah[r * PA + ks + 4 + l4];
            ah[mi][3] = Ah[(r + 8) * PA + ks + 4 + l4];
            if (useLo) {
                al[mi][0] = Al[r * PA + ks + l4];
                al[mi][1] = Al[(r + 8) * PA + ks + l4];
                al[mi][2] = Al[r * PA + ks + 4 + l4];
                al[mi][3] = Al[(r + 8) * PA + ks + 4 + l4];
            }
        }
        uint32_t bh[NI][2], bl[NI][2];
        #pragma unroll
        for (int ni = 0; ni < NI; ++ni) {
            int n = n0w + ni * 8 + gq;
            bh[ni][0] = Bh[(ks + l4) * PBx + n];
            bh[ni][1] = Bh[(ks + 4 + l4) * PBx + n];
            bl[ni][0] = Bl[(ks + l4) * PBx + n];
            bl[ni][1] = Bl[(ks + 4 + l4) * PBx + n];
        }
        #pragma unroll
        for (int mi = 0; mi < 4; ++mi)
            #pragma unroll
            for (int ni = 0; ni < NI; ++ni) {
                mma8(acc[mi][ni], ah[mi], bh[ni]);
                if (useLo) mma8(acc[mi][ni], al[mi], bh[ni]);
                mma8(acc[mi][ni], ah[mi], bl[ni]);
            }
    }
}

// -------- fused per-block kernel: cheb GEMM -> swish -> MLP1 -> swish -> MLP2 -> h += --------
__global__ void __launch_bounds__(256)
fused_block(const float* __restrict__ W1, const float* __restrict__ b1,
            const float* __restrict__ W2, const float* __restrict__ b2,
            const float* __restrict__ cb, const float* __restrict__ betaPtr)
{
    extern __shared__ uint32_t sm[];
    uint32_t* Ah = sm;                     // [128][68]
    uint32_t* Al = Ah + 128 * PA;
    uint32_t* Bh = Al + 128 * PA;          // [64][132]
    uint32_t* Bl = Bh + 64 * PB;
    float*    Gf = (float*)(Bl + 64 * PB); // [128][132]

    const int tid  = threadIdx.x;
    const int warp = tid >> 5, lane = tid & 31;
    const int gq   = lane >> 2, l4 = lane & 3;
    const int wm   = warp >> 2, wn = warp & 3;   // 2 x 4 warp grid
    const int m0w  = wm * 64;
    const int mblk = blockIdx.x * 128;
    const float spv = log1pf(__expf(*betaPtr));

    // ================= Stage 1: cheb (K=192: h fp32, t1h, t2h) =================
    {
        const int n0w = wn * 32;
        float acc[4][4][4];
        #pragma unroll
        for (int mi = 0; mi < 4; ++mi)
            #pragma unroll
            for (int ni = 0; ni < 4; ++ni)
                #pragma unroll
                for (int q = 0; q < 4; ++q) acc[mi][ni][q] = 0.f;

        for (int ch = 0; ch < 3; ++ch) {
            if (ch) __syncthreads();
            // A fill
            if (ch == 0) {
                for (int i = tid; i < 128 * 16; i += 256) {
                    int m = i >> 4, q = i & 15;
                    float4 v = *(const float4*)(g_h + (size_t)(mblk + m) * 64 + q * 4);
                    uint4 h4, l4v;
                    split_tf32(v.x, h4.x, l4v.x);
                    split_tf32(v.y, h4.y, l4v.y);
                    split_tf32(v.z, h4.z, l4v.z);
                    split_tf32(v.w, h4.w, l4v.w);
                    *(uint4*)(Ah + m * PA + q * 4) = h4;
                    *(uint4*)(Al + m * PA + q * 4) = l4v;
                }
            } else {
                const __half* srcH = (ch == 1) ? g_t1h : g_t2h;
                for (int i = tid; i < 128 * 16; i += 256) {
                    int m = i >> 4, q = i & 15;
                    uint2 raw = *(const uint2*)(srcH + (size_t)(mblk + m) * 64 + q * 4);
                    const __half2* hp = (const __half2*)&raw;
                    float2 f0 = __half22float2(hp[0]);
                    float2 f1 = __half22float2(hp[1]);
                    uint4 h4;
                    h4.x = to_tf32(f0.x); h4.y = to_tf32(f0.y);
                    h4.z = to_tf32(f1.x); h4.w = to_tf32(f1.y);
                    *(uint4*)(Ah + m * PA + q * 4) = h4;   // exact: fp16 in tf32, lo == 0
                }
            }
            // B fill (g_wc chunk)
            for (int i = tid; i < 64 * 32; i += 256) {
                int k = i >> 5, q = i & 31;
                float4 v = *(const float4*)(g_wc + (size_t)(ch * 64 + k) * 128 + q * 4);
                uint4 h4, l4v;
                split_tf32(v.x, h4.x, l4v.x);
                split_tf32(v.y, h4.y, l4v.y);
                split_tf32(v.z, h4.z, l4v.z);
                split_tf32(v.w, h4.w, l4v.w);
                *(uint4*)(Bh + k * PB + q * 4) = h4;
                *(uint4*)(Bl + k * PB + q * 4) = l4v;
            }
            __syncthreads();
            mma_chunk<4, PB>(Ah, Al, Bh, Bl, m0w, n0w, gq, l4, acc, ch == 0);
        }
        // epilogue: swish -> Gf
        #pragma unroll
        for (int mi = 0; mi < 4; ++mi) {
            int r0 = m0w + mi * 16 + gq;
            #pragma unroll
            for (int ni = 0; ni < 4; ++ni) {
                int c = n0w + ni * 8 + 2 * l4;
                float bb0 = __ldg(cb + c), bb1 = __ldg(cb + c + 1);
                float v00 = acc[mi][ni][0] + bb0, v01 = acc[mi][ni][1] + bb1;
                float v10 = acc[mi][ni][2] + bb0, v11 = acc[mi][ni][3] + bb1;
                v00 = v00 / (1.1f * (1.f + __expf(-v00 * spv)));
                v01 = v01 / (1.1f * (1.f + __expf(-v01 * spv)));
                v10 = v10 / (1.1f * (1.f + __expf(-v10 * spv)));
                v11 = v11 / (1.1f * (1.f + __expf(-v11 * spv)));
                *(float2*)(Gf + r0 * PG + c)       = make_float2(v00, v01);
                *(float2*)(Gf + (r0 + 8) * PG + c) = make_float2(v10, v11);
            }
        }
    }
    __syncthreads();

    // ================= Stage 2: MLP1 (K=128 from Gf, BN=128) =================
    {
        const int n0w = wn * 32;
        float acc[4][4][4];
        #pragma unroll
        for (int mi = 0; mi < 4; ++mi)
            #pragma unroll
            for (int ni = 0; ni < 4; ++ni)
                #pragma unroll
                for (int q = 0; q < 4; ++q) acc[mi][ni][q] = 0.f;

        for (int ch = 0; ch < 2; ++ch) {
            if (ch) __syncthreads();
            for (int i = tid; i < 128 * 16; i += 256) {
                int m = i >> 4, q = i & 15;
                float4 v = *(const float4*)(Gf + m * PG + ch * 64 + q * 4);
                uint4 h4, l4v;
                split_tf32(v.x, h4.x, l4v.x);
                split_tf32(v.y, h4.y, l4v.y);
                split_tf32(v.z, h4.z, l4v.z);
                split_tf32(v.w, h4.w, l4v.w);
                *(uint4*)(Ah + m * PA + q * 4) = h4;
                *(uint4*)(Al + m * PA + q * 4) = l4v;
            }
            for (int i = tid; i < 64 * 32; i += 256) {
                int k = i >> 5, q = i & 31;
                float4 v = *(const float4*)(W1 + (size_t)(ch * 64 + k) * 128 + q * 4);
                uint4 h4, l4v;
                split_tf32(v.x, h4.x, l4v.x);
                split_tf32(v.y, h4.y, l4v.y);
                split_tf32(v.z, h4.z, l4v.z);
                split_tf32(v.w, h4.w, l4v.w);
                *(uint4*)(Bh + k * PB + q * 4) = h4;
                *(uint4*)(Bl + k * PB + q * 4) = l4v;
            }
            __syncthreads();
            mma_chunk<4, PB>(Ah, Al, Bh, Bl, m0w, n0w, gq, l4, acc, true);
        }
        #pragma unroll
        for (int mi = 0; mi < 4; ++mi) {
            int r0 = m0w + mi * 16 + gq;
            #pragma unroll
            for (int ni = 0; ni < 4; ++ni) {
                int c = n0w + ni * 8 + 2 * l4;
                float bb0 = __ldg(b1 + c), bb1 = __ldg(b1 + c + 1);
                float v00 = acc[mi][ni][0] + bb0, v01 = acc[mi][ni][1] + bb1;
                float v10 = acc[mi][ni][2] + bb0, v11 = acc[mi][ni][3] + bb1;
                v00 = v00 / (1.1f * (1.f + __expf(-v00 * spv)));
                v01 = v01 / (1.1f * (1.f + __expf(-v01 * spv)));
                v10 = v10 / (1.1f * (1.f + __expf(-v10 * spv)));
                v11 = v11 / (1.1f * (1.f + __expf(-v11 * spv)));
                *(float2*)(Gf + r0 * PG + c)       = make_float2(v00, v01);
                *(float2*)(Gf + (r0 + 8) * PG + c) = make_float2(v10, v11);
            }
        }
    }
    __syncthreads();

    // ================= Stage 3: MLP2 (K=128 from Gf, BN=64) + residual =================
    {
        const int n0w = wn * 16;
        float acc[4][2][4];
        #pragma unroll
        for (int mi = 0; mi < 4; ++mi)
            #pragma unroll
            for (int ni = 0; ni < 2; ++ni)
                #pragma unroll
                for (int q = 0; q < 4; ++q) acc[mi][ni][q] = 0.f;

        for (int ch = 0; ch < 2; ++ch) {
            if (ch) __syncthreads();
            for (int i = tid; i < 128 * 16; i += 256) {
                int m = i >> 4, q = i & 15;
                float4 v = *(const float4*)(Gf + m * PG + ch * 64 + q * 4);
                uint4 h4, l4v;
                split_tf32(v.x, h4.x, l4v.x);
                split_tf32(v.y, h4.y, l4v.y);
                split_tf32(v.z, h4.z, l4v.z);
                split_tf32(v.w, h4.w, l4v.w);
                *(uint4*)(Ah + m * PA + q * 4) = h4;
                *(uint4*)(Al + m * PA + q * 4) = l4v;
            }
            for (int i = tid; i < 64 * 16; i += 256) {
                int k = i >> 4, q = i & 15;
                float4 v = *(const float4*)(W2 + (size_t)(ch * 64 + k) * 64 + q * 4);
                uint4 h4, l4v;
                split_tf32(v.x, h4.x, l4v.x);
                split_tf32(v.y, h4.y, l4v.y);
                split_tf32(v.z, h4.z, l4v.z);
                split_tf32(v.w, h4.w, l4v.w);
                *(uint4*)(Bh + k * PB3 + q * 4) = h4;
                *(uint4*)(Bl + k * PB3 + q * 4) = l4v;
            }
            __syncthreads();
            mma_chunk<2, PB3>(Ah, Al, Bh, Bl, m0w, n0w, gq, l4, acc, true);
        }
        // epilogue: h += Fx ; also refresh fp16 shadow
        #pragma unroll
        for (int mi = 0; mi < 4; ++mi) {
            int r0 = mblk + m0w + mi * 16 + gq;
            #pragma unroll
            for (int ni = 0; ni < 2; ++ni) {
                int c = n0w + ni * 8 + 2 * l4;
                float bb0 = __ldg(b2 + c), bb1 = __ldg(b2 + c + 1);
                float2 cur0 = *(float2*)(g_h + (size_t)r0 * 64 + c);
                float2 cur1 = *(float2*)(g_h + (size_t)(r0 + 8) * 64 + c);
                cur0.x += acc[mi][ni][0] + bb0;
                cur0.y += acc[mi][ni][1] + bb1;
                cur1.x += acc[mi][ni][2] + bb0;
                cur1.y += acc[mi][ni][3] + bb1;
                *(float2*)(g_h + (size_t)r0 * 64 + c)       = cur0;
                *(float2*)(g_h + (size_t)(r0 + 8) * 64 + c) = cur1;
                *(__half2*)(g_hh + (size_t)r0 * 64 + c)       = __floats2half2_rn(cur0.x, cur0.y);
                *(__half2*)(g_hh + (size_t)(r0 + 8) * 64 + c) = __floats2half2_rn(cur1.x, cur1.y);
            }
        }
    }
}

// -------- host launcher --------
extern "C" void kernel_launch(void* const* d_in, const int* in_sizes, int n_in,
                              void* d_out, int out_size) {
    const float* x      = (const float*)d_in[0];
    const int*   ei     = (const int*)  d_in[1];
    const float* ew     = (const float*)d_in[2];
    const float* cheb_w = (const float*)d_in[3];
    const float* cheb_b = (const float*)d_in[4];
    const float* beta   = (const float*)d_in[5];
    const float* w1     = (const float*)d_in[6];
    const float* b1     = (const float*)d_in[7];
    const float* w2     = (const float*)d_in[8];
    const float* b2     = (const float*)d_in[9];
    float* out = (float*)d_out;
    const int* src = ei;
    const int* dst = ei + Ee;

    // smem: 2*128*68 + 2*64*132 + 128*132 words = 51200 * 4 = 204800 B
    constexpr int SMEM_FUSED = (2 * 128 * PA + 2 * 64 * PB + 128 * PG) * 4;
    cudaFuncSetAttribute((const void*)fused_block,
                         cudaFuncAttributeMaxDynamicSharedMemorySize, SMEM_FUSED);

    const int EB = (Ee + 255) / 256;     // 2500
    const int NBk = (Nn + 255) / 256;    // 79

    zero_deg_cnt<<<NBk, 256>>>();
    deg_kernel<<<EB, 256>>>(src, ew);
    dinv_kernel<<<NBk, 256>>>();
    w_count_kernel<<<EB, 256>>>(src, dst, ew);
    scan_kernel<<<1, 1024>>>();
    zero_cnt<<<NBk, 256>>>();
    fill_kernel<<<EB, 256>>>(src, dst);

    t_in_kernel<<<Nn, 256>>>((const float4*)x);

    for (int b = 0; b < NBlk; ++b) {
        spmm16_kernel<0><<<Nn, 128>>>();             // t1h = Lhat h   (fp16 gather)
        spmm16_kernel<1><<<Nn, 128>>>();             // t2h = Lhat t1
        prep_wc<<<32, 256>>>(cheb_w, b);
        fused_block<<<2500, 256, SMEM_FUSED>>>(
            w1 + (size_t)b * 128 * 128, b1 + b * 128,
            w2 + (size_t)b * 128 * 64,  b2 + b * 64,
            cheb_b + b * 128, beta + b);
    }

    t_out_kernel<<<Nn, 256>>>((float4*)out);
}

// round 4
// speedup vs baseline: 1.8163x; 1.2385x over previous
#include <cuda_runtime.h>
#include <cuda_fp16.h>
#include <cuda_bf16.h>
#include <stdint.h>
#include <math.h>

// Problem constants
constexpr int Bc   = 16;
constexpr int Nn   = 20000;
constexpr int Cc   = 64;
constexpr int Ee   = 640000;
constexpr int NBlk = 3;
constexpr int ROWS = Nn * Bc;          // 320000
constexpr int RowF = Bc * Cc;          // 1024 elems per node row ([N][B][C])
constexpr int RowF4 = RowF / 4;

// -------- device scratch --------
__device__ float  g_h  [ROWS * Cc];
__device__ __half g_hh [ROWS * Cc];
__device__ __half g_t1h[ROWS * Cc];
__device__ __half g_t2h[ROWS * Cc];
__device__ float g_deg [Nn];
__device__ float g_dinv[Nn];
__device__ float g_w   [Ee];
__device__ int   g_off [Nn + 1];
__device__ int   g_cnt [Nn];
__device__ int   g_csrc[Ee];
__device__ float g_csw [Ee];
__device__ float g_wc  [3 * 192 * 128];

// -------- small setup kernels --------
__global__ void zero_deg_cnt() {
    int i = blockIdx.x * blockDim.x + threadIdx.x;
    if (i < Nn) { g_deg[i] = 0.f; g_cnt[i] = 0; }
}
__global__ void deg_kernel(const int* __restrict__ src, const float* __restrict__ ew) {
    int e = blockIdx.x * blockDim.x + threadIdx.x;
    if (e < Ee) atomicAdd(&g_deg[src[e]], ew[e]);
}
__global__ void dinv_kernel() {
    int i = blockIdx.x * blockDim.x + threadIdx.x;
    if (i < Nn) {
        float d = g_deg[i];
        g_dinv[i] = (d > 0.f) ? rsqrtf(fmaxf(d, 1e-12f)) : 0.f;
    }
}
__global__ void w_count_kernel(const int* __restrict__ src, const int* __restrict__ dst,
                               const float* __restrict__ ew) {
    int e = blockIdx.x * blockDim.x + threadIdx.x;
    if (e < Ee) {
        int s = src[e], d = dst[e];
        g_w[e] = -g_dinv[s] * ew[e] * g_dinv[d];
        atomicAdd(&g_cnt[d], 1);
    }
}
__global__ void scan_kernel() {
    __shared__ int warp_sums[32];
    __shared__ int s_carry;
    int t = threadIdx.x;
    if (t == 0) s_carry = 0;
    __syncthreads();
    for (int base = 0; base < Nn; base += 1024) {
        int v = (base + t < Nn) ? g_cnt[base + t] : 0;
        if (base + t < Nn) g_cnt[base + t] = 0;
        int x = v;
        #pragma unroll
        for (int d = 1; d < 32; d <<= 1) {
            int y = __shfl_up_sync(0xFFFFFFFFu, x, d);
            if ((t & 31) >= d) x += y;
        }
        if ((t & 31) == 31) warp_sums[t >> 5] = x;
        __syncthreads();
        if (t < 32) {
            int y = warp_sums[t];
            #pragma unroll
            for (int d = 1; d < 32; d <<= 1) {
                int z = __shfl_up_sync(0xFFFFFFFFu, y, d);
                if (t >= d) y += z;
            }
            warp_sums[t] = y;
        }
        __syncthreads();
        int excl = s_carry + (x - v) + ((t >= 32) ? warp_sums[(t >> 5) - 1] : 0);
        if (base + t < Nn) g_off[base + t] = excl;
        __syncthreads();
        if (t == 0) s_carry += warp_sums[31];
        __syncthreads();
    }
    if (t == 0) g_off[Nn] = s_carry;
}
__global__ void fill_kernel(const int* __restrict__ src, const int* __restrict__ dst) {
    int e = blockIdx.x * blockDim.x + threadIdx.x;
    if (e < Ee) {
        int d = dst[e];
        int pos = g_off[d] + atomicAdd(&g_cnt[d], 1);
        g_csrc[pos] = src[e];
        g_csw[pos]  = g_w[e];
    }
}

// -------- transposes --------
__global__ void t_in_kernel(const float4* __restrict__ x4) {
    int idx = blockIdx.x * 256 + threadIdx.x;
    int b = idx / (Nn * 16);
    int r = idx % (Nn * 16);
    int n = r >> 4, c4 = r & 15;
    float4 v = x4[idx];
    int o4 = n * RowF4 + b * 16 + c4;
    ((float4*)g_h)[o4] = v;
    ((__half2*)g_hh)[o4 * 2]     = __floats2half2_rn(v.x, v.y);
    ((__half2*)g_hh)[o4 * 2 + 1] = __floats2half2_rn(v.z, v.w);
}
__global__ void t_out_kernel(float4* __restrict__ o4) {
    int idx = blockIdx.x * 256 + threadIdx.x;
    int b = idx / (Nn * 16);
    int r = idx % (Nn * 16);
    int n = r >> 4, c4 = r & 15;
    o4[idx] = ((const float4*)g_h)[n * RowF4 + b * 16 + c4];
}

// -------- SpMM fp16, dual edge streams --------
template <int PHASE>
__global__ void __launch_bounds__(256) spmm16_kernel() {
    const __half* __restrict__ in = (PHASE == 0) ? g_hh : g_t1h;
    __half* __restrict__ out      = (PHASE == 0) ? g_t1h : g_t2h;
    __shared__ float red[8 * 128];
    int n = blockIdx.x;
    int stream = threadIdx.x >> 7;
    int t = threadIdx.x & 127;
    int e0 = g_off[n], e1 = g_off[n + 1];
    float acc[8];
    #pragma unroll
    for (int q = 0; q < 8; ++q) acc[q] = 0.f;
    #pragma unroll 4
    for (int e = e0 + stream; e < e1; e += 2) {
        int   s  = __ldg(&g_csrc[e]);
        float wv = __ldg(&g_csw[e]);
        uint4 raw = __ldg((const uint4*)(in + (size_t)s * RowF) + t);
        const __half2* hp = (const __half2*)&raw;
        #pragma unroll
        for (int p = 0; p < 4; ++p) {
            float2 f = __half22float2(hp[p]);
            acc[2 * p]     = fmaf(wv, f.x, acc[2 * p]);
            acc[2 * p + 1] = fmaf(wv, f.y, acc[2 * p + 1]);
        }
    }
    if (stream) {
        #pragma unroll
        for (int q = 0; q < 8; ++q) red[q * 128 + t] = acc[q];
    }
    __syncthreads();
    if (!stream) {
        uint4 res;
        __half2* rp = (__half2*)&res;
        #pragma unroll
        for (int p = 0; p < 4; ++p)
            rp[p] = __floats2half2_rn(acc[2 * p] + red[(2 * p) * 128 + t],
                                      acc[2 * p + 1] + red[(2 * p + 1) * 128 + t]);
        ((uint4*)(out + (size_t)n * RowF))[t] = res;
    }
}

// -------- prepack cheb weights for all blocks --------
__global__ void prep_wc_all(const float* __restrict__ cw) {
    int idx = blockIdx.x * 256 + threadIdx.x;
    if (idx < 3 * 8192) {
        int b = idx >> 13, r = idx & 8191;
        const float* base = cw + (size_t)b * 24576;
        float w0  = base[r];
        float w1v = base[8192 + r];
        float w2v = base[16384 + r];
        float* o = g_wc + (size_t)b * 24576;
        o[r]         = w0 - w2v;
        o[8192 + r]  = w1v;
        o[16384 + r] = 2.f * w2v;
    }
}

// -------- bf16 split helpers --------
__device__ __forceinline__ uint32_t pack2(__nv_bfloat16 a, __nv_bfloat16 b) {
    __nv_bfloat162 t(a, b);
    return *(uint32_t*)&t;
}
__device__ __forceinline__ void split2(float v0, float v1, uint32_t& hi, uint32_t& lo) {
    __nv_bfloat16 h0 = __float2bfloat16_rn(v0), h1 = __float2bfloat16_rn(v1);
    float r0 = v0 - __bfloat162float(h0);
    float r1 = v1 - __bfloat162float(h1);
    hi = pack2(h0, h1);
    lo = pack2(__float2bfloat16_rn(r0), __float2bfloat16_rn(r1));
}
__device__ __forceinline__ void mma16(float* c, const uint32_t* a, const uint32_t* b) {
    asm volatile(
        "mma.sync.aligned.m16n8k16.row.col.f32.bf16.bf16.f32 "
        "{%0,%1,%2,%3}, {%4,%5,%6,%7}, {%8,%9}, {%0,%1,%2,%3};\n"
        : "+f"(c[0]), "+f"(c[1]), "+f"(c[2]), "+f"(c[3])
        : "r"(a[0]), "r"(a[1]), "r"(a[2]), "r"(a[3]), "r"(b[0]), "r"(b[1]));
}

constexpr int PAw = 68;     // [128][68] u32 k-pair buffers (banks: 68%32=4 -> clean)
constexpr int PBw = 136;    // [32][136] u32 B buffer (136%32=8 -> clean)

template <int NI>
__device__ __forceinline__ void mma_chunk16(
    const uint32_t* __restrict__ Ahp, const uint32_t* __restrict__ Alp,
    const uint32_t* __restrict__ Bhp, const uint32_t* __restrict__ Blp,
    int colBase, int m0w, int n0w, int gq, int l4, float acc[4][NI][4])
{
    #pragma unroll
    for (int s = 0; s < 4; ++s) {
        const int kb = colBase + 8 * s + l4;
        uint32_t ah[4][4], al[4][4];
        #pragma unroll
        for (int mi = 0; mi < 4; ++mi) {
            int r = m0w + mi * 16 + gq;
            ah[mi][0] = Ahp[r * PAw + kb];
            ah[mi][1] = Ahp[(r + 8) * PAw + kb];
            ah[mi][2] = Ahp[r * PAw + kb + 4];
            ah[mi][3] = Ahp[(r + 8) * PAw + kb + 4];
            al[mi][0] = Alp[r * PAw + kb];
            al[mi][1] = Alp[(r + 8) * PAw + kb];
            al[mi][2] = Alp[r * PAw + kb + 4];
            al[mi][3] = Alp[(r + 8) * PAw + kb + 4];
        }
        const int kr = (8 * s + l4) * PBw;
        uint32_t bh[NI][2], bl[NI][2];
        #pragma unroll
        for (int ni = 0; ni < NI; ++ni) {
            int n = n0w + ni * 8 + gq;
            bh[ni][0] = Bhp[kr + n];
            bh[ni][1] = Bhp[kr + 4 * PBw + n];
            bl[ni][0] = Blp[kr + n];
            bl[ni][1] = Blp[kr + 4 * PBw + n];
        }
        #pragma unroll
        for (int mi = 0; mi < 4; ++mi)
            #pragma unroll
            for (int ni = 0; ni < NI; ++ni) {
                mma16(acc[mi][ni], ah[mi], bh[ni]);
                mma16(acc[mi][ni], ah[mi], bl[ni]);
                mma16(acc[mi][ni], al[mi], bh[ni]);
            }
    }
}

__device__ __forceinline__ void fill_B(const float* __restrict__ W, int BN,
                                       uint32_t* __restrict__ Bhp, uint32_t* __restrict__ Blp,
                                       int tid)
{
    int quads = BN / 4;
    for (int i = tid; i < 32 * quads; i += 256) {
        int k2 = i / quads, n4 = i % quads;
        float4 fa = *(const float4*)(W + (size_t)(2 * k2) * BN + n4 * 4);
        float4 fb = *(const float4*)(W + (size_t)(2 * k2 + 1) * BN + n4 * 4);
        uint4 h4, l4v;
        split2(fa.x, fb.x, h4.x, l4v.x);
        split2(fa.y, fb.y, h4.y, l4v.y);
        split2(fa.z, fb.z, h4.z, l4v.z);
        split2(fa.w, fb.w, h4.w, l4v.w);
        *(uint4*)(Bhp + k2 * PBw + n4 * 4) = h4;
        *(uint4*)(Blp + k2 * PBw + n4 * 4) = l4v;
    }
}

// -------- fused per-block kernel --------
__global__ void __launch_bounds__(256)
fused_block(int blk,
            const float* __restrict__ W1, const float* __restrict__ b1,
            const float* __restrict__ W2, const float* __restrict__ b2,
            const float* __restrict__ cb, const float* __restrict__ betaPtr)
{
    extern __shared__ uint32_t sm[];
    uint32_t* Ahp = sm;                       // stage1 A / stage2-out (G2)
    uint32_t* Alp = Ahp + 128 * PAw;
    uint32_t* G1h = Alp + 128 * PAw;          // stage1-out / stage2 A
    uint32_t* G1l = G1h + 128 * PAw;
    uint32_t* Bhp = G1l + 128 * PAw;
    uint32_t* Blp = Bhp + 32 * PBw;

    const float* wcb = g_wc + (size_t)blk * 24576;

    const int tid  = threadIdx.x;
    const int warp = tid >> 5, lane = tid & 31;
    const int gq   = lane >> 2, l4 = lane & 3;
    const int wm   = warp >> 2, wn = warp & 3;
    const int m0w  = wm * 64;
    const int mblk = blockIdx.x * 128;
    const float spv = log1pf(__expf(*betaPtr));

    // ===== Stage 1: cheb (3 chunks) =====
    {
        const int n0w = wn * 32;
        float acc[4][4][4];
        #pragma unroll
        for (int mi = 0; mi < 4; ++mi)
            #pragma unroll
            for (int ni = 0; ni < 4; ++ni)
                #pragma unroll
                for (int q = 0; q < 4; ++q) acc[mi][ni][q] = 0.f;

        for (int ch = 0; ch < 3; ++ch) {
            if (ch) __syncthreads();
            if (ch == 0) {
                for (int i = tid; i < 128 * 16; i += 256) {
                    int m = i >> 4, q = i & 15;
                    float4 v = *(const float4*)(g_h + (size_t)(mblk + m) * 64 + q * 4);
                    uint32_t h0, l0, h1, l1;
                    split2(v.x, v.y, h0, l0);
                    split2(v.z, v.w, h1, l1);
                    *(uint2*)(Ahp + m * PAw + 2 * q) = make_uint2(h0, h1);
                    *(uint2*)(Alp + m * PAw + 2 * q) = make_uint2(l0, l1);
                }
            } else {
                const __half* srcH = (ch == 1) ? g_t1h : g_t2h;
                for (int i = tid; i < 128 * 16; i += 256) {
                    int m = i >> 4, q = i & 15;
                    uint2 raw = *(const uint2*)(srcH + (size_t)(mblk + m) * 64 + q * 4);
                    const __half2* hp = (const __half2*)&raw;
                    float2 f0 = __half22float2(hp[0]);
                    float2 f1 = __half22float2(hp[1]);
                    uint32_t h0, l0, h1, l1;
                    split2(f0.x, f0.y, h0, l0);
                    split2(f1.x, f1.y, h1, l1);
                    *(uint2*)(Ahp + m * PAw + 2 * q) = make_uint2(h0, h1);
                    *(uint2*)(Alp + m * PAw + 2 * q) = make_uint2(l0, l1);
                }
            }
            fill_B(wcb + (size_t)(ch * 64) * 128, 128, Bhp, Blp, tid);
            __syncthreads();
            mma_chunk16<4>(Ahp, Alp, Bhp, Blp, 0, m0w, n0w, gq, l4, acc);
        }
        #pragma unroll
        for (int mi = 0; mi < 4; ++mi) {
            int r0 = m0w + mi * 16 + gq;
            #pragma unroll
            for (int ni = 0; ni < 4; ++ni) {
                int c = n0w + ni * 8 + 2 * l4;
                float bb0 = __ldg(cb + c), bb1 = __ldg(cb + c + 1);
                float v00 = acc[mi][ni][0] + bb0, v01 = acc[mi][ni][1] + bb1;
                float v10 = acc[mi][ni][2] + bb0, v11 = acc[mi][ni][3] + bb1;
                v00 = v00 / (1.1f * (1.f + __expf(-v00 * spv)));
                v01 = v01 / (1.1f * (1.f + __expf(-v01 * spv)));
                v10 = v10 / (1.1f * (1.f + __expf(-v10 * spv)));
                v11 = v11 / (1.1f * (1.f + __expf(-v11 * spv)));
                int w = c >> 1;
                uint32_t h, l;
                split2(v00, v01, h, l);
                G1h[r0 * PAw + w] = h;  G1l[r0 * PAw + w] = l;
                split2(v10, v11, h, l);
                G1h[(r0 + 8) * PAw + w] = h;  G1l[(r0 + 8) * PAw + w] = l;
            }
        }
    }
    __syncthreads();

    // ===== Stage 2: MLP1 (A = G1) =====
    {
        const int n0w = wn * 32;
        float acc[4][4][4];
        #pragma unroll
        for (int mi = 0; mi < 4; ++mi)
            #pragma unroll
            for (int ni = 0; ni < 4; ++ni)
                #pragma unroll
                for (int q = 0; q < 4; ++q) acc[mi][ni][q] = 0.f;

        for (int ch = 0; ch < 2; ++ch) {
            fill_B(W1 + (size_t)(ch * 64) * 128, 128, Bhp, Blp, tid);
            __syncthreads();
            mma_chunk16<4>(G1h, G1l, Bhp, Blp, ch * 32, m0w, n0w, gq, l4, acc);
            __syncthreads();
        }
        #pragma unroll
        for (int mi = 0; mi < 4; ++mi) {
            int r0 = m0w + mi * 16 + gq;
            #pragma unroll
            for (int ni = 0; ni < 4; ++ni) {
                int c = n0w + ni * 8 + 2 * l4;
                float bb0 = __ldg(b1 + c), bb1 = __ldg(b1 + c + 1);
                float v00 = acc[mi][ni][0] + bb0, v01 = acc[mi][ni][1] + bb1;
                float v10 = acc[mi][ni][2] + bb0, v11 = acc[mi][ni][3] + bb1;
                v00 = v00 / (1.1f * (1.f + __expf(-v00 * spv)));
                v01 = v01 / (1.1f * (1.f + __expf(-v01 * spv)));
                v10 = v10 / (1.1f * (1.f + __expf(-v10 * spv)));
                v11 = v11 / (1.1f * (1.f + __expf(-v11 * spv)));
                int w = c >> 1;
                uint32_t h, l;
                split2(v00, v01, h, l);
                Ahp[r0 * PAw + w] = h;  Alp[r0 * PAw + w] = l;
                split2(v10, v11, h, l);
                Ahp[(r0 + 8) * PAw + w] = h;  Alp[(r0 + 8) * PAw + w] = l;
            }
        }
    }
    __syncthreads();

    // ===== Stage 3: MLP2 (A = G2, BN=64) + residual =====
    {
        const int n0w = wn * 16;
        float acc[4][2][4];
        #pragma unroll
        for (int mi = 0; mi < 4; ++mi)
            #pragma unroll
            for (int ni = 0; ni < 2; ++ni)
                #pragma unroll
                for (int q = 0; q < 4; ++q) acc[mi][ni][q] = 0.f;

        for (int ch = 0; ch < 2; ++ch) {
            fill_B(W2 + (size_t)(ch * 64) * 64, 64, Bhp, Blp, tid);
            __syncthreads();
            mma_chunk16<2>(Ahp, Alp, Bhp, Blp, ch * 32, m0w, n0w, gq, l4, acc);
            __syncthreads();
        }
        #pragma unroll
        for (int mi = 0; mi < 4; ++mi) {
            int r0 = mblk + m0w + mi * 16 + gq;
            #pragma unroll
            for (int ni = 0; ni < 2; ++ni) {
                int c = n0w + ni * 8 + 2 * l4;
                float bb0 = __ldg(b2 + c), bb1 = __ldg(b2 + c + 1);
                float2 cur0 = *(float2*)(g_h + (size_t)r0 * 64 + c);
                float2 cur1 = *(float2*)(g_h + (size_t)(r0 + 8) * 64 + c);
                cur0.x += acc[mi][ni][0] + bb0;
                cur0.y += acc[mi][ni][1] + bb1;
                cur1.x += acc[mi][ni][2] + bb0;
                cur1.y += acc[mi][ni][3] + bb1;
                *(float2*)(g_h + (size_t)r0 * 64 + c)       = cur0;
                *(float2*)(g_h + (size_t)(r0 + 8) * 64 + c) = cur1;
                *(__half2*)(g_hh + (size_t)r0 * 64 + c)       = __floats2half2_rn(cur0.x, cur0.y);
                *(__half2*)(g_hh + (size_t)(r0 + 8) * 64 + c) = __floats2half2_rn(cur1.x, cur1.y);
            }
        }
    }
}

// -------- host launcher --------
extern "C" void kernel_launch(void* const* d_in, const int* in_sizes, int n_in,
                              void* d_out, int out_size) {
    const float* x      = (const float*)d_in[0];
    const int*   ei     = (const int*)  d_in[1];
    const float* ew     = (const float*)d_in[2];
    const float* cheb_w = (const float*)d_in[3];
    const float* cheb_b = (const float*)d_in[4];
    const float* beta   = (const float*)d_in[5];
    const float* w1     = (const float*)d_in[6];
    const float* b1     = (const float*)d_in[7];
    const float* w2     = (const float*)d_in[8];
    const float* b2     = (const float*)d_in[9];
    float* out = (float*)d_out;
    const int* src = ei;
    const int* dst = ei + Ee;

    constexpr int SMEM_FUSED = (4 * 128 * PAw + 2 * 32 * PBw) * 4;  // 174080 B
    cudaFuncSetAttribute((const void*)fused_block,
                         cudaFuncAttributeMaxDynamicSharedMemorySize, SMEM_FUSED);

    const int EB = (Ee + 255) / 256;
    const int NBk = (Nn + 255) / 256;

    zero_deg_cnt<<<NBk, 256>>>();
    deg_kernel<<<EB, 256>>>(src, ew);
    dinv_kernel<<<NBk, 256>>>();
    w_count_kernel<<<EB, 256>>>(src, dst, ew);
    scan_kernel<<<1, 1024>>>();
    fill_kernel<<<EB, 256>>>(src, dst);
    prep_wc_all<<<96, 256>>>(cheb_w);

    t_in_kernel<<<Nn, 256>>>((const float4*)x);

    for (int b = 0; b < NBlk; ++b) {
        spmm16_kernel<0><<<Nn, 256>>>();
        spmm16_kernel<1><<<Nn, 256>>>();
        fused_block<<<2500, 256, SMEM_FUSED>>>(
            b,
            w1 + (size_t)b * 128 * 128, b1 + b * 128,
            w2 + (size_t)b * 128 * 64,  b2 + b * 64,
            cheb_b + b * 128, beta + b);
    }

    t_out_kernel<<<Nn, 256>>>((float4*)out);
}

// round 5
// speedup vs baseline: 2.2953x; 1.2637x over previous
#include <cuda_runtime.h>
#include <cuda_fp16.h>
#include <cuda_bf16.h>
#include <stdint.h>
#include <math.h>

// Problem constants
constexpr int Bc   = 16;
constexpr int Nn   = 20000;
constexpr int Cc   = 64;
constexpr int Ee   = 640000;
constexpr int NBlk = 3;
constexpr int ROWS = Nn * Bc;          // 320000
constexpr int RowF = Bc * Cc;          // 1024 elems per node row ([N][B][C])
constexpr int RowF4 = RowF / 4;

// -------- device scratch --------
__device__ float  g_h  [ROWS * Cc];
__device__ __half g_hh [ROWS * Cc];
__device__ __half g_t1h[ROWS * Cc];
__device__ __half g_t2h[ROWS * Cc];
__device__ float g_deg [Nn];
__device__ float g_dinv[Nn];
__device__ float g_w   [Ee];
__device__ int   g_off [Nn + 1];
__device__ int   g_cnt [Nn];
__device__ int   g_csrc[Ee];
__device__ float g_csw [Ee];
__device__ float g_wc  [3 * 192 * 128];

// -------- small setup kernels --------
__global__ void zero_deg_cnt() {
    int i = blockIdx.x * blockDim.x + threadIdx.x;
    if (i < Nn) { g_deg[i] = 0.f; g_cnt[i] = 0; }
}
__global__ void deg_kernel(const int* __restrict__ src, const float* __restrict__ ew) {
    int e = blockIdx.x * blockDim.x + threadIdx.x;
    if (e < Ee) atomicAdd(&g_deg[src[e]], ew[e]);
}
__global__ void dinv_kernel() {
    int i = blockIdx.x * blockDim.x + threadIdx.x;
    if (i < Nn) {
        float d = g_deg[i];
        g_dinv[i] = (d > 0.f) ? rsqrtf(fmaxf(d, 1e-12f)) : 0.f;
    }
}
__global__ void w_count_kernel(const int* __restrict__ src, const int* __restrict__ dst,
                               const float* __restrict__ ew) {
    int e = blockIdx.x * blockDim.x + threadIdx.x;
    if (e < Ee) {
        int s = src[e], d = dst[e];
        g_w[e] = -g_dinv[s] * ew[e] * g_dinv[d];
        atomicAdd(&g_cnt[d], 1);
    }
}
__global__ void scan_kernel() {
    __shared__ int warp_sums[32];
    __shared__ int s_carry;
    int t = threadIdx.x;
    if (t == 0) s_carry = 0;
    __syncthreads();
    for (int base = 0; base < Nn; base += 1024) {
        int v = (base + t < Nn) ? g_cnt[base + t] : 0;
        if (base + t < Nn) g_cnt[base + t] = 0;
        int x = v;
        #pragma unroll
        for (int d = 1; d < 32; d <<= 1) {
            int y = __shfl_up_sync(0xFFFFFFFFu, x, d);
            if ((t & 31) >= d) x += y;
        }
        if ((t & 31) == 31) warp_sums[t >> 5] = x;
        __syncthreads();
        if (t < 32) {
            int y = warp_sums[t];
            #pragma unroll
            for (int d = 1; d < 32; d <<= 1) {
                int z = __shfl_up_sync(0xFFFFFFFFu, y, d);
                if (t >= d) y += z;
            }
            warp_sums[t] = y;
        }
        __syncthreads();
        int excl = s_carry + (x - v) + ((t >= 32) ? warp_sums[(t >> 5) - 1] : 0);
        if (base + t < Nn) g_off[base + t] = excl;
        __syncthreads();
        if (t == 0) s_carry += warp_sums[31];
        __syncthreads();
    }
    if (t == 0) g_off[Nn] = s_carry;
}
__global__ void fill_kernel(const int* __restrict__ src, const int* __restrict__ dst) {
    int e = blockIdx.x * blockDim.x + threadIdx.x;
    if (e < Ee) {
        int d = dst[e];
        int pos = g_off[d] + atomicAdd(&g_cnt[d], 1);
        g_csrc[pos] = src[e];
        g_csw[pos]  = g_w[e];
    }
}

// -------- transposes --------
__global__ void t_in_kernel(const float4* __restrict__ x4) {
    int idx = blockIdx.x * 256 + threadIdx.x;
    int b = idx / (Nn * 16);
    int r = idx % (Nn * 16);
    int n = r >> 4, c4 = r & 15;
    float4 v = x4[idx];
    int o4 = n * RowF4 + b * 16 + c4;
    ((float4*)g_h)[o4] = v;
    ((__half2*)g_hh)[o4 * 2]     = __floats2half2_rn(v.x, v.y);
    ((__half2*)g_hh)[o4 * 2 + 1] = __floats2half2_rn(v.z, v.w);
}
__global__ void t_out_kernel(float4* __restrict__ o4) {
    int idx = blockIdx.x * 256 + threadIdx.x;
    int b = idx / (Nn * 16);
    int r = idx % (Nn * 16);
    int n = r >> 4, c4 = r & 15;
    o4[idx] = ((const float4*)g_h)[n * RowF4 + b * 16 + c4];
}

// -------- SpMM fp16, dual edge streams --------
template <int PHASE>
__global__ void __launch_bounds__(256) spmm16_kernel() {
    const __half* __restrict__ in = (PHASE == 0) ? g_hh : g_t1h;
    __half* __restrict__ out      = (PHASE == 0) ? g_t1h : g_t2h;
    __shared__ float red[8 * 128];
    int n = blockIdx.x;
    int stream = threadIdx.x >> 7;
    int t = threadIdx.x & 127;
    int e0 = g_off[n], e1 = g_off[n + 1];
    float acc[8];
    #pragma unroll
    for (int q = 0; q < 8; ++q) acc[q] = 0.f;
    #pragma unroll 4
    for (int e = e0 + stream; e < e1; e += 2) {
        int   s  = __ldg(&g_csrc[e]);
        float wv = __ldg(&g_csw[e]);
        uint4 raw = __ldg((const uint4*)(in + (size_t)s * RowF) + t);
        const __half2* hp = (const __half2*)&raw;
        #pragma unroll
        for (int p = 0; p < 4; ++p) {
            float2 f = __half22float2(hp[p]);
            acc[2 * p]     = fmaf(wv, f.x, acc[2 * p]);
            acc[2 * p + 1] = fmaf(wv, f.y, acc[2 * p + 1]);
        }
    }
    if (stream) {
        #pragma unroll
        for (int q = 0; q < 8; ++q) red[q * 128 + t] = acc[q];
    }
    __syncthreads();
    if (!stream) {
        uint4 res;
        __half2* rp = (__half2*)&res;
        #pragma unroll
        for (int p = 0; p < 4; ++p)
            rp[p] = __floats2half2_rn(acc[2 * p] + red[(2 * p) * 128 + t],
                                      acc[2 * p + 1] + red[(2 * p + 1) * 128 + t]);
        ((uint4*)(out + (size_t)n * RowF))[t] = res;
    }
}

// -------- prepack cheb weights --------
__global__ void prep_wc_all(const float* __restrict__ cw) {
    int idx = blockIdx.x * 256 + threadIdx.x;
    if (idx < 3 * 8192) {
        int b = idx >> 13, r = idx & 8191;
        const float* base = cw + (size_t)b * 24576;
        float w0  = base[r];
        float w1v = base[8192 + r];
        float w2v = base[16384 + r];
        float* o = g_wc + (size_t)b * 24576;
        o[r]         = w0 - w2v;
        o[8192 + r]  = w1v;
        o[16384 + r] = 2.f * w2v;
    }
}

// -------- bf16 split helpers --------
__device__ __forceinline__ uint32_t pack2(__nv_bfloat16 a, __nv_bfloat16 b) {
    __nv_bfloat162 t(a, b);
    return *(uint32_t*)&t;
}
__device__ __forceinline__ void split2(float v0, float v1, uint32_t& hi, uint32_t& lo) {
    __nv_bfloat16 h0 = __float2bfloat16_rn(v0), h1 = __float2bfloat16_rn(v1);
    float r0 = v0 - __bfloat162float(h0);
    float r1 = v1 - __bfloat162float(h1);
    hi = pack2(h0, h1);
    lo = pack2(__float2bfloat16_rn(r0), __float2bfloat16_rn(r1));
}
__device__ __forceinline__ void mma16(float* c, const uint32_t* a, const uint32_t* b) {
    asm volatile(
        "mma.sync.aligned.m16n8k16.row.col.f32.bf16.bf16.f32 "
        "{%0,%1,%2,%3}, {%4,%5,%6,%7}, {%8,%9}, {%0,%1,%2,%3};\n"
        : "+f"(c[0]), "+f"(c[1]), "+f"(c[2]), "+f"(c[3])
        : "r"(a[0]), "r"(a[1]), "r"(a[2]), "r"(a[3]), "r"(b[0]), "r"(b[1]));
}

constexpr int PAw = 68;     // [128][68] u32 k-pair A buffer
constexpr int PBw = 136;    // [32][136] u32 B buffer

template <int NI>
__device__ __forceinline__ void mma_chunk16(
    const uint32_t* __restrict__ Ahp, const uint32_t* __restrict__ Alp,
    const uint32_t* __restrict__ Bhp, const uint32_t* __restrict__ Blp,
    int colBase, int m0w, int n0w, int gq, int l4, float acc[4][NI][4])
{
    #pragma unroll
    for (int s = 0; s < 4; ++s) {
        const int kb = colBase + 8 * s + l4;
        uint32_t ah[4][4], al[4][4];
        #pragma unroll
        for (int mi = 0; mi < 4; ++mi) {
            int r = m0w + mi * 16 + gq;
            ah[mi][0] = Ahp[r * PAw + kb];
            ah[mi][1] = Ahp[(r + 8) * PAw + kb];
            ah[mi][2] = Ahp[r * PAw + kb + 4];
            ah[mi][3] = Ahp[(r + 8) * PAw + kb + 4];
            al[mi][0] = Alp[r * PAw + kb];
            al[mi][1] = Alp[(r + 8) * PAw + kb];
            al[mi][2] = Alp[r * PAw + kb + 4];
            al[mi][3] = Alp[(r + 8) * PAw + kb + 4];
        }
        const int kr = (8 * s + l4) * PBw;
        uint32_t bh[NI][2], bl[NI][2];
        #pragma unroll
        for (int ni = 0; ni < NI; ++ni) {
            int n = n0w + ni * 8 + gq;
            bh[ni][0] = Bhp[kr + n];
            bh[ni][1] = Bhp[kr + 4 * PBw + n];
            bl[ni][0] = Blp[kr + n];
            bl[ni][1] = Blp[kr + 4 * PBw + n];
        }
        #pragma unroll
        for (int mi = 0; mi < 4; ++mi)
            #pragma unroll
            for (int ni = 0; ni < NI; ++ni) {
                mma16(acc[mi][ni], ah[mi], bh[ni]);
                mma16(acc[mi][ni], ah[mi], bl[ni]);
                mma16(acc[mi][ni], al[mi], bh[ni]);
            }
    }
}

__device__ __forceinline__ void fill_B(const float* __restrict__ W, int BN,
                                       uint32_t* __restrict__ Bhp, uint32_t* __restrict__ Blp,
                                       int tid)
{
    int quads = BN / 4;
    for (int i = tid; i < 32 * quads; i += 256) {
        int k2 = i / quads, n4 = i % quads;
        float4 fa = *(const float4*)(W + (size_t)(2 * k2) * BN + n4 * 4);
        float4 fb = *(const float4*)(W + (size_t)(2 * k2 + 1) * BN + n4 * 4);
        uint4 h4, l4v;
        split2(fa.x, fb.x, h4.x, l4v.x);
        split2(fa.y, fb.y, h4.y, l4v.y);
        split2(fa.z, fb.z, h4.z, l4v.z);
        split2(fa.w, fb.w, h4.w, l4v.w);
        *(uint4*)(Bhp + k2 * PBw + n4 * 4) = h4;
        *(uint4*)(Blp + k2 * PBw + n4 * 4) = l4v;
    }
}

// fill A chunk (K=64 -> words 0..31) from an fp16 source; fp16->bf16 hi/lo is exact
__device__ __forceinline__ void fill_A16(const __half* __restrict__ srcH, int mblk,
                                         uint32_t* __restrict__ Ahp, uint32_t* __restrict__ Alp,
                                         int tid)
{
    for (int i = tid; i < 128 * 16; i += 256) {
        int m = i >> 4, q = i & 15;
        uint2 raw = *(const uint2*)(srcH + (size_t)(mblk + m) * 64 + q * 4);
        const __half2* hp = (const __half2*)&raw;
        float2 f0 = __half22float2(hp[0]);
        float2 f1 = __half22float2(hp[1]);
        uint32_t h0, l0, h1, l1;
        split2(f0.x, f0.y, h0, l0);
        split2(f1.x, f1.y, h1, l1);
        *(uint2*)(Ahp + m * PAw + 2 * q) = make_uint2(h0, h1);
        *(uint2*)(Alp + m * PAw + 2 * q) = make_uint2(l0, l1);
    }
}

// -------- fused per-block kernel (2 CTAs/SM) --------
__global__ void __launch_bounds__(256, 2)
fused_block(int blk,
            const float* __restrict__ W1, const float* __restrict__ b1,
            const float* __restrict__ W2, const float* __restrict__ b2,
            const float* __restrict__ cb, const float* __restrict__ betaPtr)
{
    extern __shared__ uint32_t sm[];
    uint32_t* Ahp = sm;                       // [128][68] (reused across all stages)
    uint32_t* Alp = Ahp + 128 * PAw;
    uint32_t* Bhp = Alp + 128 * PAw;          // [32][136]
    uint32_t* Blp = Bhp + 32 * PBw;

    const float* wcb = g_wc + (size_t)blk * 24576;

    const int tid  = threadIdx.x;
    const int warp = tid >> 5, lane = tid & 31;
    const int gq   = lane >> 2, l4 = lane & 3;
    const int wm   = warp >> 2, wn = warp & 3;   // 2 x 4 warp grid
    const int m0w  = wm * 64;
    const int mblk = blockIdx.x * 128;
    const float spv = log1pf(__expf(*betaPtr));

    const int n0w4 = wn * 32;                // BN=128 stages
    const int n0w2 = wn * 16;                // BN=64 stage

    float acc[4][4][4];

    // ===== Stage 1: cheb (3 chunks of K=64, sources g_hh/g_t1h/g_t2h) =====
    #pragma unroll
    for (int mi = 0; mi < 4; ++mi)
        #pragma unroll
        for (int ni = 0; ni < 4; ++ni)
            #pragma unroll
            for (int q = 0; q < 4; ++q) acc[mi][ni][q] = 0.f;

    #pragma unroll 1
    for (int ch = 0; ch < 3; ++ch) {
        if (ch) __syncthreads();             // previous mma done before refill
        const __half* srcH = (ch == 0) ? g_hh : (ch == 1) ? g_t1h : g_t2h;
        fill_A16(srcH, mblk, Ahp, Alp, tid);
        fill_B(wcb + (size_t)(ch * 64) * 128, 128, Bhp, Blp, tid);
        __syncthreads();
        mma_chunk16<4>(Ahp, Alp, Bhp, Blp, 0, m0w, n0w4, gq, l4, acc);
    }
    __syncthreads();
    // epilogue 1: bias+swish -> A buffer (packed, words 0..63); also fill B for MLP1 ch0
    #pragma unroll
    for (int mi = 0; mi < 4; ++mi) {
        int r0 = m0w + mi * 16 + gq;
        #pragma unroll
        for (int ni = 0; ni < 4; ++ni) {
            int c = n0w4 + ni * 8 + 2 * l4;
            float bb0 = __ldg(cb + c), bb1 = __ldg(cb + c + 1);
            float v00 = acc[mi][ni][0] + bb0, v01 = acc[mi][ni][1] + bb1;
            float v10 = acc[mi][ni][2] + bb0, v11 = acc[mi][ni][3] + bb1;
            v00 = v00 / (1.1f * (1.f + __expf(-v00 * spv)));
            v01 = v01 / (1.1f * (1.f + __expf(-v01 * spv)));
            v10 = v10 / (1.1f * (1.f + __expf(-v10 * spv)));
            v11 = v11 / (1.1f * (1.f + __expf(-v11 * spv)));
            int w = c >> 1;
            uint32_t h, l;
            split2(v00, v01, h, l);
            Ahp[r0 * PAw + w] = h;  Alp[r0 * PAw + w] = l;
            split2(v10, v11, h, l);
            Ahp[(r0 + 8) * PAw + w] = h;  Alp[(r0 + 8) * PAw + w] = l;
        }
    }
    fill_B(W1, 128, Bhp, Blp, tid);
    __syncthreads();

    // ===== Stage 2: MLP1 (A in buffer, K=128) =====
    #pragma unroll
    for (int mi = 0; mi < 4; ++mi)
        #pragma unroll
        for (int ni = 0; ni < 4; ++ni)
            #pragma unroll
            for (int q = 0; q < 4; ++q) acc[mi][ni][q] = 0.f;

    mma_chunk16<4>(Ahp, Alp, Bhp, Blp, 0, m0w, n0w4, gq, l4, acc);
    __syncthreads();
    fill_B(W1 + (size_t)64 * 128, 128, Bhp, Blp, tid);
    __syncthreads();
    mma_chunk16<4>(Ahp, Alp, Bhp, Blp, 32, m0w, n0w4, gq, l4, acc);
    __syncthreads();
    // epilogue 2 -> A buffer; fill B for MLP2 ch0
    #pragma unroll
    for (int mi = 0; mi < 4; ++mi) {
        int r0 = m0w + mi * 16 + gq;
        #pragma unroll
        for (int ni = 0; ni < 4; ++ni) {
            int c = n0w4 + ni * 8 + 2 * l4;
            float bb0 = __ldg(b1 + c), bb1 = __ldg(b1 + c + 1);
            float v00 = acc[mi][ni][0] + bb0, v01 = acc[mi][ni][1] + bb1;
            float v10 = acc[mi][ni][2] + bb0, v11 = acc[mi][ni][3] + bb1;
            v00 = v00 / (1.1f * (1.f + __expf(-v00 * spv)));
            v01 = v01 / (1.1f * (1.f + __expf(-v01 * spv)));
            v10 = v10 / (1.1f * (1.f + __expf(-v10 * spv)));
            v11 = v11 / (1.1f * (1.f + __expf(-v11 * spv)));
            int w = c >> 1;
            uint32_t h, l;
            split2(v00, v01, h, l);
            Ahp[r0 * PAw + w] = h;  Alp[r0 * PAw + w] = l;
            split2(v10, v11, h, l);
            Ahp[(r0 + 8) * PAw + w] = h;  Alp[(r0 + 8) * PAw + w] = l;
        }
    }
    fill_B(W2, 64, Bhp, Blp, tid);
    __syncthreads();

    // ===== Stage 3: MLP2 (BN=64) + residual =====
    float acc3[4][2][4];
    #pragma unroll
    for (int mi = 0; mi < 4; ++mi)
        #pragma unroll
        for (int ni = 0; ni < 2; ++ni)
            #pragma unroll
            for (int q = 0; q < 4; ++q) acc3[mi][ni][q] = 0.f;

    mma_chunk16<2>(Ahp, Alp, Bhp, Blp, 0, m0w, n0w2, gq, l4, acc3);
    __syncthreads();
    fill_B(W2 + (size_t)64 * 64, 64, Bhp, Blp, tid);
    __syncthreads();
    mma_chunk16<2>(Ahp, Alp, Bhp, Blp, 32, m0w, n0w2, gq, l4, acc3);

    // final epilogue: h += Fx (gmem only, no smem dependency -> no sync needed)
    #pragma unroll
    for (int mi = 0; mi < 4; ++mi) {
        int r0 = mblk + m0w + mi * 16 + gq;
        #pragma unroll
        for (int ni = 0; ni < 2; ++ni) {
            int c = n0w2 + ni * 8 + 2 * l4;
            float bb0 = __ldg(b2 + c), bb1 = __ldg(b2 + c + 1);
            float2 cur0 = *(float2*)(g_h + (size_t)r0 * 64 + c);
            float2 cur1 = *(float2*)(g_h + (size_t)(r0 + 8) * 64 + c);
            cur0.x += acc3[mi][ni][0] + bb0;
            cur0.y += acc3[mi][ni][1] + bb1;
            cur1.x += acc3[mi][ni][2] + bb0;
            cur1.y += acc3[mi][ni][3] + bb1;
            *(float2*)(g_h + (size_t)r0 * 64 + c)       = cur0;
            *(float2*)(g_h + (size_t)(r0 + 8) * 64 + c) = cur1;
            *(__half2*)(g_hh + (size_t)r0 * 64 + c)       = __floats2half2_rn(cur0.x, cur0.y);
            *(__half2*)(g_hh + (size_t)(r0 + 8) * 64 + c) = __floats2half2_rn(cur1.x, cur1.y);
        }
    }
}

// -------- host launcher --------
extern "C" void kernel_launch(void* const* d_in, const int* in_sizes, int n_in,
                              void* d_out, int out_size) {
    const float* x      = (const float*)d_in[0];
    const int*   ei     = (const int*)  d_in[1];
    const float* ew     = (const float*)d_in[2];
    const float* cheb_w = (const float*)d_in[3];
    const float* cheb_b = (const float*)d_in[4];
    const float* beta   = (const float*)d_in[5];
    const float* w1     = (const float*)d_in[6];
    const float* b1     = (const float*)d_in[7];
    const float* w2     = (const float*)d_in[8];
    const float* b2     = (const float*)d_in[9];
    float* out = (float*)d_out;
    const int* src = ei;
    const int* dst = ei + Ee;

    // smem: (2*128*68 + 2*32*136) * 4 = 104448 B  -> 2 CTAs/SM
    constexpr int SMEM_FUSED = (2 * 128 * PAw + 2 * 32 * PBw) * 4;
    cudaFuncSetAttribute((const void*)fused_block,
                         cudaFuncAttributeMaxDynamicSharedMemorySize, SMEM_FUSED);

    const int EB = (Ee + 255) / 256;
    const int NBk = (Nn + 255) / 256;

    zero_deg_cnt<<<NBk, 256>>>();
    deg_kernel<<<EB, 256>>>(src, ew);
    dinv_kernel<<<NBk, 256>>>();
    w_count_kernel<<<EB, 256>>>(src, dst, ew);
    scan_kernel<<<1, 1024>>>();
    fill_kernel<<<EB, 256>>>(src, dst);
    prep_wc_all<<<96, 256>>>(cheb_w);

    t_in_kernel<<<Nn, 256>>>((const float4*)x);

    for (int b = 0; b < NBlk; ++b) {
        spmm16_kernel<0><<<Nn, 256>>>();
        spmm16_kernel<1><<<Nn, 256>>>();
        fused_block<<<2500, 256, SMEM_FUSED>>>(
            b,
            w1 + (size_t)b * 128 * 128, b1 + b * 128,
            w2 + (size_t)b * 128 * 64,  b2 + b * 64,
            cheb_b + b * 128, beta + b);
    }

    t_out_kernel<<<Nn, 256>>>((float4*)out);
}

// round 7
// speedup vs baseline: 2.5274x; 1.1011x over previous
#include <cuda_runtime.h>
#include <cuda_fp16.h>
#include <stdint.h>
#include <math.h>

// Problem constants
constexpr int Bc   = 16;
constexpr int Nn   = 20000;
constexpr int Cc   = 64;
constexpr int Ee   = 640000;
constexpr int NBlk = 3;
constexpr int ROWS = Nn * Bc;          // 320000
constexpr int RowF = Bc * Cc;          // 1024 halfs per node row ([N][B][C])
constexpr int RowF4 = RowF / 4;

// -------- device scratch --------
__device__ __align__(16) float  g_h  [ROWS * Cc];
__device__ __align__(16) __half g_hh [ROWS * Cc];
__device__ __align__(16) __half g_t1h[ROWS * Cc];
__device__ __align__(16) __half g_t2h[ROWS * Cc];
__device__ float g_deg [Nn];
__device__ float g_dinv[Nn];
__device__ float g_w   [Ee];
__device__ int   g_off [Nn + 1];
__device__ int   g_cnt [Nn];
__device__ int   g_csrc[Ee];
__device__ float g_csw [Ee];
__device__ float g_wc  [3 * 192 * 128];
// Pre-packed fp16 hi/lo B operands in mma-fragment word layout:
// word(k2, n) = {W[2*k2][n], W[2*k2+1][n]} packed halfs, rows k2=0..31 per 64-K chunk
__device__ __align__(16) uint32_t g_Bc[2][3][3][32 * 128];  // [hi/lo][block][chunk]
__device__ __align__(16) uint32_t g_B1[2][3][2][32 * 128];
__device__ __align__(16) uint32_t g_B2[2][3][2][32 * 64];

// -------- small setup kernels --------
__global__ void zero_deg_cnt() {
    int i = blockIdx.x * blockDim.x + threadIdx.x;
    if (i < Nn) { g_deg[i] = 0.f; g_cnt[i] = 0; }
}
__global__ void deg_kernel(const int* __restrict__ src, const float* __restrict__ ew) {
    int e = blockIdx.x * blockDim.x + threadIdx.x;
    if (e < Ee) atomicAdd(&g_deg[src[e]], ew[e]);
}
__global__ void dinv_kernel() {
    int i = blockIdx.x * blockDim.x + threadIdx.x;
    if (i < Nn) {
        float d = g_deg[i];
        g_dinv[i] = (d > 0.f) ? rsqrtf(fmaxf(d, 1e-12f)) : 0.f;
    }
}
__global__ void w_count_kernel(const int* __restrict__ src, const int* __restrict__ dst,
                               const float* __restrict__ ew) {
    int e = blockIdx.x * blockDim.x + threadIdx.x;
    if (e < Ee) {
        int s = src[e], d = dst[e];
        g_w[e] = -g_dinv[s] * ew[e] * g_dinv[d];
        atomicAdd(&g_cnt[d], 1);
    }
}
__global__ void scan_kernel() {
    __shared__ int warp_sums[32];
    __shared__ int s_carry;
    int t = threadIdx.x;
    if (t == 0) s_carry = 0;
    __syncthreads();
    for (int base = 0; base < Nn; base += 1024) {
        int v = (base + t < Nn) ? g_cnt[base + t] : 0;
        if (base + t < Nn) g_cnt[base + t] = 0;
        int x = v;
        #pragma unroll
        for (int d = 1; d < 32; d <<= 1) {
            int y = __shfl_up_sync(0xFFFFFFFFu, x, d);
            if ((t & 31) >= d) x += y;
        }
        if ((t & 31) == 31) warp_sums[t >> 5] = x;
        __syncthreads();
        if (t < 32) {
            int y = warp_sums[t];
            #pragma unroll
            for (int d = 1; d < 32; d <<= 1) {
                int z = __shfl_up_sync(0xFFFFFFFFu, y, d);
                if (t >= d) y += z;
            }
            warp_sums[t] = y;
        }
        __syncthreads();
        int excl = s_carry + (x - v) + ((t >= 32) ? warp_sums[(t >> 5) - 1] : 0);
        if (base + t < Nn) g_off[base + t] = excl;
        __syncthreads();
        if (t == 0) s_carry += warp_sums[31];
        __syncthreads();
    }
    if (t == 0) g_off[Nn] = s_carry;
}
__global__ void fill_kernel(const int* __restrict__ src, const int* __restrict__ dst) {
    int e = blockIdx.x * blockDim.x + threadIdx.x;
    if (e < Ee) {
        int d = dst[e];
        int pos = g_off[d] + atomicAdd(&g_cnt[d], 1);
        g_csrc[pos] = src[e];
        g_csw[pos]  = g_w[e];
    }
}

// -------- transposes --------
__global__ void t_in_kernel(const float4* __restrict__ x4) {
    int idx = blockIdx.x * 256 + threadIdx.x;
    int b = idx / (Nn * 16);
    int r = idx % (Nn * 16);
    int n = r >> 4, c4 = r & 15;
    float4 v = x4[idx];
    int o4 = n * RowF4 + b * 16 + c4;
    ((float4*)g_h)[o4] = v;
    ((__half2*)g_hh)[o4 * 2]     = __floats2half2_rn(v.x, v.y);
    ((__half2*)g_hh)[o4 * 2 + 1] = __floats2half2_rn(v.z, v.w);
}
__global__ void t_out_kernel(float4* __restrict__ o4) {
    int idx = blockIdx.x * 256 + threadIdx.x;
    int b = idx / (Nn * 16);
    int r = idx % (Nn * 16);
    int n = r >> 4, c4 = r & 15;
    o4[idx] = ((const float4*)g_h)[n * RowF4 + b * 16 + c4];
}

// -------- SpMM fp16, dual edge streams --------
template <int PHASE>
__global__ void __launch_bounds__(256) spmm16_kernel() {
    const __half* __restrict__ in = (PHASE == 0) ? g_hh : g_t1h;
    __half* __restrict__ out      = (PHASE == 0) ? g_t1h : g_t2h;
    __shared__ float red[8 * 128];
    int n = blockIdx.x;
    int stream = threadIdx.x >> 7;
    int t = threadIdx.x & 127;
    int e0 = g_off[n], e1 = g_off[n + 1];
    float acc[8];
    #pragma unroll
    for (int q = 0; q < 8; ++q) acc[q] = 0.f;
    #pragma unroll 4
    for (int e = e0 + stream; e < e1; e += 2) {
        int   s  = __ldg(&g_csrc[e]);
        float wv = __ldg(&g_csw[e]);
        uint4 raw = __ldg((const uint4*)(in + (size_t)s * RowF) + t);
        const __half2* hp = (const __half2*)&raw;
        #pragma unroll
        for (int p = 0; p < 4; ++p) {
            float2 f = __half22float2(hp[p]);
            acc[2 * p]     = fmaf(wv, f.x, acc[2 * p]);
            acc[2 * p + 1] = fmaf(wv, f.y, acc[2 * p + 1]);
        }
    }
    if (stream) {
        #pragma unroll
        for (int q = 0; q < 8; ++q) red[q * 128 + t] = acc[q];
    }
    __syncthreads();
    if (!stream) {
        uint4 res;
        __half2* rp = (__half2*)&res;
        #pragma unroll
        for (int p = 0; p < 4; ++p)
            rp[p] = __floats2half2_rn(acc[2 * p] + red[(2 * p) * 128 + t],
                                      acc[2 * p + 1] + red[(2 * p + 1) * 128 + t]);
        ((uint4*)(out + (size_t)n * RowF))[t] = res;
    }
}

// -------- weight prep --------
__global__ void prep_wc_all(const float* __restrict__ cw) {
    int idx = blockIdx.x * 256 + threadIdx.x;
    if (idx < 3 * 8192) {
        int b = idx >> 13, r = idx & 8191;
        const float* base = cw + (size_t)b * 24576;
        float w0  = base[r];
        float w1v = base[8192 + r];
        float w2v = base[16384 + r];
        float* o = g_wc + (size_t)b * 24576;
        o[r]         = w0 - w2v;
        o[8192 + r]  = w1v;
        o[16384 + r] = 2.f * w2v;
    }
}
__device__ __forceinline__ void split_h(float v, __half& h, __half& l) {
    h = __float2half_rn(v);
    l = __float2half_rn(v - __half2float(h));
}
__device__ __forceinline__ uint32_t pack_h2(__half a, __half b) {
    __half2 t = __halves2half2(a, b);
    return *(uint32_t*)&t;
}
// pack fragment words from a row-major fp32 [K][N] chunk
__device__ __forceinline__ void pack_word(const float* W, int BN, int k2, int n,
                                          uint32_t& hi, uint32_t& lo) {
    float v0 = W[(size_t)(2 * k2) * BN + n];
    float v1 = W[(size_t)(2 * k2 + 1) * BN + n];
    __half h0, l0, h1, l1;
    split_h(v0, h0, l0); split_h(v1, h1, l1);
    hi = pack_h2(h0, h1);
    lo = pack_h2(l0, l1);
}
__global__ void prep_Bc() {
    int idx = blockIdx.x * 256 + threadIdx.x;        // 3*3*4096 = 36864
    if (idx < 36864) {
        int b = idx / 12288, r2 = idx % 12288;
        int c = r2 >> 12, r = r2 & 4095;
        int k2 = r >> 7, n = r & 127;
        uint32_t hi, lo;
        pack_word(g_wc + (size_t)b * 24576 + (size_t)c * 64 * 128, 128, k2, n, hi, lo);
        g_Bc[0][b][c][r] = hi;
        g_Bc[1][b][c][r] = lo;
    }
}
__global__ void prep_B1(const float* __restrict__ w1) {
    int idx = blockIdx.x * 256 + threadIdx.x;        // 3*2*4096 = 24576
    if (idx < 24576) {
        int b = idx / 8192, r2 = idx % 8192;
        int c = r2 >> 12, r = r2 & 4095;
        int k2 = r >> 7, n = r & 127;
        uint32_t hi, lo;
        pack_word(w1 + (size_t)b * 16384 + (size_t)c * 64 * 128, 128, k2, n, hi, lo);
        g_B1[0][b][c][r] = hi;
        g_B1[1][b][c][r] = lo;
    }
}
__global__ void prep_B2(const float* __restrict__ w2) {
    int idx = blockIdx.x * 256 + threadIdx.x;        // 3*2*2048 = 12288
    if (idx < 12288) {
        int b = idx / 4096, r2 = idx % 4096;
        int c = r2 >> 11, r = r2 & 2047;
        int k2 = r >> 6, n = r & 63;
        uint32_t hi, lo;
        pack_word(w2 + (size_t)b * 8192 + (size_t)c * 64 * 64, 64, k2, n, hi, lo);
        g_B2[0][b][c][r] = hi;
        g_B2[1][b][c][r] = lo;
    }
}

// ================== fused GEMM chain (mma.sync f16 + ldmatrix) ==================
__device__ __forceinline__ uint32_t s2u(const void* p) {
    uint32_t a;
    asm("{ .reg .u64 t; cvta.to.shared.u64 t, %1; cvt.u32.u64 %0, t; }" : "=r"(a) : "l"(p));
    return a;
}
__device__ __forceinline__ void mma_f16(float* c, const uint32_t* a, const uint32_t* b) {
    asm volatile(
        "mma.sync.aligned.m16n8k16.row.col.f32.f16.f16.f32 "
        "{%0,%1,%2,%3}, {%4,%5,%6,%7}, {%8,%9}, {%0,%1,%2,%3};\n"
        : "+f"(c[0]), "+f"(c[1]), "+f"(c[2]), "+f"(c[3])
        : "r"(a[0]), "r"(a[1]), "r"(a[2]), "r"(a[3]), "r"(b[0]), "r"(b[1]));
}
#define LDSM4(r, a) \
    asm volatile("ldmatrix.sync.aligned.m8n8.x4.shared.b16 {%0,%1,%2,%3}, [%4];" \
        : "=r"((r)[0]), "=r"((r)[1]), "=r"((r)[2]), "=r"((r)[3]) : "r"(a))

constexpr int PAH = 136;    // A tile pitch in halfs (272B rows, 16B-aligned, LDSM conflict-free)
constexpr int PBw = 136;    // B tile pitch in u32 words
// SMEM byte offsets
constexpr uint32_t AH_OFF = 0;
constexpr uint32_t AL_OFF = 34816;       // 128*136*2
constexpr uint32_t BH_OFF = 69632;
constexpr uint32_t BL_OFF = 87040;       // +32*136*4
constexpr int SMEM_FUSED = 104448;

// mma over one K=64 chunk (4 k16-steps). A via ldmatrix from fp16 tiles.
template <int NI, bool ALO>
__device__ __forceinline__ void mma_chunk(
    uint32_t aHiLane, uint32_t aLoLane, int colOffHalfs,
    const uint32_t* __restrict__ Bhp, const uint32_t* __restrict__ Blp,
    int n0w, int gq, int l4, float acc[4][NI][4])
{
    #pragma unroll
    for (int s = 0; s < 4; ++s) {
        const int kr = (8 * s + l4) * PBw;
        uint32_t bh[NI][2], bl[NI][2];
        #pragma unroll
        for (int ni = 0; ni < NI; ++ni) {
            int n = n0w + ni * 8 + gq;
            bh[ni][0] = Bhp[kr + n];
            bh[ni][1] = Bhp[kr + 4 * PBw + n];
            bl[ni][0] = Blp[kr + n];
            bl[ni][1] = Blp[kr + 4 * PBw + n];
        }
        const uint32_t aoff = (uint32_t)(colOffHalfs + s * 16) * 2;
        #pragma unroll
        for (int mi = 0; mi < 4; ++mi) {
            uint32_t ah[4];
            LDSM4(ah, aHiLane + aoff + mi * (16 * PAH * 2));
            #pragma unroll
            for (int ni = 0; ni < NI; ++ni) {
                mma_f16(acc[mi][ni], ah, bh[ni]);
                mma_f16(acc[mi][ni], ah, bl[ni]);
            }
            if (ALO) {
                uint32_t al[4];
                LDSM4(al, aLoLane + aoff + mi * (16 * PAH * 2));
                #pragma unroll
                for (int ni = 0; ni < NI; ++ni)
                    mma_f16(acc[mi][ni], al, bh[ni]);
            }
        }
    }
}

// copy a pre-packed B chunk (32 rows x WN words) into smem B tiles
template <int WN>
__device__ __forceinline__ void copy_B(const uint32_t* __restrict__ srcH,
                                       const uint32_t* __restrict__ srcL,
                                       char* smem, int tid)
{
    constexpr int Q = WN / 4;            // uint4 per row
    for (int i = tid; i < 32 * Q; i += 256) {
        int r = i / Q, q = i % Q;
        *(uint4*)(smem + BH_OFF + (r * PBw + 4 * q) * 4) = *(const uint4*)(srcH + r * WN + 4 * q);
        *(uint4*)(smem + BL_OFF + (r * PBw + 4 * q) * 4) = *(const uint4*)(srcL + r * WN + 4 * q);
    }
}

// -------- fused per-block kernel --------
__global__ void __launch_bounds__(256, 2)
fused_block(int blk,
            const float* __restrict__ b1, const float* __restrict__ b2,
            const float* __restrict__ cb, const float* __restrict__ betaPtr)
{
    extern __shared__ __align__(16) char smem[];
    const uint32_t sb = s2u(smem);
    const uint32_t* Bhp = (const uint32_t*)(smem + BH_OFF);
    const uint32_t* Blp = (const uint32_t*)(smem + BL_OFF);

    const int tid  = threadIdx.x;
    const int warp = tid >> 5, lane = tid & 31;
    const int gq   = lane >> 2, l4 = lane & 3;
    const int wm   = warp >> 2, wn = warp & 3;    // 2 x 4 warp grid
    const int m0w  = wm * 64;
    const int mblk = blockIdx.x * 128;
    const float spv = log1pf(__expf(*betaPtr));
    const int n0w4 = wn * 32;
    const int n0w2 = wn * 16;

    // ldmatrix per-lane base addresses (row = m0w + lane&15, col halfs = (lane>>4)*8)
    const uint32_t aLaneOff = (uint32_t)((m0w + (lane & 15)) * PAH + (lane >> 4) * 8) * 2;
    const uint32_t aHiLane = sb + AH_OFF + aLaneOff;
    const uint32_t aLoLane = sb + AL_OFF + aLaneOff;

    float acc[4][4][4];

    // ===== Stage 1: cheb, 3 chunks; A = fp16 source (exact, 2-term) =====
    #pragma unroll
    for (int mi = 0; mi < 4; ++mi)
        #pragma unroll
        for (int ni = 0; ni < 4; ++ni)
            #pragma unroll
            for (int q = 0; q < 4; ++q) acc[mi][ni][q] = 0.f;

    #pragma unroll 1
    for (int ch = 0; ch < 3; ++ch) {
        if (ch) __syncthreads();
        const __half* srcA = (ch == 0) ? g_hh : (ch == 1) ? g_t1h : g_t2h;
        // pure fp16 copy into A-hi tile cols 0..63 (8 uint4 per row)
        for (int i = tid; i < 128 * 8; i += 256) {
            int m = i >> 3, q = i & 7;
            uint4 v = *(const uint4*)(srcA + (size_t)(mblk + m) * 64 + q * 8);
            *(uint4*)(smem + AH_OFF + (m * PAH + q * 8) * 2) = v;
        }
        copy_B<128>(&g_Bc[0][blk][ch][0], &g_Bc[1][blk][ch][0], smem, tid);
        __syncthreads();
        mma_chunk<4, false>(aHiLane, aLoLane, 0, Bhp, Blp, n0w4, gq, l4, acc);
    }
    __syncthreads();

    // ===== Epilogue 1: bias+swish -> fp16 hi/lo A tiles (cols 0..127); fill B for MLP1 ch0 =====
    #pragma unroll
    for (int mi = 0; mi < 4; ++mi) {
        int r0 = m0w + mi * 16 + gq;
        #pragma unroll
        for (int ni = 0; ni < 4; ++ni) {
            int c = n0w4 + ni * 8 + 2 * l4;
            float bb0 = __ldg(cb + c), bb1 = __ldg(cb + c + 1);
            float v00 = acc[mi][ni][0] + bb0, v01 = acc[mi][ni][1] + bb1;
            float v10 = acc[mi][ni][2] + bb0, v11 = acc[mi][ni][3] + bb1;
            v00 = v00 / (1.1f * (1.f + __expf(-v00 * spv)));
            v01 = v01 / (1.1f * (1.f + __expf(-v01 * spv)));
            v10 = v10 / (1.1f * (1.f + __expf(-v10 * spv)));
            v11 = v11 / (1.1f * (1.f + __expf(-v11 * spv)));
            __half h0, l0, h1, l1;
            split_h(v00, h0, l0); split_h(v01, h1, l1);
            *(__half2*)(smem + AH_OFF + (r0 * PAH + c) * 2) = __halves2half2(h0, h1);
            *(__half2*)(smem + AL_OFF + (r0 * PAH + c) * 2) = __halves2half2(l0, l1);
            split_h(v10, h0, l0); split_h(v11, h1, l1);
            *(__half2*)(smem + AH_OFF + ((r0 + 8) * PAH + c) * 2) = __halves2half2(h0, h1);
            *(__half2*)(smem + AL_OFF + ((r0 + 8) * PAH + c) * 2) = __halves2half2(l0, l1);
        }
    }
    copy_B<128>(&g_B1[0][blk][0][0], &g_B1[1][blk][0][0], smem, tid);
    __syncthreads();

    // ===== Stage 2: MLP1 (A cols 0..127, 3-term) =====
    #pragma unroll
    for (int mi = 0; mi < 4; ++mi)
        #pragma unroll
        for (int ni = 0; ni < 4; ++ni)
            #pragma unroll
            for (int q = 0; q < 4; ++q) acc[mi][ni][q] = 0.f;

    mma_chunk<4, true>(aHiLane, aLoLane, 0, Bhp, Blp, n0w4, gq, l4, acc);
    __syncthreads();
    copy_B<128>(&g_B1[0][blk][1][0], &g_B1[1][blk][1][0], smem, tid);
    __syncthreads();
    mma_chunk<4, true>(aHiLane, aLoLane, 64, Bhp, Blp, n0w4, gq, l4, acc);
    __syncthreads();

    // ===== Epilogue 2 -> A tiles; fill B for MLP2 ch0 =====
    #pragma unroll
    for (int mi = 0; mi < 4; ++mi) {
        int r0 = m0w + mi * 16 + gq;
        #pragma unroll
        for (int ni = 0; ni < 4; ++ni) {
            int c = n0w4 + ni * 8 + 2 * l4;
            float bb0 = __ldg(b1 + c), bb1 = __ldg(b1 + c + 1);
            float v00 = acc[mi][ni][0] + bb0, v01 = acc[mi][ni][1] + bb1;
            float v10 = acc[mi][ni][2] + bb0, v11 = acc[mi][ni][3] + bb1;
            v00 = v00 / (1.1f * (1.f + __expf(-v00 * spv)));
            v01 = v01 / (1.1f * (1.f + __expf(-v01 * spv)));
            v10 = v10 / (1.1f * (1.f + __expf(-v10 * spv)));
            v11 = v11 / (1.1f * (1.f + __expf(-v11 * spv)));
            __half h0, l0, h1, l1;
            split_h(v00, h0, l0); split_h(v01, h1, l1);
            *(__half2*)(smem + AH_OFF + (r0 * PAH + c) * 2) = __halves2half2(h0, h1);
            *(__half2*)(smem + AL_OFF + (r0 * PAH + c) * 2) = __halves2half2(l0, l1);
            split_h(v10, h0, l0); split_h(v11, h1, l1);
            *(__half2*)(smem + AH_OFF + ((r0 + 8) * PAH + c) * 2) = __halves2half2(h0, h1);
            *(__half2*)(smem + AL_OFF + ((r0 + 8) * PAH + c) * 2) = __halves2half2(l0, l1);
        }
    }
    copy_B<64>(&g_B2[0][blk][0][0], &g_B2[1][blk][0][0], smem, tid);
    __syncthreads();

    // ===== Stage 3: MLP2 (N=64, 3-term) + residual =====
    float acc3[4][2][4];
    #pragma unroll
    for (int mi = 0; mi < 4; ++mi)
        #pragma unroll
        for (int ni = 0; ni < 2; ++ni)
            #pragma unroll
            for (int q = 0; q < 4; ++q) acc3[mi][ni][q] = 0.f;

    mma_chunk<2, true>(aHiLane, aLoLane, 0, Bhp, Blp, n0w2, gq, l4, acc3);
    __syncthreads();
    copy_B<64>(&g_B2[0][blk][1][0], &g_B2[1][blk][1][0], smem, tid);
    __syncthreads();
    mma_chunk<2, true>(aHiLane, aLoLane, 64, Bhp, Blp, n0w2, gq, l4, acc3);

    // final epilogue: h += Fx (gmem only)
    #pragma unroll
    for (int mi = 0; mi < 4; ++mi) {
        int r0 = mblk + m0w + mi * 16 + gq;
        #pragma unroll
        for (int ni = 0; ni < 2; ++ni) {
            int c = n0w2 + ni * 8 + 2 * l4;
            float bb0 = __ldg(b2 + c), bb1 = __ldg(b2 + c + 1);
            float2 cur0 = *(float2*)(g_h + (size_t)r0 * 64 + c);
            float2 cur1 = *(float2*)(g_h + (size_t)(r0 + 8) * 64 + c);
            cur0.x += acc3[mi][ni][0] + bb0;
            cur0.y += acc3[mi][ni][1] + bb1;
            cur1.x += acc3[mi][ni][2] + bb0;
            cur1.y += acc3[mi][ni][3] + bb1;
            *(float2*)(g_h + (size_t)r0 * 64 + c)       = cur0;
            *(float2*)(g_h + (size_t)(r0 + 8) * 64 + c) = cur1;
            *(__half2*)(g_hh + (size_t)r0 * 64 + c)       = __floats2half2_rn(cur0.x, cur0.y);
            *(__half2*)(g_hh + (size_t)(r0 + 8) * 64 + c) = __floats2half2_rn(cur1.x, cur1.y);
        }
    }
}

// -------- host launcher --------
extern "C" void kernel_launch(void* const* d_in, const int* in_sizes, int n_in,
                              void* d_out, int out_size) {
    const float* x      = (const float*)d_in[0];
    const int*   ei     = (const int*)  d_in[1];
    const float* ew     = (const float*)d_in[2];
    const float* cheb_w = (const float*)d_in[3];
    const float* cheb_b = (const float*)d_in[4];
    const float* beta   = (const float*)d_in[5];
    const float* w1     = (const float*)d_in[6];
    const float* b1     = (const float*)d_in[7];
    const float* w2     = (const float*)d_in[8];
    const float* b2     = (const float*)d_in[9];
    float* out = (float*)d_out;
    const int* src = ei;
    const int* dst = ei + Ee;

    cudaFuncSetAttribute((const void*)fused_block,
                         cudaFuncAttributeMaxDynamicSharedMemorySize, SMEM_FUSED);

    const int EB = (Ee + 255) / 256;
    const int NBk = (Nn + 255) / 256;

    zero_deg_cnt<<<NBk, 256>>>();
    deg_kernel<<<EB, 256>>>(src, ew);
    dinv_kernel<<<NBk, 256>>>();
    w_count_kernel<<<EB, 256>>>(src, dst, ew);
    scan_kernel<<<1, 1024>>>();
    fill_kernel<<<EB, 256>>>(src, dst);
    prep_wc_all<<<96, 256>>>(cheb_w);
    prep_Bc<<<144, 256>>>();
    prep_B1<<<96, 256>>>(w1);
    prep_B2<<<48, 256>>>(w2);

    t_in_kernel<<<Nn, 256>>>((const float4*)x);

    for (int b = 0; b < NBlk; ++b) {
        spmm16_kernel<0><<<Nn, 256>>>();
        spmm16_kernel<1><<<Nn, 256>>>();
        fused_block<<<2500, 256, SMEM_FUSED>>>(
            b, b1 + b * 128, b2 + b * 64, cheb_b + b * 128, beta + b);
    }

    t_out_kernel<<<Nn, 256>>>((float4*)out);
}

// round 8
// speedup vs baseline: 2.5339x; 1.0026x over previous
#include <cuda_runtime.h>
#include <cuda_fp16.h>
#include <stdint.h>
#include <math.h>

// Problem constants
constexpr int Bc   = 16;
constexpr int Nn   = 20000;
constexpr int Cc   = 64;
constexpr int Ee   = 640000;
constexpr int NBlk = 3;
constexpr int ROWS = Nn * Bc;          // 320000
constexpr int RowF = Bc * Cc;          // 1024 halfs per node row ([N][B][C])
constexpr int RowF4 = RowF / 4;

// -------- device scratch --------
__device__ __align__(16) float  g_h  [ROWS * Cc];
__device__ __align__(16) __half g_hh [ROWS * Cc];
__device__ __align__(16) __half g_t1h[ROWS * Cc];
__device__ __align__(16) __half g_t2h[ROWS * Cc];
__device__ float g_deg [Nn];
__device__ float g_dinv[Nn];
__device__ float g_w   [Ee];
__device__ int   g_off [Nn + 1];
__device__ int   g_cnt [Nn];
__device__ int   g_csrc[Ee];
__device__ float g_csw [Ee];
__device__ float g_wc  [3 * 192 * 128];
// Pre-packed fp16 hi/lo B operands, LANE-VECTORIZED fragment layout:
// For N=128: word index = k2*128 + gq*16 + wn*4 + ni, where n = wn*32 + ni*8 + gq
// For N=64 : word index = k2*64  + gq*8  + wn*2 + ni, where n = wn*16 + ni*8 + gq
// Each word packs halfs {W[2*k2][n], W[2*k2+1][n]}.
__device__ __align__(16) uint32_t g_Bc[2][3][3][32 * 128];  // [hi/lo][block][chunk]
__device__ __align__(16) uint32_t g_B1[2][3][2][32 * 128];
__device__ __align__(16) uint32_t g_B2[2][3][2][32 * 64];

// -------- small setup kernels --------
__global__ void zero_deg_cnt() {
    int i = blockIdx.x * blockDim.x + threadIdx.x;
    if (i < Nn) { g_deg[i] = 0.f; g_cnt[i] = 0; }
}
__global__ void deg_kernel(const int* __restrict__ src, const float* __restrict__ ew) {
    int e = blockIdx.x * blockDim.x + threadIdx.x;
    if (e < Ee) atomicAdd(&g_deg[src[e]], ew[e]);
}
__global__ void dinv_kernel() {
    int i = blockIdx.x * blockDim.x + threadIdx.x;
    if (i < Nn) {
        float d = g_deg[i];
        g_dinv[i] = (d > 0.f) ? rsqrtf(fmaxf(d, 1e-12f)) : 0.f;
    }
}
__global__ void w_count_kernel(const int* __restrict__ src, const int* __restrict__ dst,
                               const float* __restrict__ ew) {
    int e = blockIdx.x * blockDim.x + threadIdx.x;
    if (e < Ee) {
        int s = src[e], d = dst[e];
        g_w[e] = -g_dinv[s] * ew[e] * g_dinv[d];
        atomicAdd(&g_cnt[d], 1);
    }
}
__global__ void scan_kernel() {
    __shared__ int warp_sums[32];
    __shared__ int s_carry;
    int t = threadIdx.x;
    if (t == 0) s_carry = 0;
    __syncthreads();
    for (int base = 0; base < Nn; base += 1024) {
        int v = (base + t < Nn) ? g_cnt[base + t] : 0;
        if (base + t < Nn) g_cnt[base + t] = 0;
        int x = v;
        #pragma unroll
        for (int d = 1; d < 32; d <<= 1) {
            int y = __shfl_up_sync(0xFFFFFFFFu, x, d);
            if ((t & 31) >= d) x += y;
        }
        if ((t & 31) == 31) warp_sums[t >> 5] = x;
        __syncthreads();
        if (t < 32) {
            int y = warp_sums[t];
            #pragma unroll
            for (int d = 1; d < 32; d <<= 1) {
                int z = __shfl_up_sync(0xFFFFFFFFu, y, d);
                if (t >= d) y += z;
            }
            warp_sums[t] = y;
        }
        __syncthreads();
        int excl = s_carry + (x - v) + ((t >= 32) ? warp_sums[(t >> 5) - 1] : 0);
        if (base + t < Nn) g_off[base + t] = excl;
        __syncthreads();
        if (t == 0) s_carry += warp_sums[31];
        __syncthreads();
    }
    if (t == 0) g_off[Nn] = s_carry;
}
__global__ void fill_kernel(const int* __restrict__ src, const int* __restrict__ dst) {
    int e = blockIdx.x * blockDim.x + threadIdx.x;
    if (e < Ee) {
        int d = dst[e];
        int pos = g_off[d] + atomicAdd(&g_cnt[d], 1);
        g_csrc[pos] = src[e];
        g_csw[pos]  = g_w[e];
    }
}

// -------- transposes --------
__global__ void t_in_kernel(const float4* __restrict__ x4) {
    int idx = blockIdx.x * 256 + threadIdx.x;
    int b = idx / (Nn * 16);
    int r = idx % (Nn * 16);
    int n = r >> 4, c4 = r & 15;
    float4 v = x4[idx];
    int o4 = n * RowF4 + b * 16 + c4;
    ((float4*)g_h)[o4] = v;
    ((__half2*)g_hh)[o4 * 2]     = __floats2half2_rn(v.x, v.y);
    ((__half2*)g_hh)[o4 * 2 + 1] = __floats2half2_rn(v.z, v.w);
}
__global__ void t_out_kernel(float4* __restrict__ o4) {
    int idx = blockIdx.x * 256 + threadIdx.x;
    int b = idx / (Nn * 16);
    int r = idx % (Nn * 16);
    int n = r >> 4, c4 = r & 15;
    o4[idx] = ((const float4*)g_h)[n * RowF4 + b * 16 + c4];
}

// -------- SpMM fp16, dual edge streams --------
template <int PHASE>
__global__ void __launch_bounds__(256) spmm16_kernel() {
    const __half* __restrict__ in = (PHASE == 0) ? g_hh : g_t1h;
    __half* __restrict__ out      = (PHASE == 0) ? g_t1h : g_t2h;
    __shared__ float red[8 * 128];
    int n = blockIdx.x;
    int stream = threadIdx.x >> 7;
    int t = threadIdx.x & 127;
    int e0 = g_off[n], e1 = g_off[n + 1];
    float acc[8];
    #pragma unroll
    for (int q = 0; q < 8; ++q) acc[q] = 0.f;
    #pragma unroll 4
    for (int e = e0 + stream; e < e1; e += 2) {
        int   s  = __ldg(&g_csrc[e]);
        float wv = __ldg(&g_csw[e]);
        uint4 raw = __ldg((const uint4*)(in + (size_t)s * RowF) + t);
        const __half2* hp = (const __half2*)&raw;
        #pragma unroll
        for (int p = 0; p < 4; ++p) {
            float2 f = __half22float2(hp[p]);
            acc[2 * p]     = fmaf(wv, f.x, acc[2 * p]);
            acc[2 * p + 1] = fmaf(wv, f.y, acc[2 * p + 1]);
        }
    }
    if (stream) {
        #pragma unroll
        for (int q = 0; q < 8; ++q) red[q * 128 + t] = acc[q];
    }
    __syncthreads();
    if (!stream) {
        uint4 res;
        __half2* rp = (__half2*)&res;
        #pragma unroll
        for (int p = 0; p < 4; ++p)
            rp[p] = __floats2half2_rn(acc[2 * p] + red[(2 * p) * 128 + t],
                                      acc[2 * p + 1] + red[(2 * p + 1) * 128 + t]);
        ((uint4*)(out + (size_t)n * RowF))[t] = res;
    }
}

// -------- weight prep --------
__global__ void prep_wc_all(const float* __restrict__ cw) {
    int idx = blockIdx.x * 256 + threadIdx.x;
    if (idx < 3 * 8192) {
        int b = idx >> 13, r = idx & 8191;
        const float* base = cw + (size_t)b * 24576;
        float w0  = base[r];
        float w1v = base[8192 + r];
        float w2v = base[16384 + r];
        float* o = g_wc + (size_t)b * 24576;
        o[r]         = w0 - w2v;
        o[8192 + r]  = w1v;
        o[16384 + r] = 2.f * w2v;
    }
}
__device__ __forceinline__ void split_h(float v, __half& h, __half& l) {
    h = __float2half_rn(v);
    l = __float2half_rn(v - __half2float(h));
}
__device__ __forceinline__ uint32_t pack_h2(__half a, __half b) {
    __half2 t = __halves2half2(a, b);
    return *(uint32_t*)&t;
}
__device__ __forceinline__ void pack_word(const float* W, int BN, int k2, int n,
                                          uint32_t& hi, uint32_t& lo) {
    float v0 = W[(size_t)(2 * k2) * BN + n];
    float v1 = W[(size_t)(2 * k2 + 1) * BN + n];
    __half h0, l0, h1, l1;
    split_h(v0, h0, l0); split_h(v1, h1, l1);
    hi = pack_h2(h0, h1);
    lo = pack_h2(l0, l1);
}
// N=128 lane-vectorized layout: r = k2*128 + gq*16 + wn*4 + ni ; n = wn*32+ni*8+gq
__global__ void prep_Bc() {
    int idx = blockIdx.x * 256 + threadIdx.x;        // 3*3*4096 = 36864
    if (idx < 36864) {
        int b = idx / 12288, r2 = idx % 12288;
        int c = r2 >> 12, r = r2 & 4095;
        int k2 = r >> 7, t = r & 127;
        int gq = t >> 4, rem = t & 15, wn = rem >> 2, ni = rem & 3;
        int n = wn * 32 + ni * 8 + gq;
        uint32_t hi, lo;
        pack_word(g_wc + (size_t)b * 24576 + (size_t)c * 64 * 128, 128, k2, n, hi, lo);
        g_Bc[0][b][c][r] = hi;
        g_Bc[1][b][c][r] = lo;
    }
}
__global__ void prep_B1(const float* __restrict__ w1) {
    int idx = blockIdx.x * 256 + threadIdx.x;        // 3*2*4096 = 24576
    if (idx < 24576) {
        int b = idx / 8192, r2 = idx % 8192;
        int c = r2 >> 12, r = r2 & 4095;
        int k2 = r >> 7, t = r & 127;
        int gq = t >> 4, rem = t & 15, wn = rem >> 2, ni = rem & 3;
        int n = wn * 32 + ni * 8 + gq;
        uint32_t hi, lo;
        pack_word(w1 + (size_t)b * 16384 + (size_t)c * 64 * 128, 128, k2, n, hi, lo);
        g_B1[0][b][c][r] = hi;
        g_B1[1][b][c][r] = lo;
    }
}
// N=64 layout: r = k2*64 + gq*8 + wn*2 + ni ; n = wn*16+ni*8+gq
__global__ void prep_B2(const float* __restrict__ w2) {
    int idx = blockIdx.x * 256 + threadIdx.x;        // 3*2*2048 = 12288
    if (idx < 12288) {
        int b = idx / 4096, r2 = idx % 4096;
        int c = r2 >> 11, r = r2 & 2047;
        int k2 = r >> 6, t = r & 63;
        int gq = t >> 3, rem = t & 7, wn = rem >> 1, ni = rem & 1;
        int n = wn * 16 + ni * 8 + gq;
        uint32_t hi, lo;
        pack_word(w2 + (size_t)b * 8192 + (size_t)c * 64 * 64, 64, k2, n, hi, lo);
        g_B2[0][b][c][r] = hi;
        g_B2[1][b][c][r] = lo;
    }
}

// ================== fused GEMM chain (mma.sync f16, A:ldmatrix, B:gmem L1) ==================
__device__ __forceinline__ uint32_t s2u(const void* p) {
    uint32_t a;
    asm("{ .reg .u64 t; cvta.to.shared.u64 t, %1; cvt.u32.u64 %0, t; }" : "=r"(a) : "l"(p));
    return a;
}
__device__ __forceinline__ void mma_f16(float* c, const uint32_t* a, const uint32_t* b) {
    asm volatile(
        "mma.sync.aligned.m16n8k16.row.col.f32.f16.f16.f32 "
        "{%0,%1,%2,%3}, {%4,%5,%6,%7}, {%8,%9}, {%0,%1,%2,%3};\n"
        : "+f"(c[0]), "+f"(c[1]), "+f"(c[2]), "+f"(c[3])
        : "r"(a[0]), "r"(a[1]), "r"(a[2]), "r"(a[3]), "r"(b[0]), "r"(b[1]));
}
#define LDSM4(r, a) \
    asm volatile("ldmatrix.sync.aligned.m8n8.x4.shared.b16 {%0,%1,%2,%3}, [%4];" \
        : "=r"((r)[0]), "=r"((r)[1]), "=r"((r)[2]), "=r"((r)[3]) : "r"(a))

constexpr int PAH = 136;    // A tile pitch in halfs
constexpr uint32_t AH_OFF = 0;
constexpr uint32_t AL_OFF = 34816;       // 128*136*2
constexpr int SMEM_FUSED = 69632;        // 2 A tiles only

// mma over one K=64 chunk (4 k16-steps); B via vectorized __ldg from gmem (L1-resident)
template <int NI, bool ALO>
__device__ __forceinline__ void mma_chunk(
    uint32_t aHiLane, uint32_t aLoLane, int colOffHalfs,
    const uint32_t* __restrict__ BH, const uint32_t* __restrict__ BL,
    int wn, int gq, int l4, float acc[4][NI][4])
{
    #pragma unroll
    for (int s = 0; s < 4; ++s) {
        const int k2a = 8 * s + l4, k2b = k2a + 4;
        uint32_t bh[NI][2], bl[NI][2];
        if constexpr (NI == 4) {
            const int base = gq * 16 + wn * 4;
            uint4 h0 = __ldg((const uint4*)(BH + k2a * 128 + base));
            uint4 h1 = __ldg((const uint4*)(BH + k2b * 128 + base));
            uint4 l0 = __ldg((const uint4*)(BL + k2a * 128 + base));
            uint4 l1 = __ldg((const uint4*)(BL + k2b * 128 + base));
            bh[0][0] = h0.x; bh[1][0] = h0.y; bh[2][0] = h0.z; bh[3][0] = h0.w;
            bh[0][1] = h1.x; bh[1][1] = h1.y; bh[2][1] = h1.z; bh[3][1] = h1.w;
            bl[0][0] = l0.x; bl[1][0] = l0.y; bl[2][0] = l0.z; bl[3][0] = l0.w;
            bl[0][1] = l1.x; bl[1][1] = l1.y; bl[2][1] = l1.z; bl[3][1] = l1.w;
        } else {
            const int base = gq * 8 + wn * 2;
            uint2 h0 = __ldg((const uint2*)(BH + k2a * 64 + base));
            uint2 h1 = __ldg((const uint2*)(BH + k2b * 64 + base));
            uint2 l0 = __ldg((const uint2*)(BL + k2a * 64 + base));
            uint2 l1 = __ldg((const uint2*)(BL + k2b * 64 + base));
            bh[0][0] = h0.x; bh[1][0] = h0.y;
            bh[0][1] = h1.x; bh[1][1] = h1.y;
            bl[0][0] = l0.x; bl[1][0] = l0.y;
            bl[0][1] = l1.x; bl[1][1] = l1.y;
        }
        const uint32_t aoff = (uint32_t)(colOffHalfs + s * 16) * 2;
        #pragma unroll
        for (int mi = 0; mi < 4; ++mi) {
            uint32_t ah[4];
            LDSM4(ah, aHiLane + aoff + mi * (16 * PAH * 2));
            #pragma unroll
            for (int ni = 0; ni < NI; ++ni) {
                mma_f16(acc[mi][ni], ah, bh[ni]);
                mma_f16(acc[mi][ni], ah, bl[ni]);
            }
            if (ALO) {
                uint32_t al[4];
                LDSM4(al, aLoLane + aoff + mi * (16 * PAH * 2));
                #pragma unroll
                for (int ni = 0; ni < NI; ++ni)
                    mma_f16(acc[mi][ni], al, bh[ni]);
            }
        }
    }
}

// -------- fused per-block kernel --------
__global__ void __launch_bounds__(256, 2)
fused_block(int blk,
            const float* __restrict__ b1, const float* __restrict__ b2,
            const float* __restrict__ cb, const float* __restrict__ betaPtr)
{
    extern __shared__ __align__(16) char smem[];
    const uint32_t sb = s2u(smem);

    const int tid  = threadIdx.x;
    const int warp = tid >> 5, lane = tid & 31;
    const int gq   = lane >> 2, l4 = lane & 3;
    const int wm   = warp >> 2, wn = warp & 3;    // 2 x 4 warp grid
    const int m0w  = wm * 64;
    const int mblk = blockIdx.x * 128;
    const float spv = log1pf(__expf(*betaPtr));
    const int n0w4 = wn * 32;
    const int n0w2 = wn * 16;

    const uint32_t aLaneOff = (uint32_t)((m0w + (lane & 15)) * PAH + (lane >> 4) * 8) * 2;
    const uint32_t aHiLane = sb + AH_OFF + aLaneOff;
    const uint32_t aLoLane = sb + AL_OFF + aLaneOff;

    float acc[4][4][4];

    // ===== Stage 1: cheb, 3 chunks; A = fp16 source (exact, 2-term), B from gmem =====
    #pragma unroll
    for (int mi = 0; mi < 4; ++mi)
        #pragma unroll
        for (int ni = 0; ni < 4; ++ni)
            #pragma unroll
            for (int q = 0; q < 4; ++q) acc[mi][ni][q] = 0.f;

    #pragma unroll 1
    for (int ch = 0; ch < 3; ++ch) {
        if (ch) __syncthreads();             // A reuse: prior mma must be done
        const __half* srcA = (ch == 0) ? g_hh : (ch == 1) ? g_t1h : g_t2h;
        for (int i = tid; i < 128 * 8; i += 256) {
            int m = i >> 3, q = i & 7;
            uint4 v = *(const uint4*)(srcA + (size_t)(mblk + m) * 64 + q * 8);
            *(uint4*)(smem + AH_OFF + (m * PAH + q * 8) * 2) = v;
        }
        __syncthreads();
        mma_chunk<4, false>(aHiLane, aLoLane, 0,
                            &g_Bc[0][blk][ch][0], &g_Bc[1][blk][ch][0],
                            wn, gq, l4, acc);
    }
    __syncthreads();

    // ===== Epilogue 1: bias+swish -> fp16 hi/lo A tiles (cols 0..127) =====
    #pragma unroll
    for (int mi = 0; mi < 4; ++mi) {
        int r0 = m0w + mi * 16 + gq;
        #pragma unroll
        for (int ni = 0; ni < 4; ++ni) {
            int c = n0w4 + ni * 8 + 2 * l4;
            float bb0 = __ldg(cb + c), bb1 = __ldg(cb + c + 1);
            float v00 = acc[mi][ni][0] + bb0, v01 = acc[mi][ni][1] + bb1;
            float v10 = acc[mi][ni][2] + bb0, v11 = acc[mi][ni][3] + bb1;
            v00 = v00 / (1.1f * (1.f + __expf(-v00 * spv)));
            v01 = v01 / (1.1f * (1.f + __expf(-v01 * spv)));
            v10 = v10 / (1.1f * (1.f + __expf(-v10 * spv)));
            v11 = v11 / (1.1f * (1.f + __expf(-v11 * spv)));
            __half h0, l0, h1, l1;
            split_h(v00, h0, l0); split_h(v01, h1, l1);
            *(__half2*)(smem + AH_OFF + (r0 * PAH + c) * 2) = __halves2half2(h0, h1);
            *(__half2*)(smem + AL_OFF + (r0 * PAH + c) * 2) = __halves2half2(l0, l1);
            split_h(v10, h0, l0); split_h(v11, h1, l1);
            *(__half2*)(smem + AH_OFF + ((r0 + 8) * PAH + c) * 2) = __halves2half2(h0, h1);
            *(__half2*)(smem + AL_OFF + ((r0 + 8) * PAH + c) * 2) = __halves2half2(l0, l1);
        }
    }
    __syncthreads();

    // ===== Stage 2: MLP1 (K=128, 3-term) — no internal barriers =====
    #pragma unroll
    for (int mi = 0; mi < 4; ++mi)
        #pragma unroll
        for (int ni = 0; ni < 4; ++ni)
            #pragma unroll
            for (int q = 0; q < 4; ++q) acc[mi][ni][q] = 0.f;

    mma_chunk<4, true>(aHiLane, aLoLane, 0,
                       &g_B1[0][blk][0][0], &g_B1[1][blk][0][0], wn, gq, l4, acc);
    mma_chunk<4, true>(aHiLane, aLoLane, 64,
                       &g_B1[0][blk][1][0], &g_B1[1][blk][1][0], wn, gq, l4, acc);
    __syncthreads();

    // ===== Epilogue 2 -> A tiles =====
    #pragma unroll
    for (int mi = 0; mi < 4; ++mi) {
        int r0 = m0w + mi * 16 + gq;
        #pragma unroll
        for (int ni = 0; ni < 4; ++ni) {
            int c = n0w4 + ni * 8 + 2 * l4;
            float bb0 = __ldg(b1 + c), bb1 = __ldg(b1 + c + 1);
            float v00 = acc[mi][ni][0] + bb0, v01 = acc[mi][ni][1] + bb1;
            float v10 = acc[mi][ni][2] + bb0, v11 = acc[mi][ni][3] + bb1;
            v00 = v00 / (1.1f * (1.f + __expf(-v00 * spv)));
            v01 = v01 / (1.1f * (1.f + __expf(-v01 * spv)));
            v10 = v10 / (1.1f * (1.f + __expf(-v10 * spv)));
            v11 = v11 / (1.1f * (1.f + __expf(-v11 * spv)));
            __half h0, l0, h1, l1;
            split_h(v00, h0, l0); split_h(v01, h1, l1);
            *(__half2*)(smem + AH_OFF + (r0 * PAH + c) * 2) = __halves2half2(h0, h1);
            *(__half2*)(smem + AL_OFF + (r0 * PAH + c) * 2) = __halves2half2(l0, l1);
            split_h(v10, h0, l0); split_h(v11, h1, l1);
            *(__half2*)(smem + AH_OFF + ((r0 + 8) * PAH + c) * 2) = __halves2half2(h0, h1);
            *(__half2*)(smem + AL_OFF + ((r0 + 8) * PAH + c) * 2) = __halves2half2(l0, l1);
        }
    }
    __syncthreads();

    // ===== Stage 3: MLP2 (N=64, 3-term) — no internal barriers =====
    float acc3[4][2][4];
    #pragma unroll
    for (int mi = 0; mi < 4; ++mi)
        #pragma unroll
        for (int ni = 0; ni < 2; ++ni)
            #pragma unroll
            for (int q = 0; q < 4; ++q) acc3[mi][ni][q] = 0.f;

    mma_chunk<2, true>(aHiLane, aLoLane, 0,
                       &g_B2[0][blk][0][0], &g_B2[1][blk][0][0], wn, gq, l4, acc3);
    mma_chunk<2, true>(aHiLane, aLoLane, 64,
                       &g_B2[0][blk][1][0], &g_B2[1][blk][1][0], wn, gq, l4, acc3);

    // ===== Final epilogue: h += Fx (gmem only) =====
    #pragma unroll
    for (int mi = 0; mi < 4; ++mi) {
        int r0 = mblk + m0w + mi * 16 + gq;
        #pragma unroll
        for (int ni = 0; ni < 2; ++ni) {
            int c = n0w2 + ni * 8 + 2 * l4;
            float bb0 = __ldg(b2 + c), bb1 = __ldg(b2 + c + 1);
            float2 cur0 = *(float2*)(g_h + (size_t)r0 * 64 + c);
            float2 cur1 = *(float2*)(g_h + (size_t)(r0 + 8) * 64 + c);
            cur0.x += acc3[mi][ni][0] + bb0;
            cur0.y += acc3[mi][ni][1] + bb1;
            cur1.x += acc3[mi][ni][2] + bb0;
            cur1.y += acc3[mi][ni][3] + bb1;
            *(float2*)(g_h + (size_t)r0 * 64 + c)       = cur0;
            *(float2*)(g_h + (size_t)(r0 + 8) * 64 + c) = cur1;
            *(__half2*)(g_hh + (size_t)r0 * 64 + c)       = __floats2half2_rn(cur0.x, cur0.y);
            *(__half2*)(g_hh + (size_t)(r0 + 8) * 64 + c) = __floats2half2_rn(cur1.x, cur1.y);
        }
    }
}

// -------- host launcher --------
extern "C" void kernel_launch(void* const* d_in, const int* in_sizes, int n_in,
                              void* d_out, int out_size) {
    const float* x      = (const float*)d_in[0];
    const int*   ei     = (const int*)  d_in[1];
    const float* ew     = (const float*)d_in[2];
    const float* cheb_w = (const float*)d_in[3];
    const float* cheb_b = (const float*)d_in[4];
    const float* beta   = (const float*)d_in[5];
    const float* w1     = (const float*)d_in[6];
    const float* b1     = (const float*)d_in[7];
    const float* w2     = (const float*)d_in[8];
    const float* b2     = (const float*)d_in[9];
    float* out = (float*)d_out;
    const int* src = ei;
    const int* dst = ei + Ee;

    cudaFuncSetAttribute((const void*)fused_block,
                         cudaFuncAttributeMaxDynamicSharedMemorySize, SMEM_FUSED);

    const int EB = (Ee + 255) / 256;
    const int NBk = (Nn + 255) / 256;

    zero_deg_cnt<<<NBk, 256>>>();
    deg_kernel<<<EB, 256>>>(src, ew);
    dinv_kernel<<<NBk, 256>>>();
    w_count_kernel<<<EB, 256>>>(src, dst, ew);
    scan_kernel<<<1, 1024>>>();
    fill_kernel<<<EB, 256>>>(src, dst);
    prep_wc_all<<<96, 256>>>(cheb_w);
    prep_Bc<<<144, 256>>>();
    prep_B1<<<96, 256>>>(w1);
    prep_B2<<<48, 256>>>(w2);

    t_in_kernel<<<Nn, 256>>>((const float4*)x);

    for (int b = 0; b < NBlk; ++b) {
        spmm16_kernel<0><<<Nn, 256>>>();
        spmm16_kernel<1><<<Nn, 256>>>();
        fused_block<<<2500, 256, SMEM_FUSED>>>(
            b, b1 + b * 128, b2 + b * 64, cheb_b + b * 128, beta + b);
    }

    t_out_kernel<<<Nn, 256>>>((float4*)out);
}

// round 9
// speedup vs baseline: 2.6087x; 1.0295x over previous
#include <cuda_runtime.h>
#include <cuda_fp16.h>
#include <stdint.h>
#include <math.h>

// Problem constants
constexpr int Bc   = 16;
constexpr int Nn   = 20000;
constexpr int Cc   = 64;
constexpr int Ee   = 640000;
constexpr int NBlk = 3;
constexpr int ROWS = Nn * Bc;          // 320000
constexpr int RowF = Bc * Cc;          // 1024 halfs per node row ([N][B][C])
constexpr int RowF4 = RowF / 4;

// -------- device scratch --------
__device__ __align__(16) float  g_h  [ROWS * Cc];
__device__ __align__(16) __half g_hh [ROWS * Cc];
__device__ __align__(16) __half g_t1h[ROWS * Cc];
__device__ __align__(16) __half g_t2h[ROWS * Cc];
__device__ float g_deg [Nn];
__device__ float g_dinv[Nn];
__device__ float g_w   [Ee];
__device__ int   g_off [Nn + 1];
__device__ int   g_cnt [Nn];
__device__ int   g_csrc[Ee];
__device__ float g_csw [Ee];
__device__ float g_wc  [3 * 192 * 128];
// Pre-packed fp16 hi/lo B operands, LANE-VECTORIZED fragment layout:
// N=128: word r = k2*128 + gq*16 + wn*4 + ni  (n = wn*32 + ni*8 + gq)
// N=64 : word r = k2*64  + gq*8  + wn*2 + ni  (n = wn*16 + ni*8 + gq)
__device__ __align__(16) uint32_t g_Bc[2][3][3][32 * 128];
__device__ __align__(16) uint32_t g_B1[2][3][2][32 * 128];
__device__ __align__(16) uint32_t g_B2[2][3][2][32 * 64];

// -------- small setup kernels --------
__global__ void zero_deg_cnt() {
    int i = blockIdx.x * blockDim.x + threadIdx.x;
    if (i < Nn) { g_deg[i] = 0.f; g_cnt[i] = 0; }
}
__global__ void deg_kernel(const int* __restrict__ src, const float* __restrict__ ew) {
    int e = blockIdx.x * blockDim.x + threadIdx.x;
    if (e < Ee) atomicAdd(&g_deg[src[e]], ew[e]);
}
__global__ void dinv_kernel() {
    int i = blockIdx.x * blockDim.x + threadIdx.x;
    if (i < Nn) {
        float d = g_deg[i];
        g_dinv[i] = (d > 0.f) ? rsqrtf(fmaxf(d, 1e-12f)) : 0.f;
    }
}
__global__ void w_count_kernel(const int* __restrict__ src, const int* __restrict__ dst,
                               const float* __restrict__ ew) {
    int e = blockIdx.x * blockDim.x + threadIdx.x;
    if (e < Ee) {
        int s = src[e], d = dst[e];
        g_w[e] = -g_dinv[s] * ew[e] * g_dinv[d];
        atomicAdd(&g_cnt[d], 1);
    }
}
__global__ void scan_kernel() {
    __shared__ int warp_sums[32];
    __shared__ int s_carry;
    int t = threadIdx.x;
    if (t == 0) s_carry = 0;
    __syncthreads();
    for (int base = 0; base < Nn; base += 1024) {
        int v = (base + t < Nn) ? g_cnt[base + t] : 0;
        if (base + t < Nn) g_cnt[base + t] = 0;
        int x = v;
        #pragma unroll
        for (int d = 1; d < 32; d <<= 1) {
            int y = __shfl_up_sync(0xFFFFFFFFu, x, d);
            if ((t & 31) >= d) x += y;
        }
        if ((t & 31) == 31) warp_sums[t >> 5] = x;
        __syncthreads();
        if (t < 32) {
            int y = warp_sums[t];
            #pragma unroll
            for (int d = 1; d < 32; d <<= 1) {
                int z = __shfl_up_sync(0xFFFFFFFFu, y, d);
                if (t >= d) y += z;
            }
            warp_sums[t] = y;
        }
        __syncthreads();
        int excl = s_carry + (x - v) + ((t >= 32) ? warp_sums[(t >> 5) - 1] : 0);
        if (base + t < Nn) g_off[base + t] = excl;
        __syncthreads();
        if (t == 0) s_carry += warp_sums[31];
        __syncthreads();
    }
    if (t == 0) g_off[Nn] = s_carry;
}
__global__ void fill_kernel(const int* __restrict__ src, const int* __restrict__ dst) {
    int e = blockIdx.x * blockDim.x + threadIdx.x;
    if (e < Ee) {
        int d = dst[e];
        int pos = g_off[d] + atomicAdd(&g_cnt[d], 1);
        g_csrc[pos] = src[e];
        g_csw[pos]  = g_w[e];
    }
}

// -------- transposes --------
__global__ void t_in_kernel(const float4* __restrict__ x4) {
    int idx = blockIdx.x * 256 + threadIdx.x;
    int b = idx / (Nn * 16);
    int r = idx % (Nn * 16);
    int n = r >> 4, c4 = r & 15;
    float4 v = x4[idx];
    int o4 = n * RowF4 + b * 16 + c4;
    ((float4*)g_h)[o4] = v;
    ((__half2*)g_hh)[o4 * 2]     = __floats2half2_rn(v.x, v.y);
    ((__half2*)g_hh)[o4 * 2 + 1] = __floats2half2_rn(v.z, v.w);
}
__global__ void t_out_kernel(float4* __restrict__ o4) {
    int idx = blockIdx.x * 256 + threadIdx.x;
    int b = idx / (Nn * 16);
    int r = idx % (Nn * 16);
    int n = r >> 4, c4 = r & 15;
    o4[idx] = ((const float4*)g_h)[n * RowF4 + b * 16 + c4];
}

// -------- SpMM fp16, dual edge streams --------
template <int PHASE>
__global__ void __launch_bounds__(256) spmm16_kernel() {
    const __half* __restrict__ in = (PHASE == 0) ? g_hh : g_t1h;
    __half* __restrict__ out      = (PHASE == 0) ? g_t1h : g_t2h;
    __shared__ float red[8 * 128];
    int n = blockIdx.x;
    int stream = threadIdx.x >> 7;
    int t = threadIdx.x & 127;
    int e0 = g_off[n], e1 = g_off[n + 1];
    float acc[8];
    #pragma unroll
    for (int q = 0; q < 8; ++q) acc[q] = 0.f;
    #pragma unroll 4
    for (int e = e0 + stream; e < e1; e += 2) {
        int   s  = __ldg(&g_csrc[e]);
        float wv = __ldg(&g_csw[e]);
        uint4 raw = __ldg((const uint4*)(in + (size_t)s * RowF) + t);
        const __half2* hp = (const __half2*)&raw;
        #pragma unroll
        for (int p = 0; p < 4; ++p) {
            float2 f = __half22float2(hp[p]);
            acc[2 * p]     = fmaf(wv, f.x, acc[2 * p]);
            acc[2 * p + 1] = fmaf(wv, f.y, acc[2 * p + 1]);
        }
    }
    if (stream) {
        #pragma unroll
        for (int q = 0; q < 8; ++q) red[q * 128 + t] = acc[q];
    }
    __syncthreads();
    if (!stream) {
        uint4 res;
        __half2* rp = (__half2*)&res;
        #pragma unroll
        for (int p = 0; p < 4; ++p)
            rp[p] = __floats2half2_rn(acc[2 * p] + red[(2 * p) * 128 + t],
                                      acc[2 * p + 1] + red[(2 * p + 1) * 128 + t]);
        ((uint4*)(out + (size_t)n * RowF))[t] = res;
    }
}

// -------- weight prep --------
__global__ void prep_wc_all(const float* __restrict__ cw) {
    int idx = blockIdx.x * 256 + threadIdx.x;
    if (idx < 3 * 8192) {
        int b = idx >> 13, r = idx & 8191;
        const float* base = cw + (size_t)b * 24576;
        float w0  = base[r];
        float w1v = base[8192 + r];
        float w2v = base[16384 + r];
        float* o = g_wc + (size_t)b * 24576;
        o[r]         = w0 - w2v;
        o[8192 + r]  = w1v;
        o[16384 + r] = 2.f * w2v;
    }
}
__device__ __forceinline__ void split_h(float v, __half& h, __half& l) {
    h = __float2half_rn(v);
    l = __float2half_rn(v - __half2float(h));
}
__device__ __forceinline__ uint32_t pack_h2(__half a, __half b) {
    __half2 t = __halves2half2(a, b);
    return *(uint32_t*)&t;
}
__device__ __forceinline__ void pack_word(const float* W, int BN, int k2, int n,
                                          uint32_t& hi, uint32_t& lo) {
    float v0 = W[(size_t)(2 * k2) * BN + n];
    float v1 = W[(size_t)(2 * k2 + 1) * BN + n];
    __half h0, l0, h1, l1;
    split_h(v0, h0, l0); split_h(v1, h1, l1);
    hi = pack_h2(h0, h1);
    lo = pack_h2(l0, l1);
}
__global__ void prep_Bc() {
    int idx = blockIdx.x * 256 + threadIdx.x;
    if (idx < 36864) {
        int b = idx / 12288, r2 = idx % 12288;
        int c = r2 >> 12, r = r2 & 4095;
        int k2 = r >> 7, t = r & 127;
        int gq = t >> 4, rem = t & 15, wn = rem >> 2, ni = rem & 3;
        int n = wn * 32 + ni * 8 + gq;
        uint32_t hi, lo;
        pack_word(g_wc + (size_t)b * 24576 + (size_t)c * 64 * 128, 128, k2, n, hi, lo);
        g_Bc[0][b][c][r] = hi;
        g_Bc[1][b][c][r] = lo;
    }
}
__global__ void prep_B1(const float* __restrict__ w1) {
    int idx = blockIdx.x * 256 + threadIdx.x;
    if (idx < 24576) {
        int b = idx / 8192, r2 = idx % 8192;
        int c = r2 >> 12, r = r2 & 4095;
        int k2 = r >> 7, t = r & 127;
        int gq = t >> 4, rem = t & 15, wn = rem >> 2, ni = rem & 3;
        int n = wn * 32 + ni * 8 + gq;
        uint32_t hi, lo;
        pack_word(w1 + (size_t)b * 16384 + (size_t)c * 64 * 128, 128, k2, n, hi, lo);
        g_B1[0][b][c][r] = hi;
        g_B1[1][b][c][r] = lo;
    }
}
__global__ void prep_B2(const float* __restrict__ w2) {
    int idx = blockIdx.x * 256 + threadIdx.x;
    if (idx < 12288) {
        int b = idx / 4096, r2 = idx % 4096;
        int c = r2 >> 11, r = r2 & 2047;
        int k2 = r >> 6, t = r & 63;
        int gq = t >> 3, rem = t & 7, wn = rem >> 1, ni = rem & 1;
        int n = wn * 16 + ni * 8 + gq;
        uint32_t hi, lo;
        pack_word(w2 + (size_t)b * 8192 + (size_t)c * 64 * 64, 64, k2, n, hi, lo);
        g_B2[0][b][c][r] = hi;
        g_B2[1][b][c][r] = lo;
    }
}

// ================== fused GEMM chain (mma.sync f16, A hi-only, B hi+lo) ==================
__device__ __forceinline__ uint32_t s2u(const void* p) {
    uint32_t a;
    asm("{ .reg .u64 t; cvta.to.shared.u64 t, %1; cvt.u32.u64 %0, t; }" : "=r"(a) : "l"(p));
    return a;
}
__device__ __forceinline__ void mma_f16(float* c, const uint32_t* a, const uint32_t* b) {
    asm volatile(
        "mma.sync.aligned.m16n8k16.row.col.f32.f16.f16.f32 "
        "{%0,%1,%2,%3}, {%4,%5,%6,%7}, {%8,%9}, {%0,%1,%2,%3};\n"
        : "+f"(c[0]), "+f"(c[1]), "+f"(c[2]), "+f"(c[3])
        : "r"(a[0]), "r"(a[1]), "r"(a[2]), "r"(a[3]), "r"(b[0]), "r"(b[1]));
}
#define LDSM4(r, a) \
    asm volatile("ldmatrix.sync.aligned.m8n8.x4.shared.b16 {%0,%1,%2,%3}, [%4];" \
        : "=r"((r)[0]), "=r"((r)[1]), "=r"((r)[2]), "=r"((r)[3]) : "r"(a))

constexpr int PAH = 136;                 // A tile pitch in halfs
constexpr uint32_t A0_OFF = 0;           // ping buffer
constexpr uint32_t A1_OFF = 34816;       // pong buffer (128*136*2)
constexpr int SMEM_FUSED = 69632;

// mma over one K=64 chunk (4 k16-steps); A hi-only via ldmatrix, B hi+lo via __ldg
template <int NI>
__device__ __forceinline__ void mma_chunk(
    uint32_t aLane, int colOffHalfs,
    const uint32_t* __restrict__ BH, const uint32_t* __restrict__ BL,
    int wn, int gq, int l4, float acc[4][NI][4])
{
    #pragma unroll
    for (int s = 0; s < 4; ++s) {
        const int k2a = 8 * s + l4, k2b = k2a + 4;
        uint32_t bh[NI][2], bl[NI][2];
        if constexpr (NI == 4) {
            const int base = gq * 16 + wn * 4;
            uint4 h0 = __ldg((const uint4*)(BH + k2a * 128 + base));
            uint4 h1 = __ldg((const uint4*)(BH + k2b * 128 + base));
            uint4 l0 = __ldg((const uint4*)(BL + k2a * 128 + base));
            uint4 l1 = __ldg((const uint4*)(BL + k2b * 128 + base));
            bh[0][0] = h0.x; bh[1][0] = h0.y; bh[2][0] = h0.z; bh[3][0] = h0.w;
            bh[0][1] = h1.x; bh[1][1] = h1.y; bh[2][1] = h1.z; bh[3][1] = h1.w;
            bl[0][0] = l0.x; bl[1][0] = l0.y; bl[2][0] = l0.z; bl[3][0] = l0.w;
            bl[0][1] = l1.x; bl[1][1] = l1.y; bl[2][1] = l1.z; bl[3][1] = l1.w;
        } else {
            const int base = gq * 8 + wn * 2;
            uint2 h0 = __ldg((const uint2*)(BH + k2a * 64 + base));
            uint2 h1 = __ldg((const uint2*)(BH + k2b * 64 + base));
            uint2 l0 = __ldg((const uint2*)(BL + k2a * 64 + base));
            uint2 l1 = __ldg((const uint2*)(BL + k2b * 64 + base));
            bh[0][0] = h0.x; bh[1][0] = h0.y;
            bh[0][1] = h1.x; bh[1][1] = h1.y;
            bl[0][0] = l0.x; bl[1][0] = l0.y;
            bl[0][1] = l1.x; bl[1][1] = l1.y;
        }
        const uint32_t aoff = (uint32_t)(colOffHalfs + s * 16) * 2;
        #pragma unroll
        for (int mi = 0; mi < 4; ++mi) {
            uint32_t ah[4];
            LDSM4(ah, aLane + aoff + mi * (16 * PAH * 2));
            #pragma unroll
            for (int ni = 0; ni < NI; ++ni) {
                mma_f16(acc[mi][ni], ah, bh[ni]);
                mma_f16(acc[mi][ni], ah, bl[ni]);
            }
        }
    }
}

// -------- fused per-block kernel --------
__global__ void __launch_bounds__(256, 2)
fused_block(int blk,
            const float* __restrict__ b1, const float* __restrict__ b2,
            const float* __restrict__ cb, const float* __restrict__ betaPtr)
{
    extern __shared__ __align__(16) char smem[];
    const uint32_t sb = s2u(smem);

    const int tid  = threadIdx.x;
    const int warp = tid >> 5, lane = tid & 31;
    const int gq   = lane >> 2, l4 = lane & 3;
    const int wm   = warp >> 2, wn = warp & 3;    // 2 x 4 warp grid
    const int m0w  = wm * 64;
    const int mblk = blockIdx.x * 128;
    const float spv = log1pf(__expf(*betaPtr));
    const int n0w4 = wn * 32;
    const int n0w2 = wn * 16;

    const uint32_t aLaneOff = (uint32_t)((m0w + (lane & 15)) * PAH + (lane >> 4) * 8) * 2;
    const uint32_t aLane0 = sb + A0_OFF + aLaneOff;
    const uint32_t aLane1 = sb + A1_OFF + aLaneOff;

    float acc[4][4][4];

    // ===== Stage 1: cheb, 3 chunks, ping-pong A buffers (A0, A1, A0) =====
    #pragma unroll
    for (int mi = 0; mi < 4; ++mi)
        #pragma unroll
        for (int ni = 0; ni < 4; ++ni)
            #pragma unroll
            for (int q = 0; q < 4; ++q) acc[mi][ni][q] = 0.f;

    #pragma unroll 1
    for (int ch = 0; ch < 3; ++ch) {
        const __half* srcA = (ch == 0) ? g_hh : (ch == 1) ? g_t1h : g_t2h;
        const uint32_t dstOff = (ch == 1) ? A1_OFF : A0_OFF;
        for (int i = tid; i < 128 * 8; i += 256) {
            int m = i >> 3, q = i & 7;
            uint4 v = *(const uint4*)(srcA + (size_t)(mblk + m) * 64 + q * 8);
            *(uint4*)(smem + dstOff + (m * PAH + q * 8) * 2) = v;
        }
        __syncthreads();
        mma_chunk<4>(((ch == 1) ? aLane1 : aLane0), 0,
                     &g_Bc[0][blk][ch][0], &g_Bc[1][blk][ch][0],
                     wn, gq, l4, acc);
    }

    // ===== Epilogue 1: bias+swish -> fp16 into A1 (cols 0..127) =====
    // A1's last readers (chunk 1 LDSMs) finished before the ch2 sync.
    #pragma unroll
    for (int mi = 0; mi < 4; ++mi) {
        int r0 = m0w + mi * 16 + gq;
        #pragma unroll
        for (int ni = 0; ni < 4; ++ni) {
            int c = n0w4 + ni * 8 + 2 * l4;
            float bb0 = __ldg(cb + c), bb1 = __ldg(cb + c + 1);
            float v00 = acc[mi][ni][0] + bb0, v01 = acc[mi][ni][1] + bb1;
            float v10 = acc[mi][ni][2] + bb0, v11 = acc[mi][ni][3] + bb1;
            v00 = v00 / (1.1f * (1.f + __expf(-v00 * spv)));
            v01 = v01 / (1.1f * (1.f + __expf(-v01 * spv)));
            v10 = v10 / (1.1f * (1.f + __expf(-v10 * spv)));
            v11 = v11 / (1.1f * (1.f + __expf(-v11 * spv)));
            *(__half2*)(smem + A1_OFF + (r0 * PAH + c) * 2)       = __floats2half2_rn(v00, v01);
            *(__half2*)(smem + A1_OFF + ((r0 + 8) * PAH + c) * 2) = __floats2half2_rn(v10, v11);
        }
    }
    __syncthreads();

    // ===== Stage 2: MLP1 (K=128 from A1, 2-term) =====
    #pragma unroll
    for (int mi = 0; mi < 4; ++mi)
        #pragma unroll
        for (int ni = 0; ni < 4; ++ni)
            #pragma unroll
            for (int q = 0; q < 4; ++q) acc[mi][ni][q] = 0.f;

    mma_chunk<4>(aLane1, 0,  &g_B1[0][blk][0][0], &g_B1[1][blk][0][0], wn, gq, l4, acc);
    mma_chunk<4>(aLane1, 64, &g_B1[0][blk][1][0], &g_B1[1][blk][1][0], wn, gq, l4, acc);

    // ===== Epilogue 2 -> A0 (chunk-2 readers of A0 finished before epilogue-1 sync) =====
    #pragma unroll
    for (int mi = 0; mi < 4; ++mi) {
        int r0 = m0w + mi * 16 + gq;
        #pragma unroll
        for (int ni = 0; ni < 4; ++ni) {
            int c = n0w4 + ni * 8 + 2 * l4;
            float bb0 = __ldg(b1 + c), bb1 = __ldg(b1 + c + 1);
            float v00 = acc[mi][ni][0] + bb0, v01 = acc[mi][ni][1] + bb1;
            float v10 = acc[mi][ni][2] + bb0, v11 = acc[mi][ni][3] + bb1;
            v00 = v00 / (1.1f * (1.f + __expf(-v00 * spv)));
            v01 = v01 / (1.1f * (1.f + __expf(-v01 * spv)));
            v10 = v10 / (1.1f * (1.f + __expf(-v10 * spv)));
            v11 = v11 / (1.1f * (1.f + __expf(-v11 * spv)));
            *(__half2*)(smem + A0_OFF + (r0 * PAH + c) * 2)       = __floats2half2_rn(v00, v01);
            *(__half2*)(smem + A0_OFF + ((r0 + 8) * PAH + c) * 2) = __floats2half2_rn(v10, v11);
        }
    }
    __syncthreads();

    // ===== Stage 3: MLP2 (N=64 from A0, 2-term) + residual =====
    float acc3[4][2][4];
    #pragma unroll
    for (int mi = 0; mi < 4; ++mi)
        #pragma unroll
        for (int ni = 0; ni < 2; ++ni)
            #pragma unroll
            for (int q = 0; q < 4; ++q) acc3[mi][ni][q] = 0.f;

    mma_chunk<2>(aLane0, 0,  &g_B2[0][blk][0][0], &g_B2[1][blk][0][0], wn, gq, l4, acc3);
    mma_chunk<2>(aLane0, 64, &g_B2[0][blk][1][0], &g_B2[1][blk][1][0], wn, gq, l4, acc3);

    // ===== Final epilogue: h += Fx (gmem only) =====
    #pragma unroll
    for (int mi = 0; mi < 4; ++mi) {
        int r0 = mblk + m0w + mi * 16 + gq;
        #pragma unroll
        for (int ni = 0; ni < 2; ++ni) {
            int c = n0w2 + ni * 8 + 2 * l4;
            float bb0 = __ldg(b2 + c), bb1 = __ldg(b2 + c + 1);
            float2 cur0 = *(float2*)(g_h + (size_t)r0 * 64 + c);
            float2 cur1 = *(float2*)(g_h + (size_t)(r0 + 8) * 64 + c);
            cur0.x += acc3[mi][ni][0] + bb0;
            cur0.y += acc3[mi][ni][1] + bb1;
            cur1.x += acc3[mi][ni][2] + bb0;
            cur1.y += acc3[mi][ni][3] + bb1;
            *(float2*)(g_h + (size_t)r0 * 64 + c)       = cur0;
            *(float2*)(g_h + (size_t)(r0 + 8) * 64 + c) = cur1;
            *(__half2*)(g_hh + (size_t)r0 * 64 + c)       = __floats2half2_rn(cur0.x, cur0.y);
            *(__half2*)(g_hh + (size_t)(r0 + 8) * 64 + c) = __floats2half2_rn(cur1.x, cur1.y);
        }
    }
}

// -------- host launcher --------
extern "C" void kernel_launch(void* const* d_in, const int* in_sizes, int n_in,
                              void* d_out, int out_size) {
    const float* x      = (const float*)d_in[0];
    const int*   ei     = (const int*)  d_in[1];
    const float* ew     = (const float*)d_in[2];
    const float* cheb_w = (const float*)d_in[3];
    const float* cheb_b = (const float*)d_in[4];
    const float* beta   = (const float*)d_in[5];
    const float* w1     = (const float*)d_in[6];
    const float* b1     = (const float*)d_in[7];
    const float* w2     = (const float*)d_in[8];
    const float* b2     = (const float*)d_in[9];
    float* out = (float*)d_out;
    const int* src = ei;
    const int* dst = ei + Ee;

    cudaFuncSetAttribute((const void*)fused_block,
                         cudaFuncAttributeMaxDynamicSharedMemorySize, SMEM_FUSED);

    const int EB = (Ee + 255) / 256;
    const int NBk = (Nn + 255) / 256;

    zero_deg_cnt<<<NBk, 256>>>();
    deg_kernel<<<EB, 256>>>(src, ew);
    dinv_kernel<<<NBk, 256>>>();
    w_count_kernel<<<EB, 256>>>(src, dst, ew);
    scan_kernel<<<1, 1024>>>();
    fill_kernel<<<EB, 256>>>(src, dst);
    prep_wc_all<<<96, 256>>>(cheb_w);
    prep_Bc<<<144, 256>>>();
    prep_B1<<<96, 256>>>(w1);
    prep_B2<<<48, 256>>>(w2);

    t_in_kernel<<<Nn, 256>>>((const float4*)x);

    for (int b = 0; b < NBlk; ++b) {
        spmm16_kernel<0><<<Nn, 256>>>();
        spmm16_kernel<1><<<Nn, 256>>>();
        fused_block<<<2500, 256, SMEM_FUSED>>>(
            b, b1 + b * 128, b2 + b * 64, cheb_b + b * 128, beta + b);
    }

    t_out_kernel<<<Nn, 256>>>((float4*)out);
}

// round 10
// speedup vs baseline: 3.0319x; 1.1622x over previous
#include <cuda_runtime.h>
#include <cuda_fp16.h>
#include <stdint.h>
#include <math.h>

// Problem constants
constexpr int Bc   = 16;
constexpr int Nn   = 20000;
constexpr int Cc   = 64;
constexpr int Ee   = 640000;
constexpr int NBlk = 3;
constexpr int ROWS = Nn * Bc;          // 320000
constexpr int RowF = Bc * Cc;          // 1024 halfs per node row ([N][B][C])
constexpr int RowF4 = RowF / 4;

// -------- device scratch --------
__device__ __align__(16) float  g_h  [ROWS * Cc];
__device__ __align__(16) __half g_hh [ROWS * Cc];
__device__ __align__(16) __half g_t1h[ROWS * Cc];
__device__ __align__(16) __half g_t2h[ROWS * Cc];
__device__ float g_deg [Nn];
__device__ float g_dinv[Nn];
__device__ float g_w   [Ee];
__device__ int   g_off [Nn + 1];
__device__ int   g_cnt [Nn];
__device__ int   g_csrc[Ee];
__device__ float g_csw [Ee];
// Pre-packed fp16 hi/lo B operands, LANE-VECTORIZED fragment layout:
// N=128: word r = k2*128 + gq*16 + wn*4 + ni  (n = wn*32 + ni*8 + gq)
// N=64 : word r = k2*64  + gq*8  + wn*2 + ni  (n = wn*16 + ni*8 + gq)
__device__ __align__(16) uint32_t g_Bc[2][3][3][32 * 128];
__device__ __align__(16) uint32_t g_B1[2][3][2][32 * 128];
__device__ __align__(16) uint32_t g_B2[2][3][2][32 * 64];

// -------- small setup kernels --------
__global__ void zero_deg_cnt() {
    int i = blockIdx.x * blockDim.x + threadIdx.x;
    if (i < Nn) { g_deg[i] = 0.f; g_cnt[i] = 0; }
}
__global__ void deg_kernel(const int* __restrict__ src, const float* __restrict__ ew) {
    int e = blockIdx.x * blockDim.x + threadIdx.x;
    if (e < Ee) atomicAdd(&g_deg[src[e]], ew[e]);
}
__global__ void dinv_kernel() {
    int i = blockIdx.x * blockDim.x + threadIdx.x;
    if (i < Nn) {
        float d = g_deg[i];
        g_dinv[i] = (d > 0.f) ? rsqrtf(fmaxf(d, 1e-12f)) : 0.f;
    }
}
__global__ void w_count_kernel(const int* __restrict__ src, const int* __restrict__ dst,
                               const float* __restrict__ ew) {
    int e = blockIdx.x * blockDim.x + threadIdx.x;
    if (e < Ee) {
        int s = src[e], d = dst[e];
        g_w[e] = -g_dinv[s] * ew[e] * g_dinv[d];
        atomicAdd(&g_cnt[d], 1);
    }
}
__global__ void scan_kernel() {
    __shared__ int warp_sums[32];
    __shared__ int s_carry;
    int t = threadIdx.x;
    if (t == 0) s_carry = 0;
    __syncthreads();
    for (int base = 0; base < Nn; base += 1024) {
        int v = (base + t < Nn) ? g_cnt[base + t] : 0;
        if (base + t < Nn) g_cnt[base + t] = 0;
        int x = v;
        #pragma unroll
        for (int d = 1; d < 32; d <<= 1) {
            int y = __shfl_up_sync(0xFFFFFFFFu, x, d);
            if ((t & 31) >= d) x += y;
        }
        if ((t & 31) == 31) warp_sums[t >> 5] = x;
        __syncthreads();
        if (t < 32) {
            int y = warp_sums[t];
            #pragma unroll
            for (int d = 1; d < 32; d <<= 1) {
                int z = __shfl_up_sync(0xFFFFFFFFu, y, d);
                if (t >= d) y += z;
            }
            warp_sums[t] = y;
        }
        __syncthreads();
        int excl = s_carry + (x - v) + ((t >= 32) ? warp_sums[(t >> 5) - 1] : 0);
        if (base + t < Nn) g_off[base + t] = excl;
        __syncthreads();
        if (t == 0) s_carry += warp_sums[31];
        __syncthreads();
    }
    if (t == 0) g_off[Nn] = s_carry;
}
__global__ void fill_kernel(const int* __restrict__ src, const int* __restrict__ dst) {
    int e = blockIdx.x * blockDim.x + threadIdx.x;
    if (e < Ee) {
        int d = dst[e];
        int pos = g_off[d] + atomicAdd(&g_cnt[d], 1);
        g_csrc[pos] = src[e];
        g_csw[pos]  = g_w[e];
    }
}

// -------- transposes --------
__global__ void t_in_kernel(const float4* __restrict__ x4) {
    int idx = blockIdx.x * 256 + threadIdx.x;
    int b = idx / (Nn * 16);
    int r = idx % (Nn * 16);
    int n = r >> 4, c4 = r & 15;
    float4 v = x4[idx];
    int o4 = n * RowF4 + b * 16 + c4;
    ((float4*)g_h)[o4] = v;
    ((__half2*)g_hh)[o4 * 2]     = __floats2half2_rn(v.x, v.y);
    ((__half2*)g_hh)[o4 * 2 + 1] = __floats2half2_rn(v.z, v.w);
}
__global__ void t_out_kernel(float4* __restrict__ o4) {
    int idx = blockIdx.x * 256 + threadIdx.x;
    int b = idx / (Nn * 16);
    int r = idx % (Nn * 16);
    int n = r >> 4, c4 = r & 15;
    o4[idx] = ((const float4*)g_h)[n * RowF4 + b * 16 + c4];
}

// -------- SpMM fp16, dual edge streams (BW-bound, leave alone) --------
template <int PHASE>
__global__ void __launch_bounds__(256) spmm16_kernel() {
    const __half* __restrict__ in = (PHASE == 0) ? g_hh : g_t1h;
    __half* __restrict__ out      = (PHASE == 0) ? g_t1h : g_t2h;
    __shared__ float red[8 * 128];
    int n = blockIdx.x;
    int stream = threadIdx.x >> 7;
    int t = threadIdx.x & 127;
    int e0 = g_off[n], e1 = g_off[n + 1];
    float acc[8];
    #pragma unroll
    for (int q = 0; q < 8; ++q) acc[q] = 0.f;
    #pragma unroll 4
    for (int e = e0 + stream; e < e1; e += 2) {
        int   s  = __ldg(&g_csrc[e]);
        float wv = __ldg(&g_csw[e]);
        uint4 raw = __ldg((const uint4*)(in + (size_t)s * RowF) + t);
        const __half2* hp = (const __half2*)&raw;
        #pragma unroll
        for (int p = 0; p < 4; ++p) {
            float2 f = __half22float2(hp[p]);
            acc[2 * p]     = fmaf(wv, f.x, acc[2 * p]);
            acc[2 * p + 1] = fmaf(wv, f.y, acc[2 * p + 1]);
        }
    }
    if (stream) {
        #pragma unroll
        for (int q = 0; q < 8; ++q) red[q * 128 + t] = acc[q];
    }
    __syncthreads();
    if (!stream) {
        uint4 res;
        __half2* rp = (__half2*)&res;
        #pragma unroll
        for (int p = 0; p < 4; ++p)
            rp[p] = __floats2half2_rn(acc[2 * p] + red[(2 * p) * 128 + t],
                                      acc[2 * p + 1] + red[(2 * p + 1) * 128 + t]);
        ((uint4*)(out + (size_t)n * RowF))[t] = res;
    }
}

// -------- merged weight prep: g_Bc (cheb prepack inline), g_B1, g_B2 --------
__device__ __forceinline__ void split_h(float v, __half& h, __half& l) {
    h = __float2half_rn(v);
    l = __float2half_rn(v - __half2float(h));
}
__device__ __forceinline__ uint32_t pack_h2(__half a, __half b) {
    __half2 t = __halves2half2(a, b);
    return *(uint32_t*)&t;
}
__device__ __forceinline__ void pack2f(float v0, float v1, uint32_t& hi, uint32_t& lo) {
    __half h0, l0, h1, l1;
    split_h(v0, h0, l0); split_h(v1, h1, l1);
    hi = pack_h2(h0, h1);
    lo = pack_h2(l0, l1);
}
// cheb combined weight value: row r in [0,192) of [W0-W2 | W1 | 2W2], col n
__device__ __forceinline__ float wc_val(const float* __restrict__ cw, int b, int rg, int n) {
    int term = rg >> 6, kk = rg & 63;
    float v;
    if (term == 0)
        v = cw[((size_t)(b * 3 + 0) * 64 + kk) * 128 + n] -
            cw[((size_t)(b * 3 + 2) * 64 + kk) * 128 + n];
    else if (term == 1)
        v = cw[((size_t)(b * 3 + 1) * 64 + kk) * 128 + n];
    else
        v = 2.f * cw[((size_t)(b * 3 + 2) * 64 + kk) * 128 + n];
    return v;
}
__global__ void prep_all(const float* __restrict__ cw,
                         const float* __restrict__ w1,
                         const float* __restrict__ w2) {
    int idx = blockIdx.x * 256 + threadIdx.x;     // 73728 total
    if (idx < 36864) {                            // g_Bc
        int b = idx / 12288, r2 = idx % 12288;
        int c = r2 >> 12, r = r2 & 4095;
        int k2 = r >> 7, t = r & 127;
        int gq = t >> 4, rem = t & 15, wn = rem >> 2, ni = rem & 3;
        int n = wn * 32 + ni * 8 + gq;
        float v0 = wc_val(cw, b, c * 64 + 2 * k2,     n);
        float v1 = wc_val(cw, b, c * 64 + 2 * k2 + 1, n);
        uint32_t hi, lo;
        pack2f(v0, v1, hi, lo);
        g_Bc[0][b][c][r] = hi;
        g_Bc[1][b][c][r] = lo;
    } else if (idx < 61440) {                     // g_B1
        int j = idx - 36864;
        int b = j / 8192, r2 = j % 8192;
        int c = r2 >> 12, r = r2 & 4095;
        int k2 = r >> 7, t = r & 127;
        int gq = t >> 4, rem = t & 15, wn = rem >> 2, ni = rem & 3;
        int n = wn * 32 + ni * 8 + gq;
        const float* W = w1 + (size_t)b * 16384 + (size_t)c * 64 * 128;
        uint32_t hi, lo;
        pack2f(W[(size_t)(2 * k2) * 128 + n], W[(size_t)(2 * k2 + 1) * 128 + n], hi, lo);
        g_B1[0][b][c][r] = hi;
        g_B1[1][b][c][r] = lo;
    } else if (idx < 73728) {                     // g_B2
        int j = idx - 61440;
        int b = j / 4096, r2 = j % 4096;
        int c = r2 >> 11, r = r2 & 2047;
        int k2 = r >> 6, t = r & 63;
        int gq = t >> 3, rem = t & 7, wn = rem >> 1, ni = rem & 1;
        int n = wn * 16 + ni * 8 + gq;
        const float* W = w2 + (size_t)b * 8192 + (size_t)c * 64 * 64;
        uint32_t hi, lo;
        pack2f(W[(size_t)(2 * k2) * 64 + n], W[(size_t)(2 * k2 + 1) * 64 + n], hi, lo);
        g_B2[0][b][c][r] = hi;
        g_B2[1][b][c][r] = lo;
    }
}

// ================== fused GEMM chain (mma.sync f16, A hi-only, B hi+lo) ==================
__device__ __forceinline__ uint32_t s2u(const void* p) {
    uint32_t a;
    asm("{ .reg .u64 t; cvta.to.shared.u64 t, %1; cvt.u32.u64 %0, t; }" : "=r"(a) : "l"(p));
    return a;
}
__device__ __forceinline__ void mma_f16(float* c, const uint32_t* a, const uint32_t* b) {
    asm volatile(
        "mma.sync.aligned.m16n8k16.row.col.f32.f16.f16.f32 "
        "{%0,%1,%2,%3}, {%4,%5,%6,%7}, {%8,%9}, {%0,%1,%2,%3};\n"
        : "+f"(c[0]), "+f"(c[1]), "+f"(c[2]), "+f"(c[3])
        : "r"(a[0]), "r"(a[1]), "r"(a[2]), "r"(a[3]), "r"(b[0]), "r"(b[1]));
}
#define LDSM4(r, a) \
    asm volatile("ldmatrix.sync.aligned.m8n8.x4.shared.b16 {%0,%1,%2,%3}, [%4];" \
        : "=r"((r)[0]), "=r"((r)[1]), "=r"((r)[2]), "=r"((r)[3]) : "r"(a))

// swish via tanh.approx.f32: v*sigmoid(v*spv)/1.1 = v*A*(1 + tanh(v*spv*0.5)), A=1/2.2
__device__ __forceinline__ float swish_t(float v, float sp2, float A) {
    float t;
    asm("tanh.approx.f32 %0, %1;" : "=f"(t) : "f"(v * sp2));
    float va = v * A;
    return fmaf(va, t, va);
}

constexpr int PAH = 136;                 // A tile pitch in halfs
constexpr uint32_t A0_OFF = 0;           // ping buffer
constexpr uint32_t A1_OFF = 34816;       // pong buffer (128*136*2)
constexpr int SMEM_FUSED = 69632;

// mma over one K=64 chunk (4 k16-steps); A hi-only via ldmatrix, B hi+lo via __ldg
template <int NI>
__device__ __forceinline__ void mma_chunk(
    uint32_t aLane, int colOffHalfs,
    const uint32_t* __restrict__ BH, const uint32_t* __restrict__ BL,
    int wn, int gq, int l4, float acc[4][NI][4])
{
    #pragma unroll
    for (int s = 0; s < 4; ++s) {
        const int k2a = 8 * s + l4, k2b = k2a + 4;
        uint32_t bh[NI][2], bl[NI][2];
        if constexpr (NI == 4) {
            const int base = gq * 16 + wn * 4;
            uint4 h0 = __ldg((const uint4*)(BH + k2a * 128 + base));
            uint4 h1 = __ldg((const uint4*)(BH + k2b * 128 + base));
            uint4 l0 = __ldg((const uint4*)(BL + k2a * 128 + base));
            uint4 l1 = __ldg((const uint4*)(BL + k2b * 128 + base));
            bh[0][0] = h0.x; bh[1][0] = h0.y; bh[2][0] = h0.z; bh[3][0] = h0.w;
            bh[0][1] = h1.x; bh[1][1] = h1.y; bh[2][1] = h1.z; bh[3][1] = h1.w;
            bl[0][0] = l0.x; bl[1][0] = l0.y; bl[2][0] = l0.z; bl[3][0] = l0.w;
            bl[0][1] = l1.x; bl[1][1] = l1.y; bl[2][1] = l1.z; bl[3][1] = l1.w;
        } else {
            const int base = gq * 8 + wn * 2;
            uint2 h0 = __ldg((const uint2*)(BH + k2a * 64 + base));
            uint2 h1 = __ldg((const uint2*)(BH + k2b * 64 + base));
            uint2 l0 = __ldg((const uint2*)(BL + k2a * 64 + base));
            uint2 l1 = __ldg((const uint2*)(BL + k2b * 64 + base));
            bh[0][0] = h0.x; bh[1][0] = h0.y;
            bh[0][1] = h1.x; bh[1][1] = h1.y;
            bl[0][0] = l0.x; bl[1][0] = l0.y;
            bl[0][1] = l1.x; bl[1][1] = l1.y;
        }
        const uint32_t aoff = (uint32_t)(colOffHalfs + s * 16) * 2;
        #pragma unroll
        for (int mi = 0; mi < 4; ++mi) {
            uint32_t ah[4];
            LDSM4(ah, aLane + aoff + mi * (16 * PAH * 2));
            #pragma unroll
            for (int ni = 0; ni < NI; ++ni) {
                mma_f16(acc[mi][ni], ah, bh[ni]);
                mma_f16(acc[mi][ni], ah, bl[ni]);
            }
        }
    }
}

// -------- fused per-block kernel --------
__global__ void __launch_bounds__(256, 2)
fused_block(int blk, int last,
            const float* __restrict__ b1, const float* __restrict__ b2,
            const float* __restrict__ cb, const float* __restrict__ betaPtr)
{
    extern __shared__ __align__(16) char smem[];
    const uint32_t sb = s2u(smem);

    const int tid  = threadIdx.x;
    const int warp = tid >> 5, lane = tid & 31;
    const int gq   = lane >> 2, l4 = lane & 3;
    const int wm   = warp >> 2, wn = warp & 3;    // 2 x 4 warp grid
    const int m0w  = wm * 64;
    const int mblk = blockIdx.x * 128;
    const float spv = log1pf(__expf(*betaPtr));
    const float sp2 = 0.5f * spv;
    const float Asw = 1.f / 2.2f;
    const int n0w4 = wn * 32;
    const int n0w2 = wn * 16;

    const uint32_t aLaneOff = (uint32_t)((m0w + (lane & 15)) * PAH + (lane >> 4) * 8) * 2;
    const uint32_t aLane0 = sb + A0_OFF + aLaneOff;
    const uint32_t aLane1 = sb + A1_OFF + aLaneOff;

    float acc[4][4][4];

    // ===== Stage 1: cheb, 3 chunks, ping-pong A buffers (A0, A1, A0) =====
    #pragma unroll
    for (int mi = 0; mi < 4; ++mi)
        #pragma unroll
        for (int ni = 0; ni < 4; ++ni)
            #pragma unroll
            for (int q = 0; q < 4; ++q) acc[mi][ni][q] = 0.f;

    #pragma unroll 1
    for (int ch = 0; ch < 3; ++ch) {
        const __half* srcA = (ch == 0) ? g_hh : (ch == 1) ? g_t1h : g_t2h;
        const uint32_t dstOff = (ch == 1) ? A1_OFF : A0_OFF;
        for (int i = tid; i < 128 * 8; i += 256) {
            int m = i >> 3, q = i & 7;
            uint4 v = *(const uint4*)(srcA + (size_t)(mblk + m) * 64 + q * 8);
            *(uint4*)(smem + dstOff + (m * PAH + q * 8) * 2) = v;
        }
        __syncthreads();
        mma_chunk<4>(((ch == 1) ? aLane1 : aLane0), 0,
                     &g_Bc[0][blk][ch][0], &g_Bc[1][blk][ch][0],
                     wn, gq, l4, acc);
    }

    // ===== Epilogue 1: bias+swish(tanh) -> fp16 into A1 =====
    #pragma unroll
    for (int mi = 0; mi < 4; ++mi) {
        int r0 = m0w + mi * 16 + gq;
        #pragma unroll
        for (int ni = 0; ni < 4; ++ni) {
            int c = n0w4 + ni * 8 + 2 * l4;
            float bb0 = __ldg(cb + c), bb1 = __ldg(cb + c + 1);
            float v00 = swish_t(acc[mi][ni][0] + bb0, sp2, Asw);
            float v01 = swish_t(acc[mi][ni][1] + bb1, sp2, Asw);
            float v10 = swish_t(acc[mi][ni][2] + bb0, sp2, Asw);
            float v11 = swish_t(acc[mi][ni][3] + bb1, sp2, Asw);
            *(__half2*)(smem + A1_OFF + (r0 * PAH + c) * 2)       = __floats2half2_rn(v00, v01);
            *(__half2*)(smem + A1_OFF + ((r0 + 8) * PAH + c) * 2) = __floats2half2_rn(v10, v11);
        }
    }
    __syncthreads();

    // ===== Stage 2: MLP1 (K=128 from A1, 2-term) =====
    #pragma unroll
    for (int mi = 0; mi < 4; ++mi)
        #pragma unroll
        for (int ni = 0; ni < 4; ++ni)
            #pragma unroll
            for (int q = 0; q < 4; ++q) acc[mi][ni][q] = 0.f;

    mma_chunk<4>(aLane1, 0,  &g_B1[0][blk][0][0], &g_B1[1][blk][0][0], wn, gq, l4, acc);
    mma_chunk<4>(aLane1, 64, &g_B1[0][blk][1][0], &g_B1[1][blk][1][0], wn, gq, l4, acc);

    // ===== Epilogue 2 -> A0 =====
    #pragma unroll
    for (int mi = 0; mi < 4; ++mi) {
        int r0 = m0w + mi * 16 + gq;
        #pragma unroll
        for (int ni = 0; ni < 4; ++ni) {
            int c = n0w4 + ni * 8 + 2 * l4;
            float bb0 = __ldg(b1 + c), bb1 = __ldg(b1 + c + 1);
            float v00 = swish_t(acc[mi][ni][0] + bb0, sp2, Asw);
            float v01 = swish_t(acc[mi][ni][1] + bb1, sp2, Asw);
            float v10 = swish_t(acc[mi][ni][2] + bb0, sp2, Asw);
            float v11 = swish_t(acc[mi][ni][3] + bb1, sp2, Asw);
            *(__half2*)(smem + A0_OFF + (r0 * PAH + c) * 2)       = __floats2half2_rn(v00, v01);
            *(__half2*)(smem + A0_OFF + ((r0 + 8) * PAH + c) * 2) = __floats2half2_rn(v10, v11);
        }
    }
    __syncthreads();

    // ===== Stage 3: MLP2 (N=64 from A0, 2-term) + residual =====
    float acc3[4][2][4];
    #pragma unroll
    for (int mi = 0; mi < 4; ++mi)
        #pragma unroll
        for (int ni = 0; ni < 2; ++ni)
            #pragma unroll
            for (int q = 0; q < 4; ++q) acc3[mi][ni][q] = 0.f;

    mma_chunk<2>(aLane0, 0,  &g_B2[0][blk][0][0], &g_B2[1][blk][0][0], wn, gq, l4, acc3);
    mma_chunk<2>(aLane0, 64, &g_B2[0][blk][1][0], &g_B2[1][blk][1][0], wn, gq, l4, acc3);

    // ===== Final epilogue: h += Fx (skip fp16 shadow on last block) =====
    #pragma unroll
    for (int mi = 0; mi < 4; ++mi) {
        int r0 = mblk + m0w + mi * 16 + gq;
        #pragma unroll
        for (int ni = 0; ni < 2; ++ni) {
            int c = n0w2 + ni * 8 + 2 * l4;
            float bb0 = __ldg(b2 + c), bb1 = __ldg(b2 + c + 1);
            float2 cur0 = *(float2*)(g_h + (size_t)r0 * 64 + c);
            float2 cur1 = *(float2*)(g_h + (size_t)(r0 + 8) * 64 + c);
            cur0.x += acc3[mi][ni][0] + bb0;
            cur0.y += acc3[mi][ni][1] + bb1;
            cur1.x += acc3[mi][ni][2] + bb0;
            cur1.y += acc3[mi][ni][3] + bb1;
            *(float2*)(g_h + (size_t)r0 * 64 + c)       = cur0;
            *(float2*)(g_h + (size_t)(r0 + 8) * 64 + c) = cur1;
            if (!last) {
                *(__half2*)(g_hh + (size_t)r0 * 64 + c)       = __floats2half2_rn(cur0.x, cur0.y);
                *(__half2*)(g_hh + (size_t)(r0 + 8) * 64 + c) = __floats2half2_rn(cur1.x, cur1.y);
            }
        }
    }
}

// -------- host launcher --------
extern "C" void kernel_launch(void* const* d_in, const int* in_sizes, int n_in,
                              void* d_out, int out_size) {
    const float* x      = (const float*)d_in[0];
    const int*   ei     = (const int*)  d_in[1];
    const float* ew     = (const float*)d_in[2];
    const float* cheb_w = (const float*)d_in[3];
    const float* cheb_b = (const float*)d_in[4];
    const float* beta   = (const float*)d_in[5];
    const float* w1     = (const float*)d_in[6];
    const float* b1     = (const float*)d_in[7];
    const float* w2     = (const float*)d_in[8];
    const float* b2     = (const float*)d_in[9];
    float* out = (float*)d_out;
    const int* src = ei;
    const int* dst = ei + Ee;

    cudaFuncSetAttribute((const void*)fused_block,
                         cudaFuncAttributeMaxDynamicSharedMemorySize, SMEM_FUSED);

    const int EB = (Ee + 255) / 256;
    const int NBk = (Nn + 255) / 256;

    zero_deg_cnt<<<NBk, 256>>>();
    deg_kernel<<<EB, 256>>>(src, ew);
    dinv_kernel<<<NBk, 256>>>();
    w_count_kernel<<<EB, 256>>>(src, dst, ew);
    scan_kernel<<<1, 1024>>>();
    fill_kernel<<<EB, 256>>>(src, dst);
    prep_all<<<288, 256>>>(cheb_w, w1, w2);

    t_in_kernel<<<Nn, 256>>>((const float4*)x);

    for (int b = 0; b < NBlk; ++b) {
        spmm16_kernel<0><<<Nn, 256>>>();
        spmm16_kernel<1><<<Nn, 256>>>();
        fused_block<<<2500, 256, SMEM_FUSED>>>(
            b, (b == NBlk - 1) ? 1 : 0,
            b1 + b * 128, b2 + b * 64, cheb_b + b * 128, beta + b);
    }

    t_out_kernel<<<Nn, 256>>>((float4*)out);
}

// round 11
// speedup vs baseline: 3.3759x; 1.1135x over previous
#include <cuda_runtime.h>
#include <cuda_fp16.h>
#include <stdint.h>
#include <math.h>

// Problem constants
constexpr int Bc   = 16;
constexpr int Nn   = 20000;
constexpr int Cc   = 64;
constexpr int Ee   = 640000;
constexpr int NBlk = 3;
constexpr int ROWS = Nn * Bc;          // 320000
constexpr int RowF = Bc * Cc;          // 1024 halfs per node row ([N][B][C])
constexpr int RowF4 = RowF / 4;

// -------- device scratch --------
__device__ __align__(16) float  g_h  [ROWS * Cc];
__device__ __align__(16) __half g_hh [ROWS * Cc];
__device__ __align__(16) __half g_t1h[ROWS * Cc];
__device__ __align__(16) __half g_t2h[ROWS * Cc];
__device__ float g_deg [Nn];
__device__ float g_dinv[Nn];
__device__ float g_w   [Ee];
__device__ int   g_off [Nn + 1];
__device__ int   g_cnt [Nn];
__device__ int   g_csrc[Ee];
__device__ float g_csw [Ee];
// Pre-packed fp16 B operands (hi only), LANE-VECTORIZED fragment layout:
// N=128: word r = k2*128 + gq*16 + wn*4 + ni  (n = wn*32 + ni*8 + gq)
// N=64 : word r = k2*64  + gq*8  + wn*2 + ni  (n = wn*16 + ni*8 + gq)
__device__ __align__(16) uint32_t g_Bc[3][3][32 * 128];   // [block][chunk]
__device__ __align__(16) uint32_t g_B1[3][2][32 * 128];
__device__ __align__(16) uint32_t g_B2[3][2][32 * 64];

// -------- small setup kernels --------
__global__ void zero_deg_cnt() {
    int i = blockIdx.x * blockDim.x + threadIdx.x;
    if (i < Nn) { g_deg[i] = 0.f; g_cnt[i] = 0; }
}
__global__ void deg_kernel(const int* __restrict__ src, const float* __restrict__ ew) {
    int e = blockIdx.x * blockDim.x + threadIdx.x;
    if (e < Ee) atomicAdd(&g_deg[src[e]], ew[e]);
}
__global__ void dinv_kernel() {
    int i = blockIdx.x * blockDim.x + threadIdx.x;
    if (i < Nn) {
        float d = g_deg[i];
        g_dinv[i] = (d > 0.f) ? rsqrtf(fmaxf(d, 1e-12f)) : 0.f;
    }
}
__global__ void w_count_kernel(const int* __restrict__ src, const int* __restrict__ dst,
                               const float* __restrict__ ew) {
    int e = blockIdx.x * blockDim.x + threadIdx.x;
    if (e < Ee) {
        int s = src[e], d = dst[e];
        g_w[e] = -g_dinv[s] * ew[e] * g_dinv[d];
        atomicAdd(&g_cnt[d], 1);
    }
}
__global__ void scan_kernel() {
    __shared__ int warp_sums[32];
    __shared__ int s_carry;
    int t = threadIdx.x;
    if (t == 0) s_carry = 0;
    __syncthreads();
    for (int base = 0; base < Nn; base += 1024) {
        int v = (base + t < Nn) ? g_cnt[base + t] : 0;
        if (base + t < Nn) g_cnt[base + t] = 0;
        int x = v;
        #pragma unroll
        for (int d = 1; d < 32; d <<= 1) {
            int y = __shfl_up_sync(0xFFFFFFFFu, x, d);
            if ((t & 31) >= d) x += y;
        }
        if ((t & 31) == 31) warp_sums[t >> 5] = x;
        __syncthreads();
        if (t < 32) {
            int y = warp_sums[t];
            #pragma unroll
            for (int d = 1; d < 32; d <<= 1) {
                int z = __shfl_up_sync(0xFFFFFFFFu, y, d);
                if (t >= d) y += z;
            }
            warp_sums[t] = y;
        }
        __syncthreads();
        int excl = s_carry + (x - v) + ((t >= 32) ? warp_sums[(t >> 5) - 1] : 0);
        if (base + t < Nn) g_off[base + t] = excl;
        __syncthreads();
        if (t == 0) s_carry += warp_sums[31];
        __syncthreads();
    }
    if (t == 0) g_off[Nn] = s_carry;
}
__global__ void fill_kernel(const int* __restrict__ src, const int* __restrict__ dst) {
    int e = blockIdx.x * blockDim.x + threadIdx.x;
    if (e < Ee) {
        int d = dst[e];
        int pos = g_off[d] + atomicAdd(&g_cnt[d], 1);
        g_csrc[pos] = src[e];
        g_csw[pos]  = g_w[e];
    }
}

// -------- transposes --------
__global__ void t_in_kernel(const float4* __restrict__ x4) {
    int idx = blockIdx.x * 256 + threadIdx.x;
    int b = idx / (Nn * 16);
    int r = idx % (Nn * 16);
    int n = r >> 4, c4 = r & 15;
    float4 v = x4[idx];
    int o4 = n * RowF4 + b * 16 + c4;
    ((float4*)g_h)[o4] = v;
    ((__half2*)g_hh)[o4 * 2]     = __floats2half2_rn(v.x, v.y);
    ((__half2*)g_hh)[o4 * 2 + 1] = __floats2half2_rn(v.z, v.w);
}
__global__ void t_out_kernel(float4* __restrict__ o4) {
    int idx = blockIdx.x * 256 + threadIdx.x;
    int b = idx / (Nn * 16);
    int r = idx % (Nn * 16);
    int n = r >> 4, c4 = r & 15;
    o4[idx] = ((const float4*)g_h)[n * RowF4 + b * 16 + c4];
}

// -------- SpMM fp16, dual edge streams (BW-bound, leave alone) --------
template <int PHASE>
__global__ void __launch_bounds__(256) spmm16_kernel() {
    const __half* __restrict__ in = (PHASE == 0) ? g_hh : g_t1h;
    __half* __restrict__ out      = (PHASE == 0) ? g_t1h : g_t2h;
    __shared__ float red[8 * 128];
    int n = blockIdx.x;
    int stream = threadIdx.x >> 7;
    int t = threadIdx.x & 127;
    int e0 = g_off[n], e1 = g_off[n + 1];
    float acc[8];
    #pragma unroll
    for (int q = 0; q < 8; ++q) acc[q] = 0.f;
    #pragma unroll 4
    for (int e = e0 + stream; e < e1; e += 2) {
        int   s  = __ldg(&g_csrc[e]);
        float wv = __ldg(&g_csw[e]);
        uint4 raw = __ldg((const uint4*)(in + (size_t)s * RowF) + t);
        const __half2* hp = (const __half2*)&raw;
        #pragma unroll
        for (int p = 0; p < 4; ++p) {
            float2 f = __half22float2(hp[p]);
            acc[2 * p]     = fmaf(wv, f.x, acc[2 * p]);
            acc[2 * p + 1] = fmaf(wv, f.y, acc[2 * p + 1]);
        }
    }
    if (stream) {
        #pragma unroll
        for (int q = 0; q < 8; ++q) red[q * 128 + t] = acc[q];
    }
    __syncthreads();
    if (!stream) {
        uint4 res;
        __half2* rp = (__half2*)&res;
        #pragma unroll
        for (int p = 0; p < 4; ++p)
            rp[p] = __floats2half2_rn(acc[2 * p] + red[(2 * p) * 128 + t],
                                      acc[2 * p + 1] + red[(2 * p + 1) * 128 + t]);
        ((uint4*)(out + (size_t)n * RowF))[t] = res;
    }
}

// -------- merged weight prep (hi only) --------
__device__ __forceinline__ uint32_t pack_f2h(float v0, float v1) {
    __half2 t = __floats2half2_rn(v0, v1);
    return *(uint32_t*)&t;
}
// cheb combined weight value: row rg in [0,192) of [W0-W2 | W1 | 2W2], col n
__device__ __forceinline__ float wc_val(const float* __restrict__ cw, int b, int rg, int n) {
    int term = rg >> 6, kk = rg & 63;
    float v;
    if (term == 0)
        v = cw[((size_t)(b * 3 + 0) * 64 + kk) * 128 + n] -
            cw[((size_t)(b * 3 + 2) * 64 + kk) * 128 + n];
    else if (term == 1)
        v = cw[((size_t)(b * 3 + 1) * 64 + kk) * 128 + n];
    else
        v = 2.f * cw[((size_t)(b * 3 + 2) * 64 + kk) * 128 + n];
    return v;
}
__global__ void prep_all(const float* __restrict__ cw,
                         const float* __restrict__ w1,
                         const float* __restrict__ w2) {
    int idx = blockIdx.x * 256 + threadIdx.x;     // 73728 total
    if (idx < 36864) {                            // g_Bc
        int b = idx / 12288, r2 = idx % 12288;
        int c = r2 >> 12, r = r2 & 4095;
        int k2 = r >> 7, t = r & 127;
        int gq = t >> 4, rem = t & 15, wn = rem >> 2, ni = rem & 3;
        int n = wn * 32 + ni * 8 + gq;
        float v0 = wc_val(cw, b, c * 64 + 2 * k2,     n);
        float v1 = wc_val(cw, b, c * 64 + 2 * k2 + 1, n);
        g_Bc[b][c][r] = pack_f2h(v0, v1);
    } else if (idx < 61440) {                     // g_B1
        int j = idx - 36864;
        int b = j / 8192, r2 = j % 8192;
        int c = r2 >> 12, r = r2 & 4095;
        int k2 = r >> 7, t = r & 127;
        int gq = t >> 4, rem = t & 15, wn = rem >> 2, ni = rem & 3;
        int n = wn * 32 + ni * 8 + gq;
        const float* W = w1 + (size_t)b * 16384 + (size_t)c * 64 * 128;
        g_B1[b][c][r] = pack_f2h(W[(size_t)(2 * k2) * 128 + n],
                                 W[(size_t)(2 * k2 + 1) * 128 + n]);
    } else if (idx < 73728) {                     // g_B2
        int j = idx - 61440;
        int b = j / 4096, r2 = j % 4096;
        int c = r2 >> 11, r = r2 & 2047;
        int k2 = r >> 6, t = r & 63;
        int gq = t >> 3, rem = t & 7, wn = rem >> 1, ni = rem & 1;
        int n = wn * 16 + ni * 8 + gq;
        const float* W = w2 + (size_t)b * 8192 + (size_t)c * 64 * 64;
        g_B2[b][c][r] = pack_f2h(W[(size_t)(2 * k2) * 64 + n],
                                 W[(size_t)(2 * k2 + 1) * 64 + n]);
    }
}

// ================== fused GEMM chain (mma.sync f16, single-term) ==================
__device__ __forceinline__ uint32_t s2u(const void* p) {
    uint32_t a;
    asm("{ .reg .u64 t; cvta.to.shared.u64 t, %1; cvt.u32.u64 %0, t; }" : "=r"(a) : "l"(p));
    return a;
}
__device__ __forceinline__ void mma_f16(float* c, const uint32_t* a, const uint32_t* b) {
    asm volatile(
        "mma.sync.aligned.m16n8k16.row.col.f32.f16.f16.f32 "
        "{%0,%1,%2,%3}, {%4,%5,%6,%7}, {%8,%9}, {%0,%1,%2,%3};\n"
        : "+f"(c[0]), "+f"(c[1]), "+f"(c[2]), "+f"(c[3])
        : "r"(a[0]), "r"(a[1]), "r"(a[2]), "r"(a[3]), "r"(b[0]), "r"(b[1]));
}
#define LDSM4(r, a) \
    asm volatile("ldmatrix.sync.aligned.m8n8.x4.shared.b16 {%0,%1,%2,%3}, [%4];" \
        : "=r"((r)[0]), "=r"((r)[1]), "=r"((r)[2]), "=r"((r)[3]) : "r"(a))

// swish via tanh.approx.f32: v*sigmoid(v*spv)/1.1 = v*A*(1 + tanh(v*spv*0.5)), A=1/2.2
__device__ __forceinline__ float swish_t(float v, float sp2, float A) {
    float t;
    asm("tanh.approx.f32 %0, %1;" : "=f"(t) : "f"(v * sp2));
    float va = v * A;
    return fmaf(va, t, va);
}

constexpr int PAH = 136;                 // A tile pitch in halfs
constexpr uint32_t A0_OFF = 0;           // ping buffer
constexpr uint32_t A1_OFF = 34816;       // pong buffer (128*136*2)
constexpr int SMEM_FUSED = 69632;

// mma over one K=64 chunk (4 k16-steps); A via ldmatrix, B (hi-only) via __ldg
template <int NI>
__device__ __forceinline__ void mma_chunk(
    uint32_t aLane, int colOffHalfs,
    const uint32_t* __restrict__ BH,
    int wn, int gq, int l4, float acc[4][NI][4])
{
    #pragma unroll
    for (int s = 0; s < 4; ++s) {
        const int k2a = 8 * s + l4, k2b = k2a + 4;
        uint32_t bh[NI][2];
        if constexpr (NI == 4) {
            const int base = gq * 16 + wn * 4;
            uint4 h0 = __ldg((const uint4*)(BH + k2a * 128 + base));
            uint4 h1 = __ldg((const uint4*)(BH + k2b * 128 + base));
            bh[0][0] = h0.x; bh[1][0] = h0.y; bh[2][0] = h0.z; bh[3][0] = h0.w;
            bh[0][1] = h1.x; bh[1][1] = h1.y; bh[2][1] = h1.z; bh[3][1] = h1.w;
        } else {
            const int base = gq * 8 + wn * 2;
            uint2 h0 = __ldg((const uint2*)(BH + k2a * 64 + base));
            uint2 h1 = __ldg((const uint2*)(BH + k2b * 64 + base));
            bh[0][0] = h0.x; bh[1][0] = h0.y;
            bh[0][1] = h1.x; bh[1][1] = h1.y;
        }
        const uint32_t aoff = (uint32_t)(colOffHalfs + s * 16) * 2;
        #pragma unroll
        for (int mi = 0; mi < 4; ++mi) {
            uint32_t ah[4];
            LDSM4(ah, aLane + aoff + mi * (16 * PAH * 2));
            #pragma unroll
            for (int ni = 0; ni < NI; ++ni)
                mma_f16(acc[mi][ni], ah, bh[ni]);
        }
    }
}

// -------- fused per-block kernel --------
__global__ void __launch_bounds__(256, 2)
fused_block(int blk, int last,
            const float* __restrict__ b1, const float* __restrict__ b2,
            const float* __restrict__ cb, const float* __restrict__ betaPtr)
{
    extern __shared__ __align__(16) char smem[];
    const uint32_t sb = s2u(smem);

    const int tid  = threadIdx.x;
    const int warp = tid >> 5, lane = tid & 31;
    const int gq   = lane >> 2, l4 = lane & 3;
    const int wm   = warp >> 2, wn = warp & 3;    // 2 x 4 warp grid
    const int m0w  = wm * 64;
    const int mblk = blockIdx.x * 128;
    const float spv = log1pf(__expf(*betaPtr));
    const float sp2 = 0.5f * spv;
    const float Asw = 1.f / 2.2f;
    const int n0w4 = wn * 32;
    const int n0w2 = wn * 16;

    const uint32_t aLaneOff = (uint32_t)((m0w + (lane & 15)) * PAH + (lane >> 4) * 8) * 2;
    const uint32_t aLane0 = sb + A0_OFF + aLaneOff;
    const uint32_t aLane1 = sb + A1_OFF + aLaneOff;

    float acc[4][4][4];

    // ===== Stage 1: cheb, 3 chunks, ping-pong A buffers (A0, A1, A0) =====
    #pragma unroll
    for (int mi = 0; mi < 4; ++mi)
        #pragma unroll
        for (int ni = 0; ni < 4; ++ni)
            #pragma unroll
            for (int q = 0; q < 4; ++q) acc[mi][ni][q] = 0.f;

    #pragma unroll 1
    for (int ch = 0; ch < 3; ++ch) {
        const __half* srcA = (ch == 0) ? g_hh : (ch == 1) ? g_t1h : g_t2h;
        const uint32_t dstOff = (ch == 1) ? A1_OFF : A0_OFF;
        for (int i = tid; i < 128 * 8; i += 256) {
            int m = i >> 3, q = i & 7;
            uint4 v = *(const uint4*)(srcA + (size_t)(mblk + m) * 64 + q * 8);
            *(uint4*)(smem + dstOff + (m * PAH + q * 8) * 2) = v;
        }
        __syncthreads();
        mma_chunk<4>(((ch == 1) ? aLane1 : aLane0), 0,
                     &g_Bc[blk][ch][0], wn, gq, l4, acc);
    }

    // ===== Epilogue 1: bias+swish(tanh) -> fp16 into A1 =====
    #pragma unroll
    for (int mi = 0; mi < 4; ++mi) {
        int r0 = m0w + mi * 16 + gq;
        #pragma unroll
        for (int ni = 0; ni < 4; ++ni) {
            int c = n0w4 + ni * 8 + 2 * l4;
            float bb0 = __ldg(cb + c), bb1 = __ldg(cb + c + 1);
            float v00 = swish_t(acc[mi][ni][0] + bb0, sp2, Asw);
            float v01 = swish_t(acc[mi][ni][1] + bb1, sp2, Asw);
            float v10 = swish_t(acc[mi][ni][2] + bb0, sp2, Asw);
            float v11 = swish_t(acc[mi][ni][3] + bb1, sp2, Asw);
            *(__half2*)(smem + A1_OFF + (r0 * PAH + c) * 2)       = __floats2half2_rn(v00, v01);
            *(__half2*)(smem + A1_OFF + ((r0 + 8) * PAH + c) * 2) = __floats2half2_rn(v10, v11);
        }
    }
    __syncthreads();

    // ===== Stage 2: MLP1 (K=128 from A1) =====
    #pragma unroll
    for (int mi = 0; mi < 4; ++mi)
        #pragma unroll
        for (int ni = 0; ni < 4; ++ni)
            #pragma unroll
            for (int q = 0; q < 4; ++q) acc[mi][ni][q] = 0.f;

    mma_chunk<4>(aLane1, 0,  &g_B1[blk][0][0], wn, gq, l4, acc);
    mma_chunk<4>(aLane1, 64, &g_B1[blk][1][0], wn, gq, l4, acc);

    // ===== Epilogue 2 -> A0 =====
    #pragma unroll
    for (int mi = 0; mi < 4; ++mi) {
        int r0 = m0w + mi * 16 + gq;
        #pragma unroll
        for (int ni = 0; ni < 4; ++ni) {
            int c = n0w4 + ni * 8 + 2 * l4;
            float bb0 = __ldg(b1 + c), bb1 = __ldg(b1 + c + 1);
            float v00 = swish_t(acc[mi][ni][0] + bb0, sp2, Asw);
            float v01 = swish_t(acc[mi][ni][1] + bb1, sp2, Asw);
            float v10 = swish_t(acc[mi][ni][2] + bb0, sp2, Asw);
            float v11 = swish_t(acc[mi][ni][3] + bb1, sp2, Asw);
            *(__half2*)(smem + A0_OFF + (r0 * PAH + c) * 2)       = __floats2half2_rn(v00, v01);
            *(__half2*)(smem + A0_OFF + ((r0 + 8) * PAH + c) * 2) = __floats2half2_rn(v10, v11);
        }
    }
    __syncthreads();

    // ===== Stage 3: MLP2 (N=64 from A0) + residual =====
    float acc3[4][2][4];
    #pragma unroll
    for (int mi = 0; mi < 4; ++mi)
        #pragma unroll
        for (int ni = 0; ni < 2; ++ni)
            #pragma unroll
            for (int q = 0; q < 4; ++q) acc3[mi][ni][q] = 0.f;

    mma_chunk<2>(aLane0, 0,  &g_B2[blk][0][0], wn, gq, l4, acc3);
    mma_chunk<2>(aLane0, 64, &g_B2[blk][1][0], wn, gq, l4, acc3);

    // ===== Final epilogue: h += Fx (skip fp16 shadow on last block) =====
    #pragma unroll
    for (int mi = 0; mi < 4; ++mi) {
        int r0 = mblk + m0w + mi * 16 + gq;
        #pragma unroll
        for (int ni = 0; ni < 2; ++ni) {
            int c = n0w2 + ni * 8 + 2 * l4;
            float bb0 = __ldg(b2 + c), bb1 = __ldg(b2 + c + 1);
            float2 cur0 = *(float2*)(g_h + (size_t)r0 * 64 + c);
            float2 cur1 = *(float2*)(g_h + (size_t)(r0 + 8) * 64 + c);
            cur0.x += acc3[mi][ni][0] + bb0;
            cur0.y += acc3[mi][ni][1] + bb1;
            cur1.x += acc3[mi][ni][2] + bb0;
            cur1.y += acc3[mi][ni][3] + bb1;
            *(float2*)(g_h + (size_t)r0 * 64 + c)       = cur0;
            *(float2*)(g_h + (size_t)(r0 + 8) * 64 + c) = cur1;
            if (!last) {
                *(__half2*)(g_hh + (size_t)r0 * 64 + c)       = __floats2half2_rn(cur0.x, cur0.y);
                *(__half2*)(g_hh + (size_t)(r0 + 8) * 64 + c) = __floats2half2_rn(cur1.x, cur1.y);
            }
        }
    }
}

// -------- host launcher --------
extern "C" void kernel_launch(void* const* d_in, const int* in_sizes, int n_in,
                              void* d_out, int out_size) {
    const float* x      = (const float*)d_in[0];
    const int*   ei     = (const int*)  d_in[1];
    const float* ew     = (const float*)d_in[2];
    const float* cheb_w = (const float*)d_in[3];
    const float* cheb_b = (const float*)d_in[4];
    const float* beta   = (const float*)d_in[5];
    const float* w1     = (const float*)d_in[6];
    const float* b1     = (const float*)d_in[7];
    const float* w2     = (const float*)d_in[8];
    const float* b2     = (const float*)d_in[9];
    float* out = (float*)d_out;
    const int* src = ei;
    const int* dst = ei + Ee;

    cudaFuncSetAttribute((const void*)fused_block,
                         cudaFuncAttributeMaxDynamicSharedMemorySize, SMEM_FUSED);

    const int EB = (Ee + 255) / 256;
    const int NBk = (Nn + 255) / 256;

    zero_deg_cnt<<<NBk, 256>>>();
    deg_kernel<<<EB, 256>>>(src, ew);
    dinv_kernel<<<NBk, 256>>>();
    w_count_kernel<<<EB, 256>>>(src, dst, ew);
    scan_kernel<<<1, 1024>>>();
    fill_kernel<<<EB, 256>>>(src, dst);
    prep_all<<<288, 256>>>(cheb_w, w1, w2);

    t_in_kernel<<<Nn, 256>>>((const float4*)x);

    for (int b = 0; b < NBlk; ++b) {
        spmm16_kernel<0><<<Nn, 256>>>();
        spmm16_kernel<1><<<Nn, 256>>>();
        fused_block<<<2500, 256, SMEM_FUSED>>>(
            b, (b == NBlk - 1) ? 1 : 0,
            b1 + b * 128, b2 + b * 64, cheb_b + b * 128, beta + b);
    }

    t_out_kernel<<<Nn, 256>>>((float4*)out);
}

// round 12
// speedup vs baseline: 3.3961x; 1.0060x over previous
#include <cuda_runtime.h>
#include <cuda_fp16.h>
#include <stdint.h>
#include <math.h>

// Problem constants
constexpr int Bc   = 16;
constexpr int Nn   = 20000;
constexpr int Cc   = 64;
constexpr int Ee   = 640000;
constexpr int NBlk = 3;
constexpr int ROWS = Nn * Bc;          // 320000
constexpr int RowF = Bc * Cc;          // 1024 halfs per node row ([N][B][C])
constexpr int RowF4 = RowF / 4;

// -------- device scratch --------
__device__ __align__(16) float  g_h  [ROWS * Cc];
__device__ __align__(16) __half g_hh [ROWS * Cc];
__device__ __align__(16) __half g_t1h[ROWS * Cc];
__device__ __align__(16) __half g_t2h[ROWS * Cc];
__device__ float g_deg [Nn];
__device__ float g_dinv[Nn];
__device__ float g_w   [Ee];
__device__ int   g_off [Nn + 1];
__device__ int   g_cnt [Nn];
__device__ int   g_csrc[Ee];
__device__ float g_csw [Ee];
// Pre-packed fp16 B operands (hi only), LANE-VECTORIZED fragment layout:
// N=128: word r = k2*128 + gq*16 + wn*4 + ni  (n = wn*32 + ni*8 + gq)
// N=64 : word r = k2*64  + gq*8  + wn*2 + ni  (n = wn*16 + ni*8 + gq)
__device__ __align__(16) uint32_t g_Bc[3][3][32 * 128];   // [block][chunk]
__device__ __align__(16) uint32_t g_B1[3][2][32 * 128];
__device__ __align__(16) uint32_t g_B2[3][2][32 * 64];

// -------- small setup kernels --------
__global__ void zero_deg_cnt() {
    int i = blockIdx.x * blockDim.x + threadIdx.x;
    if (i < Nn) { g_deg[i] = 0.f; g_cnt[i] = 0; }
}
__global__ void deg_kernel(const int* __restrict__ src, const float* __restrict__ ew) {
    int e = blockIdx.x * blockDim.x + threadIdx.x;
    if (e < Ee) atomicAdd(&g_deg[src[e]], ew[e]);
}
__global__ void dinv_kernel() {
    int i = blockIdx.x * blockDim.x + threadIdx.x;
    if (i < Nn) {
        float d = g_deg[i];
        g_dinv[i] = (d > 0.f) ? rsqrtf(fmaxf(d, 1e-12f)) : 0.f;
    }
}
__global__ void w_count_kernel(const int* __restrict__ src, const int* __restrict__ dst,
                               const float* __restrict__ ew) {
    int e = blockIdx.x * blockDim.x + threadIdx.x;
    if (e < Ee) {
        int s = src[e], d = dst[e];
        g_w[e] = -g_dinv[s] * ew[e] * g_dinv[d];
        atomicAdd(&g_cnt[d], 1);
    }
}
__global__ void scan_kernel() {
    __shared__ int warp_sums[32];
    __shared__ int s_carry;
    int t = threadIdx.x;
    if (t == 0) s_carry = 0;
    __syncthreads();
    for (int base = 0; base < Nn; base += 1024) {
        int v = (base + t < Nn) ? g_cnt[base + t] : 0;
        if (base + t < Nn) g_cnt[base + t] = 0;
        int x = v;
        #pragma unroll
        for (int d = 1; d < 32; d <<= 1) {
            int y = __shfl_up_sync(0xFFFFFFFFu, x, d);
            if ((t & 31) >= d) x += y;
        }
        if ((t & 31) == 31) warp_sums[t >> 5] = x;
        __syncthreads();
        if (t < 32) {
            int y = warp_sums[t];
            #pragma unroll
            for (int d = 1; d < 32; d <<= 1) {
                int z = __shfl_up_sync(0xFFFFFFFFu, y, d);
                if (t >= d) y += z;
            }
            warp_sums[t] = y;
        }
        __syncthreads();
        int excl = s_carry + (x - v) + ((t >= 32) ? warp_sums[(t >> 5) - 1] : 0);
        if (base + t < Nn) g_off[base + t] = excl;
        __syncthreads();
        if (t == 0) s_carry += warp_sums[31];
        __syncthreads();
    }
    if (t == 0) g_off[Nn] = s_carry;
}
__global__ void fill_kernel(const int* __restrict__ src, const int* __restrict__ dst) {
    int e = blockIdx.x * blockDim.x + threadIdx.x;
    if (e < Ee) {
        int d = dst[e];
        int pos = g_off[d] + atomicAdd(&g_cnt[d], 1);
        g_csrc[pos] = src[e];
        g_csw[pos]  = g_w[e];
    }
}

// -------- transposes --------
__global__ void t_in_kernel(const float4* __restrict__ x4) {
    int idx = blockIdx.x * 256 + threadIdx.x;
    int b = idx / (Nn * 16);
    int r = idx % (Nn * 16);
    int n = r >> 4, c4 = r & 15;
    float4 v = x4[idx];
    int o4 = n * RowF4 + b * 16 + c4;
    ((float4*)g_h)[o4] = v;
    ((__half2*)g_hh)[o4 * 2]     = __floats2half2_rn(v.x, v.y);
    ((__half2*)g_hh)[o4 * 2 + 1] = __floats2half2_rn(v.z, v.w);
}
__global__ void t_out_kernel(float4* __restrict__ o4) {
    int idx = blockIdx.x * 256 + threadIdx.x;
    int b = idx / (Nn * 16);
    int r = idx % (Nn * 16);
    int n = r >> 4, c4 = r & 15;
    o4[idx] = ((const float4*)g_h)[n * RowF4 + b * 16 + c4];
}

// -------- SpMM fp16, dual edge streams (BW-bound, at LTS roofline) --------
template <int PHASE>
__global__ void __launch_bounds__(256) spmm16_kernel() {
    const __half* __restrict__ in = (PHASE == 0) ? g_hh : g_t1h;
    __half* __restrict__ out      = (PHASE == 0) ? g_t1h : g_t2h;
    __shared__ float red[8 * 128];
    int n = blockIdx.x;
    int stream = threadIdx.x >> 7;
    int t = threadIdx.x & 127;
    int e0 = g_off[n], e1 = g_off[n + 1];
    float acc[8];
    #pragma unroll
    for (int q = 0; q < 8; ++q) acc[q] = 0.f;
    #pragma unroll 4
    for (int e = e0 + stream; e < e1; e += 2) {
        int   s  = __ldg(&g_csrc[e]);
        float wv = __ldg(&g_csw[e]);
        uint4 raw = __ldg((const uint4*)(in + (size_t)s * RowF) + t);
        const __half2* hp = (const __half2*)&raw;
        #pragma unroll
        for (int p = 0; p < 4; ++p) {
            float2 f = __half22float2(hp[p]);
            acc[2 * p]     = fmaf(wv, f.x, acc[2 * p]);
            acc[2 * p + 1] = fmaf(wv, f.y, acc[2 * p + 1]);
        }
    }
    if (stream) {
        #pragma unroll
        for (int q = 0; q < 8; ++q) red[q * 128 + t] = acc[q];
    }
    __syncthreads();
    if (!stream) {
        uint4 res;
        __half2* rp = (__half2*)&res;
        #pragma unroll
        for (int p = 0; p < 4; ++p)
            rp[p] = __floats2half2_rn(acc[2 * p] + red[(2 * p) * 128 + t],
                                      acc[2 * p + 1] + red[(2 * p + 1) * 128 + t]);
        ((uint4*)(out + (size_t)n * RowF))[t] = res;
    }
}

// -------- merged weight prep (hi only) --------
__device__ __forceinline__ uint32_t pack_f2h(float v0, float v1) {
    __half2 t = __floats2half2_rn(v0, v1);
    return *(uint32_t*)&t;
}
__device__ __forceinline__ float wc_val(const float* __restrict__ cw, int b, int rg, int n) {
    int term = rg >> 6, kk = rg & 63;
    float v;
    if (term == 0)
        v = cw[((size_t)(b * 3 + 0) * 64 + kk) * 128 + n] -
            cw[((size_t)(b * 3 + 2) * 64 + kk) * 128 + n];
    else if (term == 1)
        v = cw[((size_t)(b * 3 + 1) * 64 + kk) * 128 + n];
    else
        v = 2.f * cw[((size_t)(b * 3 + 2) * 64 + kk) * 128 + n];
    return v;
}
__global__ void prep_all(const float* __restrict__ cw,
                         const float* __restrict__ w1,
                         const float* __restrict__ w2) {
    int idx = blockIdx.x * 256 + threadIdx.x;     // 73728 total
    if (idx < 36864) {                            // g_Bc
        int b = idx / 12288, r2 = idx % 12288;
        int c = r2 >> 12, r = r2 & 4095;
        int k2 = r >> 7, t = r & 127;
        int gq = t >> 4, rem = t & 15, wn = rem >> 2, ni = rem & 3;
        int n = wn * 32 + ni * 8 + gq;
        float v0 = wc_val(cw, b, c * 64 + 2 * k2,     n);
        float v1 = wc_val(cw, b, c * 64 + 2 * k2 + 1, n);
        g_Bc[b][c][r] = pack_f2h(v0, v1);
    } else if (idx < 61440) {                     // g_B1
        int j = idx - 36864;
        int b = j / 8192, r2 = j % 8192;
        int c = r2 >> 12, r = r2 & 4095;
        int k2 = r >> 7, t = r & 127;
        int gq = t >> 4, rem = t & 15, wn = rem >> 2, ni = rem & 3;
        int n = wn * 32 + ni * 8 + gq;
        const float* W = w1 + (size_t)b * 16384 + (size_t)c * 64 * 128;
        g_B1[b][c][r] = pack_f2h(W[(size_t)(2 * k2) * 128 + n],
                                 W[(size_t)(2 * k2 + 1) * 128 + n]);
    } else if (idx < 73728) {                     // g_B2
        int j = idx - 61440;
        int b = j / 4096, r2 = j % 4096;
        int c = r2 >> 11, r = r2 & 2047;
        int k2 = r >> 6, t = r & 63;
        int gq = t >> 3, rem = t & 7, wn = rem >> 1, ni = rem & 1;
        int n = wn * 16 + ni * 8 + gq;
        const float* W = w2 + (size_t)b * 8192 + (size_t)c * 64 * 64;
        g_B2[b][c][r] = pack_f2h(W[(size_t)(2 * k2) * 64 + n],
                                 W[(size_t)(2 * k2 + 1) * 64 + n]);
    }
}

// ================== fused GEMM chain (mma.sync f16, single-term) ==================
__device__ __forceinline__ uint32_t s2u(const void* p) {
    uint32_t a;
    asm("{ .reg .u64 t; cvta.to.shared.u64 t, %1; cvt.u32.u64 %0, t; }" : "=r"(a) : "l"(p));
    return a;
}
__device__ __forceinline__ void mma_f16(float* c, const uint32_t* a, const uint32_t* b) {
    asm volatile(
        "mma.sync.aligned.m16n8k16.row.col.f32.f16.f16.f32 "
        "{%0,%1,%2,%3}, {%4,%5,%6,%7}, {%8,%9}, {%0,%1,%2,%3};\n"
        : "+f"(c[0]), "+f"(c[1]), "+f"(c[2]), "+f"(c[3])
        : "r"(a[0]), "r"(a[1]), "r"(a[2]), "r"(a[3]), "r"(b[0]), "r"(b[1]));
}
#define LDSM4(r, a) \
    asm volatile("ldmatrix.sync.aligned.m8n8.x4.shared.b16 {%0,%1,%2,%3}, [%4];" \
        : "=r"((r)[0]), "=r"((r)[1]), "=r"((r)[2]), "=r"((r)[3]) : "r"(a))

// swish in half2: v*A*(1 + tanh(v*sp2)) with tanh.approx.f16x2 (1 MUFU per 2 values)
__device__ __forceinline__ __half2 swish_h2(__half2 v, __half2 sp2, __half2 A) {
    __half2 w = __hmul2(v, sp2);
    uint32_t wi = *(uint32_t*)&w;
    uint32_t ti;
    asm("tanh.approx.f16x2 %0, %1;" : "=r"(ti) : "r"(wi));
    __half2 th = *(__half2*)&ti;
    __half2 va = __hmul2(v, A);
    return __hfma2(va, th, va);
}

constexpr int PAH = 136;                 // A tile pitch in halfs
constexpr uint32_t A0_OFF = 0;           // ping buffer
constexpr uint32_t A1_OFF = 34816;       // pong buffer (128*136*2)
constexpr int SMEM_FUSED = 69632;

// mma over one K=64 chunk (4 k16-steps); A via ldmatrix, B (hi-only) via __ldg
template <int NI>
__device__ __forceinline__ void mma_chunk(
    uint32_t aLane, int colOffHalfs,
    const uint32_t* __restrict__ BH,
    int wn, int gq, int l4, float acc[4][NI][4])
{
    #pragma unroll
    for (int s = 0; s < 4; ++s) {
        const int k2a = 8 * s + l4, k2b = k2a + 4;
        uint32_t bh[NI][2];
        if constexpr (NI == 4) {
            const int base = gq * 16 + wn * 4;
            uint4 h0 = __ldg((const uint4*)(BH + k2a * 128 + base));
            uint4 h1 = __ldg((const uint4*)(BH + k2b * 128 + base));
            bh[0][0] = h0.x; bh[1][0] = h0.y; bh[2][0] = h0.z; bh[3][0] = h0.w;
            bh[0][1] = h1.x; bh[1][1] = h1.y; bh[2][1] = h1.z; bh[3][1] = h1.w;
        } else {
            const int base = gq * 8 + wn * 2;
            uint2 h0 = __ldg((const uint2*)(BH + k2a * 64 + base));
            uint2 h1 = __ldg((const uint2*)(BH + k2b * 64 + base));
            bh[0][0] = h0.x; bh[1][0] = h0.y;
            bh[0][1] = h1.x; bh[1][1] = h1.y;
        }
        const uint32_t aoff = (uint32_t)(colOffHalfs + s * 16) * 2;
        #pragma unroll
        for (int mi = 0; mi < 4; ++mi) {
            uint32_t ah[4];
            LDSM4(ah, aLane + aoff + mi * (16 * PAH * 2));
            #pragma unroll
            for (int ni = 0; ni < NI; ++ni)
                mma_f16(acc[mi][ni], ah, bh[ni]);
        }
    }
}

// -------- fused per-block kernel --------
__global__ void __launch_bounds__(256, 2)
fused_block(int blk, int last,
            const float* __restrict__ b1, const float* __restrict__ b2,
            const float* __restrict__ cb, const float* __restrict__ betaPtr)
{
    extern __shared__ __align__(16) char smem[];
    const uint32_t sb = s2u(smem);

    const int tid  = threadIdx.x;
    const int warp = tid >> 5, lane = tid & 31;
    const int gq   = lane >> 2, l4 = lane & 3;
    const int wm   = warp >> 2, wn = warp & 3;    // 2 x 4 warp grid
    const int m0w  = wm * 64;
    const int mblk = blockIdx.x * 128;
    const float spv = log1pf(__expf(*betaPtr));
    const __half2 sp2h = __float2half2_rn(0.5f * spv);
    const __half2 Ah   = __float2half2_rn(1.f / 2.2f);
    const int n0w4 = wn * 32;
    const int n0w2 = wn * 16;

    const uint32_t aLaneOff = (uint32_t)((m0w + (lane & 15)) * PAH + (lane >> 4) * 8) * 2;
    const uint32_t aLane0 = sb + A0_OFF + aLaneOff;
    const uint32_t aLane1 = sb + A1_OFF + aLaneOff;

    float acc[4][4][4];

    // ===== Stage 1: cheb, 3 chunks, ping-pong A buffers (A0, A1, A0) =====
    #pragma unroll
    for (int mi = 0; mi < 4; ++mi)
        #pragma unroll
        for (int ni = 0; ni < 4; ++ni)
            #pragma unroll
            for (int q = 0; q < 4; ++q) acc[mi][ni][q] = 0.f;

    #pragma unroll 1
    for (int ch = 0; ch < 3; ++ch) {
        const __half* srcA = (ch == 0) ? g_hh : (ch == 1) ? g_t1h : g_t2h;
        const uint32_t dstOff = (ch == 1) ? A1_OFF : A0_OFF;
        for (int i = tid; i < 128 * 8; i += 256) {
            int m = i >> 3, q = i & 7;
            uint4 v = *(const uint4*)(srcA + (size_t)(mblk + m) * 64 + q * 8);
            *(uint4*)(smem + dstOff + (m * PAH + q * 8) * 2) = v;
        }
        __syncthreads();
        mma_chunk<4>(((ch == 1) ? aLane1 : aLane0), 0,
                     &g_Bc[blk][ch][0], wn, gq, l4, acc);
    }

    // ===== Epilogue 1: bias + swish(f16x2) -> A1 =====
    #pragma unroll
    for (int mi = 0; mi < 4; ++mi) {
        int r0 = m0w + mi * 16 + gq;
        #pragma unroll
        for (int ni = 0; ni < 4; ++ni) {
            int c = n0w4 + ni * 8 + 2 * l4;
            float bb0 = __ldg(cb + c), bb1 = __ldg(cb + c + 1);
            __half2 v0 = __floats2half2_rn(acc[mi][ni][0] + bb0, acc[mi][ni][1] + bb1);
            __half2 v1 = __floats2half2_rn(acc[mi][ni][2] + bb0, acc[mi][ni][3] + bb1);
            *(__half2*)(smem + A1_OFF + (r0 * PAH + c) * 2)       = swish_h2(v0, sp2h, Ah);
            *(__half2*)(smem + A1_OFF + ((r0 + 8) * PAH + c) * 2) = swish_h2(v1, sp2h, Ah);
        }
    }
    __syncthreads();

    // ===== Stage 2: MLP1 (K=128 from A1) =====
    #pragma unroll
    for (int mi = 0; mi < 4; ++mi)
        #pragma unroll
        for (int ni = 0; ni < 4; ++ni)
            #pragma unroll
            for (int q = 0; q < 4; ++q) acc[mi][ni][q] = 0.f;

    mma_chunk<4>(aLane1, 0,  &g_B1[blk][0][0], wn, gq, l4, acc);
    mma_chunk<4>(aLane1, 64, &g_B1[blk][1][0], wn, gq, l4, acc);

    // ===== Epilogue 2 -> A0 =====
    #pragma unroll
    for (int mi = 0; mi < 4; ++mi) {
        int r0 = m0w + mi * 16 + gq;
        #pragma unroll
        for (int ni = 0; ni < 4; ++ni) {
            int c = n0w4 + ni * 8 + 2 * l4;
            float bb0 = __ldg(b1 + c), bb1 = __ldg(b1 + c + 1);
            __half2 v0 = __floats2half2_rn(acc[mi][ni][0] + bb0, acc[mi][ni][1] + bb1);
            __half2 v1 = __floats2half2_rn(acc[mi][ni][2] + bb0, acc[mi][ni][3] + bb1);
            *(__half2*)(smem + A0_OFF + (r0 * PAH + c) * 2)       = swish_h2(v0, sp2h, Ah);
            *(__half2*)(smem + A0_OFF + ((r0 + 8) * PAH + c) * 2) = swish_h2(v1, sp2h, Ah);
        }
    }
    __syncthreads();

    // ===== Stage 3: MLP2 (N=64 from A0) + residual =====
    float acc3[4][2][4];
    #pragma unroll
    for (int mi = 0; mi < 4; ++mi)
        #pragma unroll
        for (int ni = 0; ni < 2; ++ni)
            #pragma unroll
            for (int q = 0; q < 4; ++q) acc3[mi][ni][q] = 0.f;

    mma_chunk<2>(aLane0, 0,  &g_B2[blk][0][0], wn, gq, l4, acc3);
    mma_chunk<2>(aLane0, 64, &g_B2[blk][1][0], wn, gq, l4, acc3);

    // ===== Final epilogue: h += Fx (skip fp16 shadow on last block) =====
    #pragma unroll
    for (int mi = 0; mi < 4; ++mi) {
        int r0 = mblk + m0w + mi * 16 + gq;
        #pragma unroll
        for (int ni = 0; ni < 2; ++ni) {
            int c = n0w2 + ni * 8 + 2 * l4;
            float bb0 = __ldg(b2 + c), bb1 = __ldg(b2 + c + 1);
            float2 cur0 = *(float2*)(g_h + (size_t)r0 * 64 + c);
            float2 cur1 = *(float2*)(g_h + (size_t)(r0 + 8) * 64 + c);
            cur0.x += acc3[mi][ni][0] + bb0;
            cur0.y += acc3[mi][ni][1] + bb1;
            cur1.x += acc3[mi][ni][2] + bb0;
            cur1.y += acc3[mi][ni][3] + bb1;
            *(float2*)(g_h + (size_t)r0 * 64 + c)       = cur0;
            *(float2*)(g_h + (size_t)(r0 + 8) * 64 + c) = cur1;
            if (!last) {
                *(__half2*)(g_hh + (size_t)r0 * 64 + c)       = __floats2half2_rn(cur0.x, cur0.y);
                *(__half2*)(g_hh + (size_t)(r0 + 8) * 64 + c) = __floats2half2_rn(cur1.x, cur1.y);
            }
        }
    }
}

// -------- host launcher --------
extern "C" void kernel_launch(void* const* d_in, const int* in_sizes, int n_in,
                              void* d_out, int out_size) {
    const float* x      = (const float*)d_in[0];
    const int*   ei     = (const int*)  d_in[1];
    const float* ew     = (const float*)d_in[2];
    const float* cheb_w = (const float*)d_in[3];
    const float* cheb_b = (const float*)d_in[4];
    const float* beta   = (const float*)d_in[5];
    const float* w1     = (const float*)d_in[6];
    const float* b1     = (const float*)d_in[7];
    const float* w2     = (const float*)d_in[8];
    const float* b2     = (const float*)d_in[9];
    float* out = (float*)d_out;
    const int* src = ei;
    const int* dst = ei + Ee;

    cudaFuncSetAttribute((const void*)fused_block,
                         cudaFuncAttributeMaxDynamicSharedMemorySize, SMEM_FUSED);

    const int EB = (Ee + 255) / 256;
    const int NBk = (Nn + 255) / 256;

    zero_deg_cnt<<<NBk, 256>>>();
    deg_kernel<<<EB, 256>>>(src, ew);
    dinv_kernel<<<NBk, 256>>>();
    w_count_kernel<<<EB, 256>>>(src, dst, ew);
    scan_kernel<<<1, 1024>>>();
    fill_kernel<<<EB, 256>>>(src, dst);
    prep_all<<<288, 256>>>(cheb_w, w1, w2);

    t_in_kernel<<<Nn, 256>>>((const float4*)x);

    for (int b = 0; b < NBlk; ++b) {
        spmm16_kernel<0><<<Nn, 256>>>();
        spmm16_kernel<1><<<Nn, 256>>>();
        fused_block<<<2500, 256, SMEM_FUSED>>>(
            b, (b == NBlk - 1) ? 1 : 0,
            b1 + b * 128, b2 + b * 64, cheb_b + b * 128, beta + b);
    }

    t_out_kernel<<<Nn, 256>>>((float4*)out);
}

// round 13
// speedup vs baseline: 3.4622x; 1.0195x over previous
#include <cuda_runtime.h>
#include <cuda_fp16.h>
#include <stdint.h>
#include <math.h>

// Problem constants
constexpr int Bc   = 16;
constexpr int Nn   = 20000;
constexpr int Cc   = 64;
constexpr int Ee   = 640000;
constexpr int NBlk = 3;
constexpr int ROWS = Nn * Bc;          // 320000
constexpr int RowF = Bc * Cc;          // 1024 halfs per node row ([N][B][C])
constexpr int RowF4 = RowF / 4;
constexpr int NSCAN = (Nn + 255) / 256;  // 79 scan blocks

// -------- device scratch --------
__device__ __align__(16) float  g_h  [ROWS * Cc];
__device__ __align__(16) __half g_hh [ROWS * Cc];
__device__ __align__(16) __half g_t1h[ROWS * Cc];
__device__ __align__(16) __half g_t2h[ROWS * Cc];
__device__ float g_deg [Nn];
__device__ float g_dinv[Nn];
__device__ float g_w   [Ee];
__device__ int   g_off [Nn + 1];
__device__ int   g_cnt [Nn];
__device__ int   g_bsum[NSCAN];
__device__ int   g_bbase[NSCAN + 1];
__device__ int   g_csrc[Ee];
__device__ float g_csw [Ee];
// Pre-packed fp16 B operands (hi only), LANE-VECTORIZED fragment layout:
// N=128: word r = k2*128 + gq*16 + wn*4 + ni  (n = wn*32 + ni*8 + gq)
// N=64 : word r = k2*64  + gq*8  + wn*2 + ni  (n = wn*16 + ni*8 + gq)
__device__ __align__(16) uint32_t g_Bc[3][3][32 * 128];   // [block][chunk]
__device__ __align__(16) uint32_t g_B1[3][2][32 * 128];
__device__ __align__(16) uint32_t g_B2[3][2][32 * 64];

// -------- small setup kernels --------
__global__ void zero_deg_cnt() {
    int i = blockIdx.x * blockDim.x + threadIdx.x;
    if (i < Nn) { g_deg[i] = 0.f; g_cnt[i] = 0; }
}
__global__ void deg_kernel(const int* __restrict__ src, const float* __restrict__ ew) {
    int e = blockIdx.x * blockDim.x + threadIdx.x;
    if (e < Ee) atomicAdd(&g_deg[src[e]], ew[e]);
}
__global__ void dinv_kernel() {
    int i = blockIdx.x * blockDim.x + threadIdx.x;
    if (i < Nn) {
        float d = g_deg[i];
        g_dinv[i] = (d > 0.f) ? rsqrtf(fmaxf(d, 1e-12f)) : 0.f;
    }
}
__global__ void w_count_kernel(const int* __restrict__ src, const int* __restrict__ dst,
                               const float* __restrict__ ew) {
    int e = blockIdx.x * blockDim.x + threadIdx.x;
    if (e < Ee) {
        int s = src[e], d = dst[e];
        g_w[e] = -g_dinv[s] * ew[e] * g_dinv[d];
        atomicAdd(&g_cnt[d], 1);
    }
}
// decoupled scan, phase 1: per-256-block exclusive scan + block total; zero g_cnt
__global__ void scan1_kernel() {
    __shared__ int wsum[8];
    int b = blockIdx.x, t = threadIdx.x;
    int i = b * 256 + t;
    int v = (i < Nn) ? g_cnt[i] : 0;
    if (i < Nn) g_cnt[i] = 0;
    int x = v;
    #pragma unroll
    for (int d = 1; d < 32; d <<= 1) {
        int y = __shfl_up_sync(0xFFFFFFFFu, x, d);
        if ((t & 31) >= d) x += y;
    }
    if ((t & 31) == 31) wsum[t >> 5] = x;
    __syncthreads();
    if (t < 8) {
        int y = wsum[t];
        #pragma unroll
        for (int d = 1; d < 8; d <<= 1) {
            int z = __shfl_up_sync(0xFFu, y, d);
            if (t >= d) y += z;
        }
        wsum[t] = y;
    }
    __syncthreads();
    int excl = (x - v) + ((t >= 32) ? wsum[(t >> 5) - 1] : 0);
    if (i < Nn) g_off[i] = excl;
    if (t == 255) g_bsum[b] = excl + v;
}
// phase 2: single-warp scan of 79 block sums
__global__ void scan2_kernel() {
    int t = threadIdx.x;              // 128 threads, need 79+1
    __shared__ int sh[NSCAN];
    if (t < NSCAN) sh[t] = g_bsum[t];
    __syncthreads();
    if (t == 0) {
        int run = 0;
        #pragma unroll 4
        for (int b = 0; b < NSCAN; ++b) { g_bbase[b] = run; run += sh[b]; }
        g_bbase[NSCAN] = run;
        g_off[Nn] = run;
    }
}
// phase 3: add block base
__global__ void scan3_kernel() {
    int i = blockIdx.x * 256 + threadIdx.x;
    if (i < Nn) g_off[i] += g_bbase[blockIdx.x];
}
__global__ void fill_kernel(const int* __restrict__ src, const int* __restrict__ dst) {
    int e = blockIdx.x * blockDim.x + threadIdx.x;
    if (e < Ee) {
        int d = dst[e];
        int pos = g_off[d] + atomicAdd(&g_cnt[d], 1);
        g_csrc[pos] = src[e];
        g_csw[pos]  = g_w[e];
    }
}

// -------- transposes --------
__global__ void t_in_kernel(const float4* __restrict__ x4) {
    int idx = blockIdx.x * 256 + threadIdx.x;
    int b = idx / (Nn * 16);
    int r = idx % (Nn * 16);
    int n = r >> 4, c4 = r & 15;
    float4 v = x4[idx];
    int o4 = n * RowF4 + b * 16 + c4;
    ((float4*)g_h)[o4] = v;
    ((__half2*)g_hh)[o4 * 2]     = __floats2half2_rn(v.x, v.y);
    ((__half2*)g_hh)[o4 * 2 + 1] = __floats2half2_rn(v.z, v.w);
}
__global__ void t_out_kernel(float4* __restrict__ o4) {
    int idx = blockIdx.x * 256 + threadIdx.x;
    int b = idx / (Nn * 16);
    int r = idx % (Nn * 16);
    int n = r >> 4, c4 = r & 15;
    o4[idx] = ((const float4*)g_h)[n * RowF4 + b * 16 + c4];
}

// -------- SpMM fp16, dual edge streams (BW-bound, at LTS roofline) --------
template <int PHASE>
__global__ void __launch_bounds__(256) spmm16_kernel() {
    const __half* __restrict__ in = (PHASE == 0) ? g_hh : g_t1h;
    __half* __restrict__ out      = (PHASE == 0) ? g_t1h : g_t2h;
    __shared__ float red[8 * 128];
    int n = blockIdx.x;
    int stream = threadIdx.x >> 7;
    int t = threadIdx.x & 127;
    int e0 = g_off[n], e1 = g_off[n + 1];
    float acc[8];
    #pragma unroll
    for (int q = 0; q < 8; ++q) acc[q] = 0.f;
    #pragma unroll 4
    for (int e = e0 + stream; e < e1; e += 2) {
        int   s  = __ldg(&g_csrc[e]);
        float wv = __ldg(&g_csw[e]);
        uint4 raw = __ldg((const uint4*)(in + (size_t)s * RowF) + t);
        const __half2* hp = (const __half2*)&raw;
        #pragma unroll
        for (int p = 0; p < 4; ++p) {
            float2 f = __half22float2(hp[p]);
            acc[2 * p]     = fmaf(wv, f.x, acc[2 * p]);
            acc[2 * p + 1] = fmaf(wv, f.y, acc[2 * p + 1]);
        }
    }
    if (stream) {
        #pragma unroll
        for (int q = 0; q < 8; ++q) red[q * 128 + t] = acc[q];
    }
    __syncthreads();
    if (!stream) {
        uint4 res;
        __half2* rp = (__half2*)&res;
        #pragma unroll
        for (int p = 0; p < 4; ++p)
            rp[p] = __floats2half2_rn(acc[2 * p] + red[(2 * p) * 128 + t],
                                      acc[2 * p + 1] + red[(2 * p + 1) * 128 + t]);
        ((uint4*)(out + (size_t)n * RowF))[t] = res;
    }
}

// -------- merged weight prep (hi only) --------
__device__ __forceinline__ uint32_t pack_f2h(float v0, float v1) {
    __half2 t = __floats2half2_rn(v0, v1);
    return *(uint32_t*)&t;
}
__device__ __forceinline__ float wc_val(const float* __restrict__ cw, int b, int rg, int n) {
    int term = rg >> 6, kk = rg & 63;
    float v;
    if (term == 0)
        v = cw[((size_t)(b * 3 + 0) * 64 + kk) * 128 + n] -
            cw[((size_t)(b * 3 + 2) * 64 + kk) * 128 + n];
    else if (term == 1)
        v = cw[((size_t)(b * 3 + 1) * 64 + kk) * 128 + n];
    else
        v = 2.f * cw[((size_t)(b * 3 + 2) * 64 + kk) * 128 + n];
    return v;
}
__global__ void prep_all(const float* __restrict__ cw,
                         const float* __restrict__ w1,
                         const float* __restrict__ w2) {
    int idx = blockIdx.x * 256 + threadIdx.x;     // 73728 total
    if (idx < 36864) {                            // g_Bc
        int b = idx / 12288, r2 = idx % 12288;
        int c = r2 >> 12, r = r2 & 4095;
        int k2 = r >> 7, t = r & 127;
        int gq = t >> 4, rem = t & 15, wn = rem >> 2, ni = rem & 3;
        int n = wn * 32 + ni * 8 + gq;
        float v0 = wc_val(cw, b, c * 64 + 2 * k2,     n);
        float v1 = wc_val(cw, b, c * 64 + 2 * k2 + 1, n);
        g_Bc[b][c][r] = pack_f2h(v0, v1);
    } else if (idx < 61440) {                     // g_B1
        int j = idx - 36864;
        int b = j / 8192, r2 = j % 8192;
        int c = r2 >> 12, r = r2 & 4095;
        int k2 = r >> 7, t = r & 127;
        int gq = t >> 4, rem = t & 15, wn = rem >> 2, ni = rem & 3;
        int n = wn * 32 + ni * 8 + gq;
        const float* W = w1 + (size_t)b * 16384 + (size_t)c * 64 * 128;
        g_B1[b][c][r] = pack_f2h(W[(size_t)(2 * k2) * 128 + n],
                                 W[(size_t)(2 * k2 + 1) * 128 + n]);
    } else if (idx < 73728) {                     // g_B2
        int j = idx - 61440;
        int b = j / 4096, r2 = j % 4096;
        int c = r2 >> 11, r = r2 & 2047;
        int k2 = r >> 6, t = r & 63;
        int gq = t >> 3, rem = t & 7, wn = rem >> 1, ni = rem & 1;
        int n = wn * 16 + ni * 8 + gq;
        const float* W = w2 + (size_t)b * 8192 + (size_t)c * 64 * 64;
        g_B2[b][c][r] = pack_f2h(W[(size_t)(2 * k2) * 64 + n],
                                 W[(size_t)(2 * k2 + 1) * 64 + n]);
    }
}

// ================== fused GEMM chain (mma.sync f16, single-term) ==================
__device__ __forceinline__ uint32_t s2u(const void* p) {
    uint32_t a;
    asm("{ .reg .u64 t; cvta.to.shared.u64 t, %1; cvt.u32.u64 %0, t; }" : "=r"(a) : "l"(p));
    return a;
}
__device__ __forceinline__ void mma_f16(float* c, const uint32_t* a, const uint32_t* b) {
    asm volatile(
        "mma.sync.aligned.m16n8k16.row.col.f32.f16.f16.f32 "
        "{%0,%1,%2,%3}, {%4,%5,%6,%7}, {%8,%9}, {%0,%1,%2,%3};\n"
        : "+f"(c[0]), "+f"(c[1]), "+f"(c[2]), "+f"(c[3])
        : "r"(a[0]), "r"(a[1]), "r"(a[2]), "r"(a[3]), "r"(b[0]), "r"(b[1]));
}
#define LDSM4(r, a) \
    asm volatile("ldmatrix.sync.aligned.m8n8.x4.shared.b16 {%0,%1,%2,%3}, [%4];" \
        : "=r"((r)[0]), "=r"((r)[1]), "=r"((r)[2]), "=r"((r)[3]) : "r"(a))

// swish via tanh.approx.f32 (kept f32: f16x2 variant cost +1.6e-4 err for ~8us, reverted)
__device__ __forceinline__ float swish_t(float v, float sp2, float A) {
    float t;
    asm("tanh.approx.f32 %0, %1;" : "=f"(t) : "f"(v * sp2));
    float va = v * A;
    return fmaf(va, t, va);
}

constexpr int PAH = 136;                 // A tile pitch in halfs
constexpr uint32_t A0_OFF = 0;           // ping buffer
constexpr uint32_t A1_OFF = 34816;       // pong buffer (128*136*2)
constexpr int SMEM_FUSED = 69632;

// mma over one K=64 chunk (4 k16-steps); A via ldmatrix, B (hi-only) via __ldg
template <int NI>
__device__ __forceinline__ void mma_chunk(
    uint32_t aLane, int colOffHalfs,
    const uint32_t* __restrict__ BH,
    int wn, int gq, int l4, float acc[4][NI][4])
{
    #pragma unroll
    for (int s = 0; s < 4; ++s) {
        const int k2a = 8 * s + l4, k2b = k2a + 4;
        uint32_t bh[NI][2];
        if constexpr (NI == 4) {
            const int base = gq * 16 + wn * 4;
            uint4 h0 = __ldg((const uint4*)(BH + k2a * 128 + base));
            uint4 h1 = __ldg((const uint4*)(BH + k2b * 128 + base));
            bh[0][0] = h0.x; bh[1][0] = h0.y; bh[2][0] = h0.z; bh[3][0] = h0.w;
            bh[0][1] = h1.x; bh[1][1] = h1.y; bh[2][1] = h1.z; bh[3][1] = h1.w;
        } else {
            const int base = gq * 8 + wn * 2;
            uint2 h0 = __ldg((const uint2*)(BH + k2a * 64 + base));
            uint2 h1 = __ldg((const uint2*)(BH + k2b * 64 + base));
            bh[0][0] = h0.x; bh[1][0] = h0.y;
            bh[0][1] = h1.x; bh[1][1] = h1.y;
        }
        const uint32_t aoff = (uint32_t)(colOffHalfs + s * 16) * 2;
        #pragma unroll
        for (int mi = 0; mi < 4; ++mi) {
            uint32_t ah[4];
            LDSM4(ah, aLane + aoff + mi * (16 * PAH * 2));
            #pragma unroll
            for (int ni = 0; ni < NI; ++ni)
                mma_f16(acc[mi][ni], ah, bh[ni]);
        }
    }
}

// -------- fused per-block kernel --------
__global__ void __launch_bounds__(256, 2)
fused_block(int blk, int last,
            const float* __restrict__ b1, const float* __restrict__ b2,
            const float* __restrict__ cb, const float* __restrict__ betaPtr)
{
    extern __shared__ __align__(16) char smem[];
    const uint32_t sb = s2u(smem);

    const int tid  = threadIdx.x;
    const int warp = tid >> 5, lane = tid & 31;
    const int gq   = lane >> 2, l4 = lane & 3;
    const int wm   = warp >> 2, wn = warp & 3;    // 2 x 4 warp grid
    const int m0w  = wm * 64;
    const int mblk = blockIdx.x * 128;
    const float spv = log1pf(__expf(*betaPtr));
    const float sp2 = 0.5f * spv;
    const float Asw = 1.f / 2.2f;
    const int n0w4 = wn * 32;
    const int n0w2 = wn * 16;

    const uint32_t aLaneOff = (uint32_t)((m0w + (lane & 15)) * PAH + (lane >> 4) * 8) * 2;
    const uint32_t aLane0 = sb + A0_OFF + aLaneOff;
    const uint32_t aLane1 = sb + A1_OFF + aLaneOff;

    // hoisted bias fragments (columns owned by this lane)
    float cbv[4][2], b1v[4][2], b2v[2][2];
    #pragma unroll
    for (int ni = 0; ni < 4; ++ni) {
        int c = n0w4 + ni * 8 + 2 * l4;
        float2 t0 = *(const float2*)(cb + c);  cbv[ni][0] = t0.x; cbv[ni][1] = t0.y;
        float2 t1 = *(const float2*)(b1 + c);  b1v[ni][0] = t1.x; b1v[ni][1] = t1.y;
    }
    #pragma unroll
    for (int ni = 0; ni < 2; ++ni) {
        int c = n0w2 + ni * 8 + 2 * l4;
        float2 t2 = *(const float2*)(b2 + c);  b2v[ni][0] = t2.x; b2v[ni][1] = t2.y;
    }

    float acc[4][4][4];

    // ===== Stage 1: cheb, 3 chunks, ping-pong A buffers (A0, A1, A0) =====
    #pragma unroll
    for (int mi = 0; mi < 4; ++mi)
        #pragma unroll
        for (int ni = 0; ni < 4; ++ni)
            #pragma unroll
            for (int q = 0; q < 4; ++q) acc[mi][ni][q] = 0.f;

    #pragma unroll 1
    for (int ch = 0; ch < 3; ++ch) {
        const __half* srcA = (ch == 0) ? g_hh : (ch == 1) ? g_t1h : g_t2h;
        const uint32_t dstOff = (ch == 1) ? A1_OFF : A0_OFF;
        for (int i = tid; i < 128 * 8; i += 256) {
            int m = i >> 3, q = i & 7;
            uint4 v = *(const uint4*)(srcA + (size_t)(mblk + m) * 64 + q * 8);
            *(uint4*)(smem + dstOff + (m * PAH + q * 8) * 2) = v;
        }
        __syncthreads();
        mma_chunk<4>(((ch == 1) ? aLane1 : aLane0), 0,
                     &g_Bc[blk][ch][0], wn, gq, l4, acc);
    }

    // ===== Epilogue 1: bias + swish(f32 tanh) -> A1 =====
    #pragma unroll
    for (int mi = 0; mi < 4; ++mi) {
        int r0 = m0w + mi * 16 + gq;
        #pragma unroll
        for (int ni = 0; ni < 4; ++ni) {
            int c = n0w4 + ni * 8 + 2 * l4;
            float v00 = swish_t(acc[mi][ni][0] + cbv[ni][0], sp2, Asw);
            float v01 = swish_t(acc[mi][ni][1] + cbv[ni][1], sp2, Asw);
            float v10 = swish_t(acc[mi][ni][2] + cbv[ni][0], sp2, Asw);
            float v11 = swish_t(acc[mi][ni][3] + cbv[ni][1], sp2, Asw);
            *(__half2*)(smem + A1_OFF + (r0 * PAH + c) * 2)       = __floats2half2_rn(v00, v01);
            *(__half2*)(smem + A1_OFF + ((r0 + 8) * PAH + c) * 2) = __floats2half2_rn(v10, v11);
        }
    }
    __syncthreads();

    // ===== Stage 2: MLP1 (K=128 from A1) =====
    #pragma unroll
    for (int mi = 0; mi < 4; ++mi)
        #pragma unroll
        for (int ni = 0; ni < 4; ++ni)
            #pragma unroll
            for (int q = 0; q < 4; ++q) acc[mi][ni][q] = 0.f;

    mma_chunk<4>(aLane1, 0,  &g_B1[blk][0][0], wn, gq, l4, acc);
    mma_chunk<4>(aLane1, 64, &g_B1[blk][1][0], wn, gq, l4, acc);

    // ===== Epilogue 2 -> A0 =====
    #pragma unroll
    for (int mi = 0; mi < 4; ++mi) {
        int r0 = m0w + mi * 16 + gq;
        #pragma unroll
        for (int ni = 0; ni < 4; ++ni) {
            int c = n0w4 + ni * 8 + 2 * l4;
            float v00 = swish_t(acc[mi][ni][0] + b1v[ni][0], sp2, Asw);
            float v01 = swish_t(acc[mi][ni][1] + b1v[ni][1], sp2, Asw);
            float v10 = swish_t(acc[mi][ni][2] + b1v[ni][0], sp2, Asw);
            float v11 = swish_t(acc[mi][ni][3] + b1v[ni][1], sp2, Asw);
            *(__half2*)(smem + A0_OFF + (r0 * PAH + c) * 2)       = __floats2half2_rn(v00, v01);
            *(__half2*)(smem + A0_OFF + ((r0 + 8) * PAH + c) * 2) = __floats2half2_rn(v10, v11);
        }
    }
    __syncthreads();

    // ===== Stage 3: MLP2 (N=64 from A0) + residual =====
    float acc3[4][2][4];
    #pragma unroll
    for (int mi = 0; mi < 4; ++mi)
        #pragma unroll
        for (int ni = 0; ni < 2; ++ni)
            #pragma unroll
            for (int q = 0; q < 4; ++q) acc3[mi][ni][q] = 0.f;

    mma_chunk<2>(aLane0, 0,  &g_B2[blk][0][0], wn, gq, l4, acc3);
    mma_chunk<2>(aLane0, 64, &g_B2[blk][1][0], wn, gq, l4, acc3);

    // ===== Final epilogue: h += Fx (skip fp16 shadow on last block) =====
    #pragma unroll
    for (int mi = 0; mi < 4; ++mi) {
        int r0 = mblk + m0w + mi * 16 + gq;
        #pragma unroll
        for (int ni = 0; ni < 2; ++ni) {
            int c = n0w2 + ni * 8 + 2 * l4;
            float2 cur0 = *(float2*)(g_h + (size_t)r0 * 64 + c);
            float2 cur1 = *(float2*)(g_h + (size_t)(r0 + 8) * 64 + c);
            cur0.x += acc3[mi][ni][0] + b2v[ni][0];
            cur0.y += acc3[mi][ni][1] + b2v[ni][1];
            cur1.x += acc3[mi][ni][2] + b2v[ni][0];
            cur1.y += acc3[mi][ni][3] + b2v[ni][1];
            *(float2*)(g_h + (size_t)r0 * 64 + c)       = cur0;
            *(float2*)(g_h + (size_t)(r0 + 8) * 64 + c) = cur1;
            if (!last) {
                *(__half2*)(g_hh + (size_t)r0 * 64 + c)       = __floats2half2_rn(cur0.x, cur0.y);
                *(__half2*)(g_hh + (size_t)(r0 + 8) * 64 + c) = __floats2half2_rn(cur1.x, cur1.y);
            }
        }
    }
}

// -------- host launcher --------
extern "C" void kernel_launch(void* const* d_in, const int* in_sizes, int n_in,
                              void* d_out, int out_size) {
    const float* x      = (const float*)d_in[0];
    const int*   ei     = (const int*)  d_in[1];
    const float* ew     = (const float*)d_in[2];
    const float* cheb_w = (const float*)d_in[3];
    const float* cheb_b = (const float*)d_in[4];
    const float* beta   = (const float*)d_in[5];
    const float* w1     = (const float*)d_in[6];
    const float* b1     = (const float*)d_in[7];
    const float* w2     = (const float*)d_in[8];
    const float* b2     = (const float*)d_in[9];
    float* out = (float*)d_out;
    const int* src = ei;
    const int* dst = ei + Ee;

    cudaFuncSetAttribute((const void*)fused_block,
                         cudaFuncAttributeMaxDynamicSharedMemorySize, SMEM_FUSED);

    const int EB = (Ee + 255) / 256;

    zero_deg_cnt<<<NSCAN, 256>>>();
    deg_kernel<<<EB, 256>>>(src, ew);
    dinv_kernel<<<NSCAN, 256>>>();
    w_count_kernel<<<EB, 256>>>(src, dst, ew);
    scan1_kernel<<<NSCAN, 256>>>();
    scan2_kernel<<<1, 128>>>();
    scan3_kernel<<<NSCAN, 256>>>();
    fill_kernel<<<EB, 256>>>(src, dst);
    prep_all<<<288, 256>>>(cheb_w, w1, w2);

    t_in_kernel<<<Nn, 256>>>((const float4*)x);

    for (int b = 0; b < NBlk; ++b) {
        spmm16_kernel<0><<<Nn, 256>>>();
        spmm16_kernel<1><<<Nn, 256>>>();
        fused_block<<<2500, 256, SMEM_FUSED>>>(
            b, (b == NBlk - 1) ? 1 : 0,
            b1 + b * 128, b2 + b * 64, cheb_b + b * 128, beta + b);
    }

    t_out_kernel<<<Nn, 256>>>((float4*)out);
}

// round 14
// speedup vs baseline: 3.5173x; 1.0159x over previous
#include <cuda_runtime.h>
#include <cuda_fp16.h>
#include <stdint.h>
#include <math.h>

// Problem constants
constexpr int Bc   = 16;
constexpr int Nn   = 20000;
constexpr int Cc   = 64;
constexpr int Ee   = 640000;
constexpr int NBlk = 3;
constexpr int ROWS = Nn * Bc;          // 320000
constexpr int RowF = Bc * Cc;          // 1024 halfs per node row ([N][B][C])
constexpr int RowF4 = RowF / 4;
constexpr int NSCAN = (Nn + 255) / 256;  // 79 scan blocks

// -------- device scratch --------
__device__ __align__(16) float  g_h  [ROWS * Cc];
__device__ __align__(16) __half g_hh [ROWS * Cc];
__device__ __align__(16) __half g_t1h[ROWS * Cc];
__device__ __align__(16) __half g_t2h[ROWS * Cc];
__device__ float g_deg [Nn];
__device__ float g_w   [Ee];
__device__ int   g_off [Nn + 1];
__device__ int   g_cnt [Nn];
__device__ int   g_bsum[NSCAN];
__device__ int   g_bbase[NSCAN + 1];
__device__ int   g_csrc[Ee];
__device__ float g_csw [Ee];
// Pre-packed fp16 B operands (hi only), LANE-VECTORIZED fragment layout:
// N=128: word r = k2*128 + gq*16 + wn*4 + ni  (n = wn*32 + ni*8 + gq)
// N=64 : word r = k2*64  + gq*8  + wn*2 + ni  (n = wn*16 + ni*8 + gq)
__device__ __align__(16) uint32_t g_Bc[3][3][32 * 128];   // [block][chunk]
__device__ __align__(16) uint32_t g_B1[3][2][32 * 128];
__device__ __align__(16) uint32_t g_B2[3][2][32 * 64];

// -------- small setup kernels --------
__global__ void zero_deg_cnt() {
    int i = blockIdx.x * blockDim.x + threadIdx.x;
    if (i < Nn) { g_deg[i] = 0.f; g_cnt[i] = 0; }
}
__global__ void deg_kernel(const int* __restrict__ src, const float* __restrict__ ew) {
    int e = blockIdx.x * blockDim.x + threadIdx.x;
    if (e < Ee) atomicAdd(&g_deg[src[e]], ew[e]);
}
// w = -dinv[s]*ew*dinv[d] with dinv computed inline (dinv kernel folded in)
__global__ void w_count_kernel(const int* __restrict__ src, const int* __restrict__ dst,
                               const float* __restrict__ ew) {
    int e = blockIdx.x * blockDim.x + threadIdx.x;
    if (e < Ee) {
        int s = src[e], d = dst[e];
        float ds = g_deg[s], dd = g_deg[d];
        float is = (ds > 0.f) ? rsqrtf(fmaxf(ds, 1e-12f)) : 0.f;
        float id = (dd > 0.f) ? rsqrtf(fmaxf(dd, 1e-12f)) : 0.f;
        g_w[e] = -is * ew[e] * id;
        atomicAdd(&g_cnt[d], 1);
    }
}
// decoupled scan, phase 1: per-256-block exclusive scan + block total; zero g_cnt
__global__ void scan1_kernel() {
    __shared__ int wsum[8];
    int b = blockIdx.x, t = threadIdx.x;
    int i = b * 256 + t;
    int v = (i < Nn) ? g_cnt[i] : 0;
    if (i < Nn) g_cnt[i] = 0;
    int x = v;
    #pragma unroll
    for (int d = 1; d < 32; d <<= 1) {
        int y = __shfl_up_sync(0xFFFFFFFFu, x, d);
        if ((t & 31) >= d) x += y;
    }
    if ((t & 31) == 31) wsum[t >> 5] = x;
    __syncthreads();
    if (t < 8) {
        int y = wsum[t];
        #pragma unroll
        for (int d = 1; d < 8; d <<= 1) {
            int z = __shfl_up_sync(0xFFu, y, d);
            if (t >= d) y += z;
        }
        wsum[t] = y;
    }
    __syncthreads();
    int excl = (x - v) + ((t >= 32) ? wsum[(t >> 5) - 1] : 0);
    if (i < Nn) g_off[i] = excl;
    if (t == 255) g_bsum[b] = excl + v;
}
__global__ void scan2_kernel() {
    int t = threadIdx.x;
    __shared__ int sh[NSCAN];
    if (t < NSCAN) sh[t] = g_bsum[t];
    __syncthreads();
    if (t == 0) {
        int run = 0;
        #pragma unroll 4
        for (int b = 0; b < NSCAN; ++b) { g_bbase[b] = run; run += sh[b]; }
        g_bbase[NSCAN] = run;
        g_off[Nn] = run;
    }
}
__global__ void scan3_kernel() {
    int i = blockIdx.x * 256 + threadIdx.x;
    if (i < Nn) g_off[i] += g_bbase[blockIdx.x];
}
__global__ void fill_kernel(const int* __restrict__ src, const int* __restrict__ dst) {
    int e = blockIdx.x * blockDim.x + threadIdx.x;
    if (e < Ee) {
        int d = dst[e];
        int pos = g_off[d] + atomicAdd(&g_cnt[d], 1);
        g_csrc[pos] = src[e];
        g_csw[pos]  = g_w[e];
    }
}

// -------- input transpose --------
__global__ void t_in_kernel(const float4* __restrict__ x4) {
    int idx = blockIdx.x * 256 + threadIdx.x;
    int b = idx / (Nn * 16);
    int r = idx % (Nn * 16);
    int n = r >> 4, c4 = r & 15;
    float4 v = x4[idx];
    int o4 = n * RowF4 + b * 16 + c4;
    ((float4*)g_h)[o4] = v;
    ((__half2*)g_hh)[o4 * 2]     = __floats2half2_rn(v.x, v.y);
    ((__half2*)g_hh)[o4 * 2 + 1] = __floats2half2_rn(v.z, v.w);
}

// -------- SpMM fp16, dual edge streams (BW-bound, at LTS roofline) --------
template <int PHASE>
__global__ void __launch_bounds__(256) spmm16_kernel() {
    const __half* __restrict__ in = (PHASE == 0) ? g_hh : g_t1h;
    __half* __restrict__ out      = (PHASE == 0) ? g_t1h : g_t2h;
    __shared__ float red[8 * 128];
    int n = blockIdx.x;
    int stream = threadIdx.x >> 7;
    int t = threadIdx.x & 127;
    int e0 = g_off[n], e1 = g_off[n + 1];
    float acc[8];
    #pragma unroll
    for (int q = 0; q < 8; ++q) acc[q] = 0.f;
    #pragma unroll 4
    for (int e = e0 + stream; e < e1; e += 2) {
        int   s  = __ldg(&g_csrc[e]);
        float wv = __ldg(&g_csw[e]);
        uint4 raw = __ldg((const uint4*)(in + (size_t)s * RowF) + t);
        const __half2* hp = (const __half2*)&raw;
        #pragma unroll
        for (int p = 0; p < 4; ++p) {
            float2 f = __half22float2(hp[p]);
            acc[2 * p]     = fmaf(wv, f.x, acc[2 * p]);
            acc[2 * p + 1] = fmaf(wv, f.y, acc[2 * p + 1]);
        }
    }
    if (stream) {
        #pragma unroll
        for (int q = 0; q < 8; ++q) red[q * 128 + t] = acc[q];
    }
    __syncthreads();
    if (!stream) {
        uint4 res;
        __half2* rp = (__half2*)&res;
        #pragma unroll
        for (int p = 0; p < 4; ++p)
            rp[p] = __floats2half2_rn(acc[2 * p] + red[(2 * p) * 128 + t],
                                      acc[2 * p + 1] + red[(2 * p + 1) * 128 + t]);
        ((uint4*)(out + (size_t)n * RowF))[t] = res;
    }
}

// -------- merged weight prep (hi only) --------
__device__ __forceinline__ uint32_t pack_f2h(float v0, float v1) {
    __half2 t = __floats2half2_rn(v0, v1);
    return *(uint32_t*)&t;
}
__device__ __forceinline__ float wc_val(const float* __restrict__ cw, int b, int rg, int n) {
    int term = rg >> 6, kk = rg & 63;
    float v;
    if (term == 0)
        v = cw[((size_t)(b * 3 + 0) * 64 + kk) * 128 + n] -
            cw[((size_t)(b * 3 + 2) * 64 + kk) * 128 + n];
    else if (term == 1)
        v = cw[((size_t)(b * 3 + 1) * 64 + kk) * 128 + n];
    else
        v = 2.f * cw[((size_t)(b * 3 + 2) * 64 + kk) * 128 + n];
    return v;
}
__global__ void prep_all(const float* __restrict__ cw,
                         const float* __restrict__ w1,
                         const float* __restrict__ w2) {
    int idx = blockIdx.x * 256 + threadIdx.x;     // 73728 total
    if (idx < 36864) {                            // g_Bc
        int b = idx / 12288, r2 = idx % 12288;
        int c = r2 >> 12, r = r2 & 4095;
        int k2 = r >> 7, t = r & 127;
        int gq = t >> 4, rem = t & 15, wn = rem >> 2, ni = rem & 3;
        int n = wn * 32 + ni * 8 + gq;
        float v0 = wc_val(cw, b, c * 64 + 2 * k2,     n);
        float v1 = wc_val(cw, b, c * 64 + 2 * k2 + 1, n);
        g_Bc[b][c][r] = pack_f2h(v0, v1);
    } else if (idx < 61440) {                     // g_B1
        int j = idx - 36864;
        int b = j / 8192, r2 = j % 8192;
        int c = r2 >> 12, r = r2 & 4095;
        int k2 = r >> 7, t = r & 127;
        int gq = t >> 4, rem = t & 15, wn = rem >> 2, ni = rem & 3;
        int n = wn * 32 + ni * 8 + gq;
        const float* W = w1 + (size_t)b * 16384 + (size_t)c * 64 * 128;
        g_B1[b][c][r] = pack_f2h(W[(size_t)(2 * k2) * 128 + n],
                                 W[(size_t)(2 * k2 + 1) * 128 + n]);
    } else if (idx < 73728) {                     // g_B2
        int j = idx - 61440;
        int b = j / 4096, r2 = j % 4096;
        int c = r2 >> 11, r = r2 & 2047;
        int k2 = r >> 6, t = r & 63;
        int gq = t >> 3, rem = t & 7, wn = rem >> 1, ni = rem & 1;
        int n = wn * 16 + ni * 8 + gq;
        const float* W = w2 + (size_t)b * 8192 + (size_t)c * 64 * 64;
        g_B2[b][c][r] = pack_f2h(W[(size_t)(2 * k2) * 64 + n],
                                 W[(size_t)(2 * k2 + 1) * 64 + n]);
    }
}

// ================== fused GEMM chain (mma.sync f16, single-term) ==================
__device__ __forceinline__ uint32_t s2u(const void* p) {
    uint32_t a;
    asm("{ .reg .u64 t; cvta.to.shared.u64 t, %1; cvt.u32.u64 %0, t; }" : "=r"(a) : "l"(p));
    return a;
}
__device__ __forceinline__ void mma_f16(float* c, const uint32_t* a, const uint32_t* b) {
    asm volatile(
        "mma.sync.aligned.m16n8k16.row.col.f32.f16.f16.f32 "
        "{%0,%1,%2,%3}, {%4,%5,%6,%7}, {%8,%9}, {%0,%1,%2,%3};\n"
        : "+f"(c[0]), "+f"(c[1]), "+f"(c[2]), "+f"(c[3])
        : "r"(a[0]), "r"(a[1]), "r"(a[2]), "r"(a[3]), "r"(b[0]), "r"(b[1]));
}
#define LDSM4(r, a) \
    asm volatile("ldmatrix.sync.aligned.m8n8.x4.shared.b16 {%0,%1,%2,%3}, [%4];" \
        : "=r"((r)[0]), "=r"((r)[1]), "=r"((r)[2]), "=r"((r)[3]) : "r"(a))

// swish via tanh.approx.f32
__device__ __forceinline__ float swish_t(float v, float sp2, float A) {
    float t;
    asm("tanh.approx.f32 %0, %1;" : "=f"(t) : "f"(v * sp2));
    float va = v * A;
    return fmaf(va, t, va);
}

constexpr int PAH = 136;                 // A tile pitch in halfs
constexpr uint32_t A0_OFF = 0;           // ping buffer
constexpr uint32_t A1_OFF = 34816;       // pong buffer (128*136*2)
constexpr int SMEM_FUSED = 69632;

// mma over one K=64 chunk (4 k16-steps); A via ldmatrix, B (hi-only) via __ldg
template <int NI>
__device__ __forceinline__ void mma_chunk(
    uint32_t aLane, int colOffHalfs,
    const uint32_t* __restrict__ BH,
    int wn, int gq, int l4, float acc[4][NI][4])
{
    #pragma unroll
    for (int s = 0; s < 4; ++s) {
        const int k2a = 8 * s + l4, k2b = k2a + 4;
        uint32_t bh[NI][2];
        if constexpr (NI == 4) {
            const int base = gq * 16 + wn * 4;
            uint4 h0 = __ldg((const uint4*)(BH + k2a * 128 + base));
            uint4 h1 = __ldg((const uint4*)(BH + k2b * 128 + base));
            bh[0][0] = h0.x; bh[1][0] = h0.y; bh[2][0] = h0.z; bh[3][0] = h0.w;
            bh[0][1] = h1.x; bh[1][1] = h1.y; bh[2][1] = h1.z; bh[3][1] = h1.w;
        } else {
            const int base = gq * 8 + wn * 2;
            uint2 h0 = __ldg((const uint2*)(BH + k2a * 64 + base));
            uint2 h1 = __ldg((const uint2*)(BH + k2b * 64 + base));
            bh[0][0] = h0.x; bh[1][0] = h0.y;
            bh[0][1] = h1.x; bh[1][1] = h1.y;
        }
        const uint32_t aoff = (uint32_t)(colOffHalfs + s * 16) * 2;
        #pragma unroll
        for (int mi = 0; mi < 4; ++mi) {
            uint32_t ah[4];
            LDSM4(ah, aLane + aoff + mi * (16 * PAH * 2));
            #pragma unroll
            for (int ni = 0; ni < NI; ++ni)
                mma_f16(acc[mi][ni], ah, bh[ni]);
        }
    }
}

// -------- fused per-block kernel --------
__global__ void __launch_bounds__(256, 2)
fused_block(int blk, int last, float* __restrict__ outp,
            const float* __restrict__ b1, const float* __restrict__ b2,
            const float* __restrict__ cb, const float* __restrict__ betaPtr)
{
    extern __shared__ __align__(16) char smem[];
    const uint32_t sb = s2u(smem);

    const int tid  = threadIdx.x;
    const int warp = tid >> 5, lane = tid & 31;
    const int gq   = lane >> 2, l4 = lane & 3;
    const int wm   = warp >> 2, wn = warp & 3;    // 2 x 4 warp grid
    const int m0w  = wm * 64;
    const int mblk = blockIdx.x * 128;
    const float spv = log1pf(__expf(*betaPtr));
    const float sp2 = 0.5f * spv;
    const float Asw = 1.f / 2.2f;
    const int n0w4 = wn * 32;
    const int n0w2 = wn * 16;

    const uint32_t aLaneOff = (uint32_t)((m0w + (lane & 15)) * PAH + (lane >> 4) * 8) * 2;
    const uint32_t aLane0 = sb + A0_OFF + aLaneOff;
    const uint32_t aLane1 = sb + A1_OFF + aLaneOff;

    // hoisted bias fragments
    float cbv[4][2], b1v[4][2], b2v[2][2];
    #pragma unroll
    for (int ni = 0; ni < 4; ++ni) {
        int c = n0w4 + ni * 8 + 2 * l4;
        float2 t0 = *(const float2*)(cb + c);  cbv[ni][0] = t0.x; cbv[ni][1] = t0.y;
        float2 t1 = *(const float2*)(b1 + c);  b1v[ni][0] = t1.x; b1v[ni][1] = t1.y;
    }
    #pragma unroll
    for (int ni = 0; ni < 2; ++ni) {
        int c = n0w2 + ni * 8 + 2 * l4;
        float2 t2 = *(const float2*)(b2 + c);  b2v[ni][0] = t2.x; b2v[ni][1] = t2.y;
    }

    float acc[4][4][4];

    // ===== Stage 1: cheb, 3 chunks, ping-pong A buffers (A0, A1, A0) =====
    #pragma unroll
    for (int mi = 0; mi < 4; ++mi)
        #pragma unroll
        for (int ni = 0; ni < 4; ++ni)
            #pragma unroll
            for (int q = 0; q < 4; ++q) acc[mi][ni][q] = 0.f;

    #pragma unroll 1
    for (int ch = 0; ch < 3; ++ch) {
        const __half* srcA = (ch == 0) ? g_hh : (ch == 1) ? g_t1h : g_t2h;
        const uint32_t dstOff = (ch == 1) ? A1_OFF : A0_OFF;
        for (int i = tid; i < 128 * 8; i += 256) {
            int m = i >> 3, q = i & 7;
            uint4 v = *(const uint4*)(srcA + (size_t)(mblk + m) * 64 + q * 8);
            *(uint4*)(smem + dstOff + (m * PAH + q * 8) * 2) = v;
        }
        __syncthreads();
        mma_chunk<4>(((ch == 1) ? aLane1 : aLane0), 0,
                     &g_Bc[blk][ch][0], wn, gq, l4, acc);
    }

    // ===== Epilogue 1: bias + swish -> A1 =====
    #pragma unroll
    for (int mi = 0; mi < 4; ++mi) {
        int r0 = m0w + mi * 16 + gq;
        #pragma unroll
        for (int ni = 0; ni < 4; ++ni) {
            int c = n0w4 + ni * 8 + 2 * l4;
            float v00 = swish_t(acc[mi][ni][0] + cbv[ni][0], sp2, Asw);
            float v01 = swish_t(acc[mi][ni][1] + cbv[ni][1], sp2, Asw);
            float v10 = swish_t(acc[mi][ni][2] + cbv[ni][0], sp2, Asw);
            float v11 = swish_t(acc[mi][ni][3] + cbv[ni][1], sp2, Asw);
            *(__half2*)(smem + A1_OFF + (r0 * PAH + c) * 2)       = __floats2half2_rn(v00, v01);
            *(__half2*)(smem + A1_OFF + ((r0 + 8) * PAH + c) * 2) = __floats2half2_rn(v10, v11);
        }
    }
    __syncthreads();

    // ===== Stage 2: MLP1 (K=128 from A1) =====
    #pragma unroll
    for (int mi = 0; mi < 4; ++mi)
        #pragma unroll
        for (int ni = 0; ni < 4; ++ni)
            #pragma unroll
            for (int q = 0; q < 4; ++q) acc[mi][ni][q] = 0.f;

    mma_chunk<4>(aLane1, 0,  &g_B1[blk][0][0], wn, gq, l4, acc);
    mma_chunk<4>(aLane1, 64, &g_B1[blk][1][0], wn, gq, l4, acc);

    // ===== Epilogue 2 -> A0 =====
    #pragma unroll
    for (int mi = 0; mi < 4; ++mi) {
        int r0 = m0w + mi * 16 + gq;
        #pragma unroll
        for (int ni = 0; ni < 4; ++ni) {
            int c = n0w4 + ni * 8 + 2 * l4;
            float v00 = swish_t(acc[mi][ni][0] + b1v[ni][0], sp2, Asw);
            float v01 = swish_t(acc[mi][ni][1] + b1v[ni][1], sp2, Asw);
            float v10 = swish_t(acc[mi][ni][2] + b1v[ni][0], sp2, Asw);
            float v11 = swish_t(acc[mi][ni][3] + b1v[ni][1], sp2, Asw);
            *(__half2*)(smem + A0_OFF + (r0 * PAH + c) * 2)       = __floats2half2_rn(v00, v01);
            *(__half2*)(smem + A0_OFF + ((r0 + 8) * PAH + c) * 2) = __floats2half2_rn(v10, v11);
        }
    }
    __syncthreads();

    // ===== Stage 3: MLP2 (N=64 from A0) + residual =====
    float acc3[4][2][4];
    #pragma unroll
    for (int mi = 0; mi < 4; ++mi)
        #pragma unroll
        for (int ni = 0; ni < 2; ++ni)
            #pragma unroll
            for (int q = 0; q < 4; ++q) acc3[mi][ni][q] = 0.f;

    mma_chunk<2>(aLane0, 0,  &g_B2[blk][0][0], wn, gq, l4, acc3);
    mma_chunk<2>(aLane0, 64, &g_B2[blk][1][0], wn, gq, l4, acc3);

    // ===== Final epilogue =====
    // last block: write h+Fx directly to output in [B][N*C] layout (t_out fused away)
    #pragma unroll
    for (int mi = 0; mi < 4; ++mi) {
        int r0 = mblk + m0w + mi * 16 + gq;
        #pragma unroll
        for (int ni = 0; ni < 2; ++ni) {
            int c = n0w2 + ni * 8 + 2 * l4;
            float2 cur0 = *(float2*)(g_h + (size_t)r0 * 64 + c);
            float2 cur1 = *(float2*)(g_h + (size_t)(r0 + 8) * 64 + c);
            cur0.x += acc3[mi][ni][0] + b2v[ni][0];
            cur0.y += acc3[mi][ni][1] + b2v[ni][1];
            cur1.x += acc3[mi][ni][2] + b2v[ni][0];
            cur1.y += acc3[mi][ni][3] + b2v[ni][1];
            if (last) {
                int r1 = r0 + 8;
                size_t o0 = (size_t)(r0 & 15) * (Nn * 64) + (size_t)(r0 >> 4) * 64 + c;
                size_t o1 = (size_t)(r1 & 15) * (Nn * 64) + (size_t)(r1 >> 4) * 64 + c;
                *(float2*)(outp + o0) = cur0;
                *(float2*)(outp + o1) = cur1;
            } else {
                *(float2*)(g_h + (size_t)r0 * 64 + c)       = cur0;
                *(float2*)(g_h + (size_t)(r0 + 8) * 64 + c) = cur1;
                *(__half2*)(g_hh + (size_t)r0 * 64 + c)       = __floats2half2_rn(cur0.x, cur0.y);
                *(__half2*)(g_hh + (size_t)(r0 + 8) * 64 + c) = __floats2half2_rn(cur1.x, cur1.y);
            }
        }
    }
}

// -------- host launcher --------
extern "C" void kernel_launch(void* const* d_in, const int* in_sizes, int n_in,
                              void* d_out, int out_size) {
    const float* x      = (const float*)d_in[0];
    const int*   ei     = (const int*)  d_in[1];
    const float* ew     = (const float*)d_in[2];
    const float* cheb_w = (const float*)d_in[3];
    const float* cheb_b = (const float*)d_in[4];
    const float* beta   = (const float*)d_in[5];
    const float* w1     = (const float*)d_in[6];
    const float* b1     = (const float*)d_in[7];
    const float* w2     = (const float*)d_in[8];
    const float* b2     = (const float*)d_in[9];
    float* out = (float*)d_out;
    const int* src = ei;
    const int* dst = ei + Ee;

    cudaFuncSetAttribute((const void*)fused_block,
                         cudaFuncAttributeMaxDynamicSharedMemorySize, SMEM_FUSED);

    const int EB = (Ee + 255) / 256;

    zero_deg_cnt<<<NSCAN, 256>>>();
    deg_kernel<<<EB, 256>>>(src, ew);
    w_count_kernel<<<EB, 256>>>(src, dst, ew);
    scan1_kernel<<<NSCAN, 256>>>();
    scan2_kernel<<<1, 128>>>();
    scan3_kernel<<<NSCAN, 256>>>();
    fill_kernel<<<EB, 256>>>(src, dst);
    prep_all<<<288, 256>>>(cheb_w, w1, w2);

    t_in_kernel<<<Nn, 256>>>((const float4*)x);

    for (int b = 0; b < NBlk; ++b) {
        spmm16_kernel<0><<<Nn, 256>>>();
        spmm16_kernel<1><<<Nn, 256>>>();
        fused_block<<<2500, 256, SMEM_FUSED>>>(
            b, (b == NBlk - 1) ? 1 : 0, out,
            b1 + b * 128, b2 + b * 64, cheb_b + b * 128, beta + b);
    }
}

// round 15
// speedup vs baseline: 3.9942x; 1.1356x over previous
#include <cuda_runtime.h>
#include <cuda_fp16.h>
#include <stdint.h>
#include <math.h>

// Problem constants
constexpr int Bc   = 16;
constexpr int Nn   = 20000;
constexpr int Cc   = 64;
constexpr int Ee   = 640000;
constexpr int NBlk = 3;
constexpr int ROWS = Nn * Bc;          // 320000
constexpr int RowF = Bc * Cc;          // 1024 halfs per node row ([N][B][C])
constexpr int RowF4 = RowF / 4;
constexpr int NSCAN = (Nn + 255) / 256;  // 79 scan blocks

// -------- device scratch --------
__device__ __align__(16) float  g_h  [ROWS * Cc];
__device__ __align__(16) __half g_hh [ROWS * Cc];
__device__ __align__(16) __half g_t1h[ROWS * Cc];
__device__ __align__(16) __half g_t2h[ROWS * Cc];
__device__ float g_deg [Nn];
__device__ float g_w   [Ee];
__device__ int   g_off [Nn + 1];
__device__ int   g_cnt [Nn];
__device__ int   g_bsum[NSCAN];
__device__ int   g_bbase[NSCAN + 1];
__device__ int   g_csrc[Ee];
__device__ float g_csw [Ee];
// Pre-packed fp16 B operands (hi only), LANE-VECTORIZED fragment layout:
// N=128: word r = k2*128 + gq*16 + wn*4 + ni  (n = wn*32 + ni*8 + gq)
// N=64 : word r = k2*64  + gq*8  + wn*2 + ni  (n = wn*16 + ni*8 + gq)
__device__ __align__(16) uint32_t g_Bc[3][3][32 * 128];   // [block][chunk]
__device__ __align__(16) uint32_t g_B1[3][2][32 * 128];
__device__ __align__(16) uint32_t g_B2[3][2][32 * 64];

// -------- small setup kernels --------
__global__ void zero_deg_cnt() {
    int i = blockIdx.x * blockDim.x + threadIdx.x;
    if (i < Nn) { g_deg[i] = 0.f; g_cnt[i] = 0; }
}
__global__ void deg_kernel(const int* __restrict__ src, const float* __restrict__ ew) {
    int e = blockIdx.x * blockDim.x + threadIdx.x;
    if (e < Ee) atomicAdd(&g_deg[src[e]], ew[e]);
}
__global__ void w_count_kernel(const int* __restrict__ src, const int* __restrict__ dst,
                               const float* __restrict__ ew) {
    int e = blockIdx.x * blockDim.x + threadIdx.x;
    if (e < Ee) {
        int s = src[e], d = dst[e];
        float ds = g_deg[s], dd = g_deg[d];
        float is = (ds > 0.f) ? rsqrtf(fmaxf(ds, 1e-12f)) : 0.f;
        float id = (dd > 0.f) ? rsqrtf(fmaxf(dd, 1e-12f)) : 0.f;
        g_w[e] = -is * ew[e] * id;
        atomicAdd(&g_cnt[d], 1);
    }
}
__global__ void scan1_kernel() {
    __shared__ int wsum[8];
    int b = blockIdx.x, t = threadIdx.x;
    int i = b * 256 + t;
    int v = (i < Nn) ? g_cnt[i] : 0;
    if (i < Nn) g_cnt[i] = 0;
    int x = v;
    #pragma unroll
    for (int d = 1; d < 32; d <<= 1) {
        int y = __shfl_up_sync(0xFFFFFFFFu, x, d);
        if ((t & 31) >= d) x += y;
    }
    if ((t & 31) == 31) wsum[t >> 5] = x;
    __syncthreads();
    if (t < 8) {
        int y = wsum[t];
        #pragma unroll
        for (int d = 1; d < 8; d <<= 1) {
            int z = __shfl_up_sync(0xFFu, y, d);
            if (t >= d) y += z;
        }
        wsum[t] = y;
    }
    __syncthreads();
    int excl = (x - v) + ((t >= 32) ? wsum[(t >> 5) - 1] : 0);
    if (i < Nn) g_off[i] = excl;
    if (t == 255) g_bsum[b] = excl + v;
}
__global__ void scan2_kernel() {
    int t = threadIdx.x;
    __shared__ int sh[NSCAN];
    if (t < NSCAN) sh[t] = g_bsum[t];
    __syncthreads();
    if (t == 0) {
        int run = 0;
        #pragma unroll 4
        for (int b = 0; b < NSCAN; ++b) { g_bbase[b] = run; run += sh[b]; }
        g_bbase[NSCAN] = run;
        g_off[Nn] = run;
    }
}
__global__ void scan3_kernel() {
    int i = blockIdx.x * 256 + threadIdx.x;
    if (i < Nn) g_off[i] += g_bbase[blockIdx.x];
}
__global__ void fill_kernel(const int* __restrict__ src, const int* __restrict__ dst) {
    int e = blockIdx.x * blockDim.x + threadIdx.x;
    if (e < Ee) {
        int d = dst[e];
        int pos = g_off[d] + atomicAdd(&g_cnt[d], 1);
        g_csrc[pos] = src[e];
        g_csw[pos]  = g_w[e];
    }
}

// -------- input transpose --------
__global__ void t_in_kernel(const float4* __restrict__ x4) {
    int idx = blockIdx.x * 256 + threadIdx.x;
    int b = idx / (Nn * 16);
    int r = idx % (Nn * 16);
    int n = r >> 4, c4 = r & 15;
    float4 v = x4[idx];
    int o4 = n * RowF4 + b * 16 + c4;
    ((float4*)g_h)[o4] = v;
    ((__half2*)g_hh)[o4 * 2]     = __floats2half2_rn(v.x, v.y);
    ((__half2*)g_hh)[o4 * 2 + 1] = __floats2half2_rn(v.z, v.w);
}

// -------- SpMM fp16, dual edge streams (BW-bound, at LTS roofline) --------
template <int PHASE>
__global__ void __launch_bounds__(256) spmm16_kernel() {
    const __half* __restrict__ in = (PHASE == 0) ? g_hh : g_t1h;
    __half* __restrict__ out      = (PHASE == 0) ? g_t1h : g_t2h;
    __shared__ float red[8 * 128];
    int n = blockIdx.x;
    int stream = threadIdx.x >> 7;
    int t = threadIdx.x & 127;
    int e0 = g_off[n], e1 = g_off[n + 1];
    float acc[8];
    #pragma unroll
    for (int q = 0; q < 8; ++q) acc[q] = 0.f;
    #pragma unroll 4
    for (int e = e0 + stream; e < e1; e += 2) {
        int   s  = __ldg(&g_csrc[e]);
        float wv = __ldg(&g_csw[e]);
        uint4 raw = __ldg((const uint4*)(in + (size_t)s * RowF) + t);
        const __half2* hp = (const __half2*)&raw;
        #pragma unroll
        for (int p = 0; p < 4; ++p) {
            float2 f = __half22float2(hp[p]);
            acc[2 * p]     = fmaf(wv, f.x, acc[2 * p]);
            acc[2 * p + 1] = fmaf(wv, f.y, acc[2 * p + 1]);
        }
    }
    if (stream) {
        #pragma unroll
        for (int q = 0; q < 8; ++q) red[q * 128 + t] = acc[q];
    }
    __syncthreads();
    if (!stream) {
        uint4 res;
        __half2* rp = (__half2*)&res;
        #pragma unroll
        for (int p = 0; p < 4; ++p)
            rp[p] = __floats2half2_rn(acc[2 * p] + red[(2 * p) * 128 + t],
                                      acc[2 * p + 1] + red[(2 * p + 1) * 128 + t]);
        ((uint4*)(out + (size_t)n * RowF))[t] = res;
    }
}

// -------- merged weight prep (hi only) --------
__device__ __forceinline__ uint32_t pack_f2h(float v0, float v1) {
    __half2 t = __floats2half2_rn(v0, v1);
    return *(uint32_t*)&t;
}
__device__ __forceinline__ float wc_val(const float* __restrict__ cw, int b, int rg, int n) {
    int term = rg >> 6, kk = rg & 63;
    float v;
    if (term == 0)
        v = cw[((size_t)(b * 3 + 0) * 64 + kk) * 128 + n] -
            cw[((size_t)(b * 3 + 2) * 64 + kk) * 128 + n];
    else if (term == 1)
        v = cw[((size_t)(b * 3 + 1) * 64 + kk) * 128 + n];
    else
        v = 2.f * cw[((size_t)(b * 3 + 2) * 64 + kk) * 128 + n];
    return v;
}
__global__ void prep_all(const float* __restrict__ cw,
                         const float* __restrict__ w1,
                         const float* __restrict__ w2) {
    int idx = blockIdx.x * 256 + threadIdx.x;     // 73728 total
    if (idx < 36864) {                            // g_Bc
        int b = idx / 12288, r2 = idx % 12288;
        int c = r2 >> 12, r = r2 & 4095;
        int k2 = r >> 7, t = r & 127;
        int gq = t >> 4, rem = t & 15, wn = rem >> 2, ni = rem & 3;
        int n = wn * 32 + ni * 8 + gq;
        float v0 = wc_val(cw, b, c * 64 + 2 * k2,     n);
        float v1 = wc_val(cw, b, c * 64 + 2 * k2 + 1, n);
        g_Bc[b][c][r] = pack_f2h(v0, v1);
    } else if (idx < 61440) {                     // g_B1
        int j = idx - 36864;
        int b = j / 8192, r2 = j % 8192;
        int c = r2 >> 12, r = r2 & 4095;
        int k2 = r >> 7, t = r & 127;
        int gq = t >> 4, rem = t & 15, wn = rem >> 2, ni = rem & 3;
        int n = wn * 32 + ni * 8 + gq;
        const float* W = w1 + (size_t)b * 16384 + (size_t)c * 64 * 128;
        g_B1[b][c][r] = pack_f2h(W[(size_t)(2 * k2) * 128 + n],
                                 W[(size_t)(2 * k2 + 1) * 128 + n]);
    } else if (idx < 73728) {                     // g_B2
        int j = idx - 61440;
        int b = j / 4096, r2 = j % 4096;
        int c = r2 >> 11, r = r2 & 2047;
        int k2 = r >> 6, t = r & 63;
        int gq = t >> 3, rem = t & 7, wn = rem >> 1, ni = rem & 1;
        int n = wn * 16 + ni * 8 + gq;
        const float* W = w2 + (size_t)b * 8192 + (size_t)c * 64 * 64;
        g_B2[b][c][r] = pack_f2h(W[(size_t)(2 * k2) * 64 + n],
                                 W[(size_t)(2 * k2 + 1) * 64 + n]);
    }
}

// ================== fused GEMM chain (mma.sync f16, single-term) ==================
__device__ __forceinline__ uint32_t s2u(const void* p) {
    uint32_t a;
    asm("{ .reg .u64 t; cvta.to.shared.u64 t, %1; cvt.u32.u64 %0, t; }" : "=r"(a) : "l"(p));
    return a;
}
__device__ __forceinline__ void mma_f16(float* c, const uint32_t* a, const uint32_t* b) {
    asm volatile(
        "mma.sync.aligned.m16n8k16.row.col.f32.f16.f16.f32 "
        "{%0,%1,%2,%3}, {%4,%5,%6,%7}, {%8,%9}, {%0,%1,%2,%3};\n"
        : "+f"(c[0]), "+f"(c[1]), "+f"(c[2]), "+f"(c[3])
        : "r"(a[0]), "r"(a[1]), "r"(a[2]), "r"(a[3]), "r"(b[0]), "r"(b[1]));
}
#define LDSM4(r, a) \
    asm volatile("ldmatrix.sync.aligned.m8n8.x4.shared.b16 {%0,%1,%2,%3}, [%4];" \
        : "=r"((r)[0]), "=r"((r)[1]), "=r"((r)[2]), "=r"((r)[3]) : "r"(a))

__device__ __forceinline__ float swish_t(float v, float sp2, float A) {
    float t;
    asm("tanh.approx.f32 %0, %1;" : "=f"(t) : "f"(v * sp2));
    float va = v * A;
    return fmaf(va, t, va);
}

constexpr int PAH = 136;                 // A tile pitch in halfs
constexpr uint32_t A0_OFF = 0;           // ping buffer
constexpr uint32_t A1_OFF = 34816;       // pong buffer (128*136*2)
constexpr int SMEM_FUSED = 69632;

template <int NI>
__device__ __forceinline__ void mma_chunk(
    uint32_t aLane, int colOffHalfs,
    const uint32_t* __restrict__ BH,
    int wn, int gq, int l4, float acc[4][NI][4])
{
    #pragma unroll
    for (int s = 0; s < 4; ++s) {
        const int k2a = 8 * s + l4, k2b = k2a + 4;
        uint32_t bh[NI][2];
        if constexpr (NI == 4) {
            const int base = gq * 16 + wn * 4;
            uint4 h0 = __ldg((const uint4*)(BH + k2a * 128 + base));
            uint4 h1 = __ldg((const uint4*)(BH + k2b * 128 + base));
            bh[0][0] = h0.x; bh[1][0] = h0.y; bh[2][0] = h0.z; bh[3][0] = h0.w;
            bh[0][1] = h1.x; bh[1][1] = h1.y; bh[2][1] = h1.z; bh[3][1] = h1.w;
        } else {
            const int base = gq * 8 + wn * 2;
            uint2 h0 = __ldg((const uint2*)(BH + k2a * 64 + base));
            uint2 h1 = __ldg((const uint2*)(BH + k2b * 64 + base));
            bh[0][0] = h0.x; bh[1][0] = h0.y;
            bh[0][1] = h1.x; bh[1][1] = h1.y;
        }
        const uint32_t aoff = (uint32_t)(colOffHalfs + s * 16) * 2;
        #pragma unroll
        for (int mi = 0; mi < 4; ++mi) {
            uint32_t ah[4];
            LDSM4(ah, aLane + aoff + mi * (16 * PAH * 2));
            #pragma unroll
            for (int ni = 0; ni < NI; ++ni)
                mma_f16(acc[mi][ni], ah, bh[ni]);
        }
    }
}

// A-tile fill: pure 16B fp16 copy
__device__ __forceinline__ void fill_A(const __half* __restrict__ srcA, int mblk,
                                       char* smem, uint32_t dstOff, int tid)
{
    for (int i = tid; i < 128 * 8; i += 256) {
        int m = i >> 3, q = i & 7;
        uint4 v = *(const uint4*)(srcA + (size_t)(mblk + m) * 64 + q * 8);
        *(uint4*)(smem + dstOff + (m * PAH + q * 8) * 2) = v;
    }
}

// -------- fused per-block kernel --------
__global__ void __launch_bounds__(256, 2)
fused_block(int blk, int last, float* __restrict__ outp,
            const float* __restrict__ b1, const float* __restrict__ b2,
            const float* __restrict__ cb, const float* __restrict__ betaPtr)
{
    extern __shared__ __align__(16) char smem[];
    const uint32_t sb = s2u(smem);

    const int tid  = threadIdx.x;
    const int warp = tid >> 5, lane = tid & 31;
    const int gq   = lane >> 2, l4 = lane & 3;
    const int wm   = warp >> 2, wn = warp & 3;    // 2 x 4 warp grid
    const int m0w  = wm * 64;
    const int mblk = blockIdx.x * 128;
    const float spv = log1pf(__expf(*betaPtr));
    const float sp2 = 0.5f * spv;
    const float Asw = 1.f / 2.2f;
    const int n0w4 = wn * 32;
    const int n0w2 = wn * 16;

    const uint32_t aLaneOff = (uint32_t)((m0w + (lane & 15)) * PAH + (lane >> 4) * 8) * 2;
    const uint32_t aLane0 = sb + A0_OFF + aLaneOff;
    const uint32_t aLane1 = sb + A1_OFF + aLaneOff;

    // hoisted bias fragments
    float cbv[4][2], b1v[4][2], b2v[2][2];
    #pragma unroll
    for (int ni = 0; ni < 4; ++ni) {
        int c = n0w4 + ni * 8 + 2 * l4;
        float2 t0 = *(const float2*)(cb + c);  cbv[ni][0] = t0.x; cbv[ni][1] = t0.y;
        float2 t1 = *(const float2*)(b1 + c);  b1v[ni][0] = t1.x; b1v[ni][1] = t1.y;
    }
    #pragma unroll
    for (int ni = 0; ni < 2; ++ni) {
        int c = n0w2 + ni * 8 + 2 * l4;
        float2 t2 = *(const float2*)(b2 + c);  b2v[ni][0] = t2.x; b2v[ni][1] = t2.y;
    }

    float acc[4][4][4];

    // ===== Stage 1: cheb, software-pipelined fills over ping-pong buffers =====
    #pragma unroll
    for (int mi = 0; mi < 4; ++mi)
        #pragma unroll
        for (int ni = 0; ni < 4; ++ni)
            #pragma unroll
            for (int q = 0; q < 4; ++q) acc[mi][ni][q] = 0.f;

    fill_A(g_hh, mblk, smem, A0_OFF, tid);                 // ch0 -> A0
    __syncthreads();
    fill_A(g_t1h, mblk, smem, A1_OFF, tid);                // ch1 -> A1 (overlaps mma ch0)
    mma_chunk<4>(aLane0, 0, &g_Bc[blk][0][0], wn, gq, l4, acc);
    __syncthreads();
    fill_A(g_t2h, mblk, smem, A0_OFF, tid);                // ch2 -> A0 (overlaps mma ch1)
    mma_chunk<4>(aLane1, 0, &g_Bc[blk][1][0], wn, gq, l4, acc);
    __syncthreads();
    mma_chunk<4>(aLane0, 0, &g_Bc[blk][2][0], wn, gq, l4, acc);

    // ===== Epilogue 1: bias + swish -> A1 (all readers of A1 done at last sync) =====
    #pragma unroll
    for (int mi = 0; mi < 4; ++mi) {
        int r0 = m0w + mi * 16 + gq;
        #pragma unroll
        for (int ni = 0; ni < 4; ++ni) {
            int c = n0w4 + ni * 8 + 2 * l4;
            float v00 = swish_t(acc[mi][ni][0] + cbv[ni][0], sp2, Asw);
            float v01 = swish_t(acc[mi][ni][1] + cbv[ni][1], sp2, Asw);
            float v10 = swish_t(acc[mi][ni][2] + cbv[ni][0], sp2, Asw);
            float v11 = swish_t(acc[mi][ni][3] + cbv[ni][1], sp2, Asw);
            *(__half2*)(smem + A1_OFF + (r0 * PAH + c) * 2)       = __floats2half2_rn(v00, v01);
            *(__half2*)(smem + A1_OFF + ((r0 + 8) * PAH + c) * 2) = __floats2half2_rn(v10, v11);
        }
    }
    __syncthreads();

    // ===== Stage 2: MLP1 (K=128 from A1) =====
    #pragma unroll
    for (int mi = 0; mi < 4; ++mi)
        #pragma unroll
        for (int ni = 0; ni < 4; ++ni)
            #pragma unroll
            for (int q = 0; q < 4; ++q) acc[mi][ni][q] = 0.f;

    mma_chunk<4>(aLane1, 0,  &g_B1[blk][0][0], wn, gq, l4, acc);
    mma_chunk<4>(aLane1, 64, &g_B1[blk][1][0], wn, gq, l4, acc);

    // ===== Epilogue 2 -> A0 =====
    #pragma unroll
    for (int mi = 0; mi < 4; ++mi) {
        int r0 = m0w + mi * 16 + gq;
        #pragma unroll
        for (int ni = 0; ni < 4; ++ni) {
            int c = n0w4 + ni * 8 + 2 * l4;
            float v00 = swish_t(acc[mi][ni][0] + b1v[ni][0], sp2, Asw);
            float v01 = swish_t(acc[mi][ni][1] + b1v[ni][1], sp2, Asw);
            float v10 = swish_t(acc[mi][ni][2] + b1v[ni][0], sp2, Asw);
            float v11 = swish_t(acc[mi][ni][3] + b1v[ni][1], sp2, Asw);
            *(__half2*)(smem + A0_OFF + (r0 * PAH + c) * 2)       = __floats2half2_rn(v00, v01);
            *(__half2*)(smem + A0_OFF + ((r0 + 8) * PAH + c) * 2) = __floats2half2_rn(v10, v11);
        }
    }
    __syncthreads();

    // ===== Stage 3: MLP2 (N=64 from A0) + residual (prefetched) =====
    float acc3[4][2][4];
    #pragma unroll
    for (int mi = 0; mi < 4; ++mi)
        #pragma unroll
        for (int ni = 0; ni < 2; ++ni)
            #pragma unroll
            for (int q = 0; q < 4; ++q) acc3[mi][ni][q] = 0.f;

    mma_chunk<2>(aLane0, 0,  &g_B2[blk][0][0], wn, gq, l4, acc3);

    // prefetch residual h under the second mma chunk
    float2 res0[4][2], res1[4][2];
    #pragma unroll
    for (int mi = 0; mi < 4; ++mi) {
        int r0 = mblk + m0w + mi * 16 + gq;
        #pragma unroll
        for (int ni = 0; ni < 2; ++ni) {
            int c = n0w2 + ni * 8 + 2 * l4;
            res0[mi][ni] = __ldg((const float2*)(g_h + (size_t)r0 * 64 + c));
            res1[mi][ni] = __ldg((const float2*)(g_h + (size_t)(r0 + 8) * 64 + c));
        }
    }

    mma_chunk<2>(aLane0, 64, &g_B2[blk][1][0], wn, gq, l4, acc3);

    // ===== Final epilogue =====
    #pragma unroll
    for (int mi = 0; mi < 4; ++mi) {
        int r0 = mblk + m0w + mi * 16 + gq;
        #pragma unroll
        for (int ni = 0; ni < 2; ++ni) {
            int c = n0w2 + ni * 8 + 2 * l4;
            float2 cur0 = res0[mi][ni];
            float2 cur1 = res1[mi][ni];
            cur0.x += acc3[mi][ni][0] + b2v[ni][0];
            cur0.y += acc3[mi][ni][1] + b2v[ni][1];
            cur1.x += acc3[mi][ni][2] + b2v[ni][0];
            cur1.y += acc3[mi][ni][3] + b2v[ni][1];
            if (last) {
                int r1 = r0 + 8;
                size_t o0 = (size_t)(r0 & 15) * (Nn * 64) + (size_t)(r0 >> 4) * 64 + c;
                size_t o1 = (size_t)(r1 & 15) * (Nn * 64) + (size_t)(r1 >> 4) * 64 + c;
                *(float2*)(outp + o0) = cur0;
                *(float2*)(outp + o1) = cur1;
            } else {
                *(float2*)(g_h + (size_t)r0 * 64 + c)       = cur0;
                *(float2*)(g_h + (size_t)(r0 + 8) * 64 + c) = cur1;
                *(__half2*)(g_hh + (size_t)r0 * 64 + c)       = __floats2half2_rn(cur0.x, cur0.y);
                *(__half2*)(g_hh + (size_t)(r0 + 8) * 64 + c) = __floats2half2_rn(cur1.x, cur1.y);
            }
        }
    }
}

// -------- host launcher --------
extern "C" void kernel_launch(void* const* d_in, const int* in_sizes, int n_in,
                              void* d_out, int out_size) {
    const float* x      = (const float*)d_in[0];
    const int*   ei     = (const int*)  d_in[1];
    const float* ew     = (const float*)d_in[2];
    const float* cheb_w = (const float*)d_in[3];
    const float* cheb_b = (const float*)d_in[4];
    const float* beta   = (const float*)d_in[5];
    const float* w1     = (const float*)d_in[6];
    const float* b1     = (const float*)d_in[7];
    const float* w2     = (const float*)d_in[8];
    const float* b2     = (const float*)d_in[9];
    float* out = (float*)d_out;
    const int* src = ei;
    const int* dst = ei + Ee;

    cudaFuncSetAttribute((const void*)fused_block,
                         cudaFuncAttributeMaxDynamicSharedMemorySize, SMEM_FUSED);

    const int EB = (Ee + 255) / 256;

    zero_deg_cnt<<<NSCAN, 256>>>();
    deg_kernel<<<EB, 256>>>(src, ew);
    w_count_kernel<<<EB, 256>>>(src, dst, ew);
    scan1_kernel<<<NSCAN, 256>>>();
    scan2_kernel<<<1, 128>>>();
    scan3_kernel<<<NSCAN, 256>>>();
    fill_kernel<<<EB, 256>>>(src, dst);
    prep_all<<<288, 256>>>(cheb_w, w1, w2);

    t_in_kernel<<<Nn, 256>>>((const float4*)x);

    for (int b = 0; b < NBlk; ++b) {
        spmm16_kernel<0><<<Nn, 256>>>();
        spmm16_kernel<1><<<Nn, 256>>>();
        fused_block<<<2500, 256, SMEM_FUSED>>>(
            b, (b == NBlk - 1) ? 1 : 0, out,
            b1 + b * 128, b2 + b * 64, cheb_b + b * 128, beta + b);
    }
}